// round 3
// baseline (speedup 1.0000x reference)
#include <cuda_runtime.h>
#include <math.h>

// ---------------- problem constants ----------------
#define S_LEN   2048
#define HID     7168
#define NH      32
#define Q_LORA  1536
#define KV_LORA 512
#define ROPE_D  64
#define CDIM    576          // KV_LORA + ROPE_D
#define V_D     128
#define MIN_MASKED (-10000.0f)

// ---------------- scratch (static device allocations) ----------------
__device__ float g_compressed[(size_t)S_LEN * CDIM];
__device__ float g_qa_pre[(size_t)S_LEN * Q_LORA];
__device__ float g_qa[(size_t)S_LEN * Q_LORA];
__device__ float g_qpe[(size_t)S_LEN * (NH * ROPE_D)];
__device__ float g_kfull[(size_t)S_LEN * CDIM];
__device__ float g_qfull[(size_t)NH * S_LEN * CDIM];
__device__ float g_logits[(size_t)NH * S_LEN * S_LEN];
__device__ float g_ctx[(size_t)NH * S_LEN * KV_LORA];
__device__ float g_attnout[(size_t)S_LEN * (NH * V_D)];

// ---------------- TF32 tensor-core GEMM ----------------
// C[M,N] = alpha * A[M,K] @ B  (+ causal logic)
//   TRANSB=false: B is [K,N] row-major
//   TRANSB=true : B is [N,K] row-major (Q @ K^T)
// mode 0: plain; mode 1: causal epilogue (+block skip); mode 2: K limited to causal extent
#define BM 128
#define BN 128
#define BK 16
#define AS_STRIDE 20    // floats; 20g mod 32 distinct -> conflict-free A LDS
#define BS_STRIDE 136   // floats; 8k mod 32 distinct  -> conflict-free B LDS

__device__ __forceinline__ float rna_tf32(float x) {
    unsigned u;
    asm("cvt.rna.tf32.f32 %0, %1;" : "=r"(u) : "f"(x));
    return __uint_as_float(u);
}

__device__ __forceinline__ void mma_tf32(float (&c)[4], const unsigned (&a)[4], const unsigned (&b)[2]) {
    asm volatile(
        "mma.sync.aligned.m16n8k8.row.col.f32.tf32.tf32.f32 "
        "{%0,%1,%2,%3}, {%4,%5,%6,%7}, {%8,%9}, {%0,%1,%2,%3};"
        : "+f"(c[0]), "+f"(c[1]), "+f"(c[2]), "+f"(c[3])
        : "r"(a[0]), "r"(a[1]), "r"(a[2]), "r"(a[3]), "r"(b[0]), "r"(b[1]));
}

template<bool TRANSB>
__global__ void __launch_bounds__(256, 2)
gemm_tc_kernel(const float* __restrict__ A, const float* __restrict__ B,
               float* __restrict__ C,
               int M, int N, int K, int lda, int ldb, int ldc,
               long long sA, long long sB, long long sC,
               float alpha, int mode)
{
    const long long bz = blockIdx.z;
    A += bz * sA;  B += bz * sB;  C += bz * sC;

    const int row0 = blockIdx.y * BM;
    const int col0 = blockIdx.x * BN;
    const int tid  = threadIdx.x;
    const int lane = tid & 31;
    const int wid  = tid >> 5;
    const int wm   = wid >> 2;        // 0..1
    const int wn   = wid & 3;         // 0..3
    const int g    = lane >> 2;       // groupID 0..7
    const int tig  = lane & 3;        // 0..3

    if (mode == 1 && col0 >= row0 + BM) {
        // fully above diagonal
        const float4 mv = make_float4(MIN_MASKED, MIN_MASKED, MIN_MASKED, MIN_MASKED);
        for (int i = tid; i < BM * (BN / 4); i += 256) {
            int r  = i / (BN / 4);
            int cq = (i % (BN / 4)) * 4;
            *(float4*)(C + (long long)(row0 + r) * ldc + col0 + cq) = mv;
        }
        return;
    }

    __shared__ float As[BM * AS_STRIDE];
    __shared__ float Bs[BK * BS_STRIDE];

    int kEnd = K;
    if (mode == 2) kEnd = min(K, row0 + BM);

    float acc[4][4][4] = {};
    float4 aR[2], bR[2];

    auto ldA = [&](int k0) {
        #pragma unroll
        for (int e = 0; e < 2; e++) {
            int idx = tid + e * 256;
            int m = idx >> 2, kq = (idx & 3) << 2;
            aR[e] = *(const float4*)(A + (long long)(row0 + m) * lda + k0 + kq);
        }
    };
    auto ldB = [&](int k0) {
        #pragma unroll
        for (int e = 0; e < 2; e++) {
            int idx = tid + e * 256;
            if (!TRANSB) {
                int k = idx >> 5, nq = (idx & 31) << 2;
                bool in = (col0 + nq) < N;
                bR[e] = in ? *(const float4*)(B + (long long)(k0 + k) * ldb + col0 + nq)
                           : make_float4(0.f, 0.f, 0.f, 0.f);
            } else {
                int n = idx >> 2, kq = (idx & 3) << 2;
                bool in = (col0 + n) < N;
                bR[e] = in ? *(const float4*)(B + (long long)(col0 + n) * ldb + k0 + kq)
                           : make_float4(0.f, 0.f, 0.f, 0.f);
            }
        }
    };
    auto stA = [&]() {
        #pragma unroll
        for (int e = 0; e < 2; e++) {
            int idx = tid + e * 256;
            int m = idx >> 2, kq = (idx & 3) << 2;
            float4 v = aR[e];
            v.x = rna_tf32(v.x); v.y = rna_tf32(v.y);
            v.z = rna_tf32(v.z); v.w = rna_tf32(v.w);
            *(float4*)&As[m * AS_STRIDE + kq] = v;
        }
    };
    auto stB = [&]() {
        #pragma unroll
        for (int e = 0; e < 2; e++) {
            int idx = tid + e * 256;
            float4 v = bR[e];
            v.x = rna_tf32(v.x); v.y = rna_tf32(v.y);
            v.z = rna_tf32(v.z); v.w = rna_tf32(v.w);
            if (!TRANSB) {
                int k = idx >> 5, nq = (idx & 31) << 2;
                *(float4*)&Bs[k * BS_STRIDE + nq] = v;
            } else {
                int n = idx >> 2, kq = (idx & 3) << 2;
                Bs[(kq + 0) * BS_STRIDE + n] = v.x;
                Bs[(kq + 1) * BS_STRIDE + n] = v.y;
                Bs[(kq + 2) * BS_STRIDE + n] = v.z;
                Bs[(kq + 3) * BS_STRIDE + n] = v.w;
            }
        }
    };
    auto compute = [&]() {
        #pragma unroll
        for (int kk = 0; kk < BK; kk += 8) {
            unsigned af[4][4], bf[4][2];
            #pragma unroll
            for (int mi = 0; mi < 4; mi++) {
                int mb = wm * 64 + mi * 16 + g;
                af[mi][0] = __float_as_uint(As[(mb    ) * AS_STRIDE + kk + tig    ]);
                af[mi][1] = __float_as_uint(As[(mb + 8) * AS_STRIDE + kk + tig    ]);
                af[mi][2] = __float_as_uint(As[(mb    ) * AS_STRIDE + kk + tig + 4]);
                af[mi][3] = __float_as_uint(As[(mb + 8) * AS_STRIDE + kk + tig + 4]);
            }
            #pragma unroll
            for (int nj = 0; nj < 4; nj++) {
                int nb = wn * 32 + nj * 8 + g;
                bf[nj][0] = __float_as_uint(Bs[(kk + tig    ) * BS_STRIDE + nb]);
                bf[nj][1] = __float_as_uint(Bs[(kk + tig + 4) * BS_STRIDE + nb]);
            }
            #pragma unroll
            for (int mi = 0; mi < 4; mi++)
                #pragma unroll
                for (int nj = 0; nj < 4; nj++)
                    mma_tf32(acc[mi][nj], af[mi], bf[nj]);
        }
    };

    ldA(0); ldB(0);
    stA(); stB();
    __syncthreads();

    for (int k0 = 0; k0 < kEnd; k0 += BK) {
        bool nxt = (k0 + BK) < kEnd;
        if (nxt) { ldA(k0 + BK); ldB(k0 + BK); }
        compute();
        __syncthreads();
        if (nxt) { stA(); stB(); __syncthreads(); }
    }

    // epilogue
    #pragma unroll
    for (int mi = 0; mi < 4; mi++) {
        int r = row0 + wm * 64 + mi * 16 + g;
        #pragma unroll
        for (int nj = 0; nj < 4; nj++) {
            int c = col0 + wn * 32 + nj * 8 + tig * 2;
            float v0 = acc[mi][nj][0] * alpha;
            float v1 = acc[mi][nj][1] * alpha;
            float v2 = acc[mi][nj][2] * alpha;
            float v3 = acc[mi][nj][3] * alpha;
            if (mode == 1) {
                v0 = (c     > r    ) ? MIN_MASKED : v0;
                v1 = (c + 1 > r    ) ? MIN_MASKED : v1;
                v2 = (c     > r + 8) ? MIN_MASKED : v2;
                v3 = (c + 1 > r + 8) ? MIN_MASKED : v3;
            }
            if (c < N) {    // N is always even; c even -> c+1 < N too
                float* p0 = C + (long long)r * ldc + c;
                float* p1 = C + (long long)(r + 8) * ldc + c;
                p0[0] = v0; p0[1] = v1;
                p1[0] = v2; p1[1] = v3;
            }
        }
    }
}

// ---------------- rmsnorm(kva) + RoPE(k_pe) -> k_full ----------------
__global__ void kva_rms_rope_kernel(const float* __restrict__ comp,
                                    const float* __restrict__ kv_ln,
                                    const int*   __restrict__ pos_ids,
                                    float* __restrict__ kfull)
{
    int s = blockIdx.x;
    const float* x = comp + (long long)s * CDIM;
    float* out = kfull + (long long)s * CDIM;

    __shared__ float red[128];
    float ss = 0.0f;
    for (int i = threadIdx.x; i < KV_LORA; i += 128) { float v = x[i]; ss += v * v; }
    red[threadIdx.x] = ss; __syncthreads();
    for (int st = 64; st > 0; st >>= 1) {
        if (threadIdx.x < st) red[threadIdx.x] += red[threadIdx.x + st];
        __syncthreads();
    }
    float scale = rsqrtf(red[0] / (float)KV_LORA + 1e-6f);

    for (int i = threadIdx.x; i < KV_LORA; i += 128)
        out[i] = x[i] * scale * kv_ln[i];

    if (threadIdx.x < ROPE_D / 2) {
        int j = threadIdx.x;
        float pos  = (float)pos_ids[s];
        float invf = powf(10000.0f, -(float)(2 * j) / (float)ROPE_D);
        float ang  = pos * invf;
        float c = cosf(ang), sn = sinf(ang);
        float x0 = x[KV_LORA + 2 * j];
        float x1 = x[KV_LORA + 2 * j + 1];
        out[KV_LORA + j]               = x0 * c - x1 * sn;
        out[KV_LORA + ROPE_D / 2 + j]  = x1 * c + x0 * sn;
    }
}

// ---------------- rmsnorm(q_a) ----------------
__global__ void qa_rms_kernel(const float* __restrict__ in,
                              const float* __restrict__ w,
                              float* __restrict__ outp)
{
    int s = blockIdx.x;
    const float* x = in + (long long)s * Q_LORA;
    float* o = outp + (long long)s * Q_LORA;

    __shared__ float red[256];
    float ss = 0.0f;
    for (int i = threadIdx.x; i < Q_LORA; i += 256) { float v = x[i]; ss += v * v; }
    red[threadIdx.x] = ss; __syncthreads();
    for (int st = 128; st > 0; st >>= 1) {
        if (threadIdx.x < st) red[threadIdx.x] += red[threadIdx.x + st];
        __syncthreads();
    }
    float scale = rsqrtf(red[0] / (float)Q_LORA + 1e-6f);
    for (int i = threadIdx.x; i < Q_LORA; i += 256)
        o[i] = x[i] * scale * w[i];
}

// ---------------- RoPE on q_pe, scatter into q_full rope columns ----------------
__global__ void rope_q_kernel(const float* __restrict__ qpe,
                              const int*   __restrict__ pos_ids,
                              float* __restrict__ qfull)
{
    int s = blockIdx.x;
    int h = blockIdx.y;
    int j = threadIdx.x;            // 0..31
    float pos  = (float)pos_ids[s];
    float invf = powf(10000.0f, -(float)(2 * j) / (float)ROPE_D);
    float ang  = pos * invf;
    float c = cosf(ang), sn = sinf(ang);
    const float* x = qpe + (long long)s * (NH * ROPE_D) + h * ROPE_D;
    float x0 = x[2 * j], x1 = x[2 * j + 1];
    float* out = qfull + ((long long)h * S_LEN + s) * CDIM + KV_LORA;
    out[j]                = x0 * c - x1 * sn;
    out[j + ROPE_D / 2]   = x1 * c + x0 * sn;
}

// ---------------- row softmax over logits [NH*S, S] ----------------
__global__ void softmax_kernel(float* __restrict__ logits)
{
    long long row = blockIdx.x;
    float* p = logits + row * S_LEN;
    int tid = threadIdx.x;

    float v[8];
    float m = -1e30f;
    #pragma unroll
    for (int i = 0; i < 8; i++) { v[i] = p[tid + i * 256]; m = fmaxf(m, v[i]); }

    __shared__ float red[256];
    red[tid] = m; __syncthreads();
    for (int st = 128; st > 0; st >>= 1) {
        if (tid < st) red[tid] = fmaxf(red[tid], red[tid + st]);
        __syncthreads();
    }
    m = red[0]; __syncthreads();

    float sum = 0.0f;
    #pragma unroll
    for (int i = 0; i < 8; i++) { v[i] = __expf(v[i] - m); sum += v[i]; }
    red[tid] = sum; __syncthreads();
    for (int st = 128; st > 0; st >>= 1) {
        if (tid < st) red[tid] += red[tid + st];
        __syncthreads();
    }
    float inv = 1.0f / red[0];
    #pragma unroll
    for (int i = 0; i < 8; i++) p[tid + i * 256] = v[i] * inv;
}

// ---------------- host launcher ----------------
static void launch_gemm(bool transb, const float* A, const float* B, float* C,
                        int M, int N, int K, int lda, int ldb, int ldc,
                        long long sA, long long sB, long long sC,
                        int batch, float alpha, int mode)
{
    dim3 grid((N + BN - 1) / BN, M / BM, batch);
    if (transb)
        gemm_tc_kernel<true><<<grid, 256>>>(A, B, C, M, N, K, lda, ldb, ldc, sA, sB, sC, alpha, mode);
    else
        gemm_tc_kernel<false><<<grid, 256>>>(A, B, C, M, N, K, lda, ldb, ldc, sA, sB, sC, alpha, mode);
}

extern "C" void kernel_launch(void* const* d_in, const int* in_sizes, int n_in,
                              void* d_out, int out_size)
{
    (void)in_sizes; (void)n_in; (void)out_size;
    const float* X        = (const float*)d_in[0];   // [S, HID]
    const int*   pos      = (const int*)d_in[2];     // [1, S]
    const float* W_kv_a   = (const float*)d_in[3];   // [HID, CDIM]
    const float* W_q_a    = (const float*)d_in[4];   // [HID, Q_LORA]
    const float* q_ln     = (const float*)d_in[5];   // [Q_LORA]
    const float* kv_ln    = (const float*)d_in[6];   // [KV_LORA]
    const float* q_rope_w = (const float*)d_in[7];   // [Q_LORA, NH*ROPE_D]
    const float* fusedqk  = (const float*)d_in[8];   // [NH, Q_LORA, KV_LORA]
    const float* v_up     = (const float*)d_in[9];   // [NH, KV_LORA, V_D]
    const float* W_o      = (const float*)d_in[10];  // [NH*V_D, HID]
    float* out = (float*)d_out;                      // [S, HID]

    float *comp, *qa_pre, *qa, *qpe, *kfull, *qfull, *logits, *ctx, *attnout;
    cudaGetSymbolAddress((void**)&comp,    g_compressed);
    cudaGetSymbolAddress((void**)&qa_pre,  g_qa_pre);
    cudaGetSymbolAddress((void**)&qa,      g_qa);
    cudaGetSymbolAddress((void**)&qpe,     g_qpe);
    cudaGetSymbolAddress((void**)&kfull,   g_kfull);
    cudaGetSymbolAddress((void**)&qfull,   g_qfull);
    cudaGetSymbolAddress((void**)&logits,  g_logits);
    cudaGetSymbolAddress((void**)&ctx,     g_ctx);
    cudaGetSymbolAddress((void**)&attnout, g_attnout);

    const float scale = 1.0f / sqrtf(192.0f);   // 1/sqrt(NOPE_D + ROPE_D)

    // 1) compressed = X @ W_kv_a                      [S, CDIM]
    launch_gemm(false, X, W_kv_a, comp, S_LEN, CDIM, HID, HID, CDIM, CDIM, 0, 0, 0, 1, 1.0f, 0);
    // 2) qa_pre = X @ W_q_a                           [S, Q_LORA]
    launch_gemm(false, X, W_q_a, qa_pre, S_LEN, Q_LORA, HID, HID, Q_LORA, Q_LORA, 0, 0, 0, 1, 1.0f, 0);
    // 3) k_full = concat(rmsnorm(kva), rope(k_pe))    [S, CDIM]
    kva_rms_rope_kernel<<<S_LEN, 128>>>(comp, kv_ln, pos, kfull);
    // 4) qa = rmsnorm(qa_pre)                         [S, Q_LORA]
    qa_rms_kernel<<<S_LEN, 256>>>(qa_pre, q_ln, qa);
    // 5) qpe = qa @ q_rope_w                          [S, NH*ROPE_D]
    launch_gemm(false, qa, q_rope_w, qpe, S_LEN, NH * ROPE_D, Q_LORA,
                Q_LORA, NH * ROPE_D, NH * ROPE_D, 0, 0, 0, 1, 1.0f, 0);
    // 6) rope(q_pe) -> q_full[:, :, 512:576]
    rope_q_kernel<<<dim3(S_LEN, NH), ROPE_D / 2>>>(qpe, pos, qfull);
    // 7) dq = qa @ fusedqk[h] -> q_full[:, :, :512]   (batched over heads)
    launch_gemm(false, qa, fusedqk, qfull, S_LEN, KV_LORA, Q_LORA,
                Q_LORA, KV_LORA, CDIM,
                0, (long long)Q_LORA * KV_LORA, (long long)S_LEN * CDIM,
                NH, 1.0f, 0);
    // 8) logits = scale * q_full @ k_full^T, causal   (batched, TRANSB)
    launch_gemm(true, qfull, kfull, logits, S_LEN, S_LEN, CDIM,
                CDIM, CDIM, S_LEN,
                (long long)S_LEN * CDIM, 0, (long long)S_LEN * S_LEN,
                NH, scale, 1);
    // 9) softmax rows
    softmax_kernel<<<NH * S_LEN, 256>>>(logits);
    // 10) ctx = probs @ kva  (V = first 512 cols of k_full), causal K-limit
    launch_gemm(false, logits, kfull, ctx, S_LEN, KV_LORA, S_LEN,
                S_LEN, CDIM, KV_LORA,
                (long long)S_LEN * S_LEN, 0, (long long)S_LEN * KV_LORA,
                NH, 1.0f, 2);
    // 11) attnout[:, h*128:(h+1)*128] = ctx[h] @ v_up[h]
    launch_gemm(false, ctx, v_up, attnout, S_LEN, V_D, KV_LORA,
                KV_LORA, V_D, NH * V_D,
                (long long)S_LEN * KV_LORA, (long long)KV_LORA * V_D, (long long)V_D,
                NH, 1.0f, 0);
    // 12) out = attnout @ W_o                          [S, HID]
    launch_gemm(false, attnout, W_o, out, S_LEN, HID, NH * V_D,
                NH * V_D, HID, HID, 0, 0, 0, 1, 1.0f, 0);
}

// round 4
// speedup vs baseline: 1.0256x; 1.0256x over previous
#include <cuda_runtime.h>
#include <math.h>

// ---------------- problem constants ----------------
#define S_LEN   2048
#define HID     7168
#define NH      32
#define Q_LORA  1536
#define KV_LORA 512
#define ROPE_D  64
#define CDIM    576          // KV_LORA + ROPE_D
#define V_D     128
#define MIN_MASKED (-10000.0f)

// ---------------- scratch (static device allocations) ----------------
__device__ float g_compressed[(size_t)S_LEN * CDIM];
__device__ float g_qa_pre[(size_t)S_LEN * Q_LORA];
__device__ float g_qa[(size_t)S_LEN * Q_LORA];
__device__ float g_qpe[(size_t)S_LEN * (NH * ROPE_D)];
__device__ float g_kfull[(size_t)S_LEN * CDIM];
__device__ float g_qfull[(size_t)NH * S_LEN * CDIM];
__device__ float g_logits[(size_t)NH * S_LEN * S_LEN];
__device__ float g_ctx[(size_t)NH * S_LEN * KV_LORA];
__device__ float g_attnout[(size_t)S_LEN * (NH * V_D)];

// ---------------- TF32 tensor-core GEMM (double-buffered) ----------------
// C[M,N] = alpha * A[M,K] @ B  (+ causal logic)
//   TRANSB=false: B is [K,N] row-major
//   TRANSB=true : B is [N,K] row-major (Q @ K^T)
// mode 0: plain
// mode 1: causal epilogue; fully-masked blocks are SKIPPED (never written:
//         downstream consumers never read above the diagonal)
// mode 2: K limited to causal extent of this row block
#define BM 128
#define BN 128
#define BK 16
#define AS_STRIDE 20    // floats; conflict-free A LDS
#define BS_STRIDE 136   // floats; conflict-free B LDS

__device__ __forceinline__ float rna_tf32(float x) {
    unsigned u;
    asm("cvt.rna.tf32.f32 %0, %1;" : "=r"(u) : "f"(x));
    return __uint_as_float(u);
}

__device__ __forceinline__ void mma_tf32(float (&c)[4], const unsigned (&a)[4], const unsigned (&b)[2]) {
    asm volatile(
        "mma.sync.aligned.m16n8k8.row.col.f32.tf32.tf32.f32 "
        "{%0,%1,%2,%3}, {%4,%5,%6,%7}, {%8,%9}, {%0,%1,%2,%3};"
        : "+f"(c[0]), "+f"(c[1]), "+f"(c[2]), "+f"(c[3])
        : "r"(a[0]), "r"(a[1]), "r"(a[2]), "r"(a[3]), "r"(b[0]), "r"(b[1]));
}

template<bool TRANSB>
__global__ void __launch_bounds__(256, 2)
gemm_tc_kernel(const float* __restrict__ A, const float* __restrict__ B,
               float* __restrict__ C,
               int M, int N, int K, int lda, int ldb, int ldc,
               long long sA, long long sB, long long sC,
               float alpha, int mode)
{
    const long long bz = blockIdx.z;
    A += bz * sA;  B += bz * sB;  C += bz * sC;

    const int row0 = blockIdx.y * BM;
    const int col0 = blockIdx.x * BN;
    const int tid  = threadIdx.x;
    const int lane = tid & 31;
    const int wid  = tid >> 5;
    const int wm   = wid >> 2;        // 0..1
    const int wn   = wid & 3;         // 0..3
    const int g    = lane >> 2;       // groupID 0..7
    const int tig  = lane & 3;        // 0..3

    // fully above diagonal: never read downstream -> skip entirely
    if (mode == 1 && col0 >= row0 + BM) return;

    __shared__ float As[2][BM * AS_STRIDE];
    __shared__ float Bs[2][BK * BS_STRIDE];

    int kEnd = K;
    if (mode == 2) kEnd = min(K, row0 + BM);

    float acc[4][4][4] = {};
    float4 aR[2], bR[2];

    auto ldA = [&](int k0) {
        #pragma unroll
        for (int e = 0; e < 2; e++) {
            int idx = tid + e * 256;
            int m = idx >> 2, kq = (idx & 3) << 2;
            aR[e] = *(const float4*)(A + (long long)(row0 + m) * lda + k0 + kq);
        }
    };
    auto ldB = [&](int k0) {
        #pragma unroll
        for (int e = 0; e < 2; e++) {
            int idx = tid + e * 256;
            if (!TRANSB) {
                int k = idx >> 5, nq = (idx & 31) << 2;
                bool in = (col0 + nq) < N;
                bR[e] = in ? *(const float4*)(B + (long long)(k0 + k) * ldb + col0 + nq)
                           : make_float4(0.f, 0.f, 0.f, 0.f);
            } else {
                int n = idx >> 2, kq = (idx & 3) << 2;
                bool in = (col0 + n) < N;
                bR[e] = in ? *(const float4*)(B + (long long)(col0 + n) * ldb + k0 + kq)
                           : make_float4(0.f, 0.f, 0.f, 0.f);
            }
        }
    };
    auto stA = [&](int buf) {
        #pragma unroll
        for (int e = 0; e < 2; e++) {
            int idx = tid + e * 256;
            int m = idx >> 2, kq = (idx & 3) << 2;
            float4 v = aR[e];
            v.x = rna_tf32(v.x); v.y = rna_tf32(v.y);
            v.z = rna_tf32(v.z); v.w = rna_tf32(v.w);
            *(float4*)&As[buf][m * AS_STRIDE + kq] = v;
        }
    };
    auto stB = [&](int buf) {
        #pragma unroll
        for (int e = 0; e < 2; e++) {
            int idx = tid + e * 256;
            float4 v = bR[e];
            v.x = rna_tf32(v.x); v.y = rna_tf32(v.y);
            v.z = rna_tf32(v.z); v.w = rna_tf32(v.w);
            if (!TRANSB) {
                int k = idx >> 5, nq = (idx & 31) << 2;
                *(float4*)&Bs[buf][k * BS_STRIDE + nq] = v;
            } else {
                int n = idx >> 2, kq = (idx & 3) << 2;
                Bs[buf][(kq + 0) * BS_STRIDE + n] = v.x;
                Bs[buf][(kq + 1) * BS_STRIDE + n] = v.y;
                Bs[buf][(kq + 2) * BS_STRIDE + n] = v.z;
                Bs[buf][(kq + 3) * BS_STRIDE + n] = v.w;
            }
        }
    };
    auto compute = [&](int buf) {
        #pragma unroll
        for (int kk = 0; kk < BK; kk += 8) {
            unsigned af[4][4], bf[4][2];
            #pragma unroll
            for (int mi = 0; mi < 4; mi++) {
                int mb = wm * 64 + mi * 16 + g;
                af[mi][0] = __float_as_uint(As[buf][(mb    ) * AS_STRIDE + kk + tig    ]);
                af[mi][1] = __float_as_uint(As[buf][(mb + 8) * AS_STRIDE + kk + tig    ]);
                af[mi][2] = __float_as_uint(As[buf][(mb    ) * AS_STRIDE + kk + tig + 4]);
                af[mi][3] = __float_as_uint(As[buf][(mb + 8) * AS_STRIDE + kk + tig + 4]);
            }
            #pragma unroll
            for (int nj = 0; nj < 4; nj++) {
                int nb = wn * 32 + nj * 8 + g;
                bf[nj][0] = __float_as_uint(Bs[buf][(kk + tig    ) * BS_STRIDE + nb]);
                bf[nj][1] = __float_as_uint(Bs[buf][(kk + tig + 4) * BS_STRIDE + nb]);
            }
            #pragma unroll
            for (int mi = 0; mi < 4; mi++)
                #pragma unroll
                for (int nj = 0; nj < 4; nj++)
                    mma_tf32(acc[mi][nj], af[mi], bf[nj]);
        }
    };

    ldA(0); ldB(0);
    stA(0); stB(0);
    __syncthreads();

    int buf = 0;
    for (int k0 = 0; k0 < kEnd; k0 += BK) {
        bool nxt = (k0 + BK) < kEnd;
        if (nxt) { ldA(k0 + BK); ldB(k0 + BK); }   // gmem -> regs (latency hidden by compute)
        compute(buf);                               // reads As/Bs[buf]
        if (nxt) { stA(buf ^ 1); stB(buf ^ 1); }   // regs -> inactive buffer
        buf ^= 1;
        __syncthreads();                            // single barrier per K step
    }

    // epilogue
    #pragma unroll
    for (int mi = 0; mi < 4; mi++) {
        int r = row0 + wm * 64 + mi * 16 + g;
        #pragma unroll
        for (int nj = 0; nj < 4; nj++) {
            int c = col0 + wn * 32 + nj * 8 + tig * 2;
            float v0 = acc[mi][nj][0] * alpha;
            float v1 = acc[mi][nj][1] * alpha;
            float v2 = acc[mi][nj][2] * alpha;
            float v3 = acc[mi][nj][3] * alpha;
            if (mode == 1) {
                v0 = (c     > r    ) ? MIN_MASKED : v0;
                v1 = (c + 1 > r    ) ? MIN_MASKED : v1;
                v2 = (c     > r + 8) ? MIN_MASKED : v2;
                v3 = (c + 1 > r + 8) ? MIN_MASKED : v3;
            }
            if (c < N) {    // N always even
                float* p0 = C + (long long)r * ldc + c;
                float* p1 = C + (long long)(r + 8) * ldc + c;
                p0[0] = v0; p0[1] = v1;
                p1[0] = v2; p1[1] = v3;
            }
        }
    }
}

// ---------------- rmsnorm(kva) + RoPE(k_pe) -> k_full ----------------
__global__ void kva_rms_rope_kernel(const float* __restrict__ comp,
                                    const float* __restrict__ kv_ln,
                                    const int*   __restrict__ pos_ids,
                                    float* __restrict__ kfull)
{
    int s = blockIdx.x;
    const float* x = comp + (long long)s * CDIM;
    float* out = kfull + (long long)s * CDIM;

    __shared__ float red[128];
    float ss = 0.0f;
    for (int i = threadIdx.x; i < KV_LORA; i += 128) { float v = x[i]; ss += v * v; }
    red[threadIdx.x] = ss; __syncthreads();
    for (int st = 64; st > 0; st >>= 1) {
        if (threadIdx.x < st) red[threadIdx.x] += red[threadIdx.x + st];
        __syncthreads();
    }
    float scale = rsqrtf(red[0] / (float)KV_LORA + 1e-6f);

    for (int i = threadIdx.x; i < KV_LORA; i += 128)
        out[i] = x[i] * scale * kv_ln[i];

    if (threadIdx.x < ROPE_D / 2) {
        int j = threadIdx.x;
        float pos  = (float)pos_ids[s];
        float invf = powf(10000.0f, -(float)(2 * j) / (float)ROPE_D);
        float ang  = pos * invf;
        float c = cosf(ang), sn = sinf(ang);
        float x0 = x[KV_LORA + 2 * j];
        float x1 = x[KV_LORA + 2 * j + 1];
        out[KV_LORA + j]               = x0 * c - x1 * sn;
        out[KV_LORA + ROPE_D / 2 + j]  = x1 * c + x0 * sn;
    }
}

// ---------------- rmsnorm(q_a) ----------------
__global__ void qa_rms_kernel(const float* __restrict__ in,
                              const float* __restrict__ w,
                              float* __restrict__ outp)
{
    int s = blockIdx.x;
    const float* x = in + (long long)s * Q_LORA;
    float* o = outp + (long long)s * Q_LORA;

    __shared__ float red[256];
    float ss = 0.0f;
    for (int i = threadIdx.x; i < Q_LORA; i += 256) { float v = x[i]; ss += v * v; }
    red[threadIdx.x] = ss; __syncthreads();
    for (int st = 128; st > 0; st >>= 1) {
        if (threadIdx.x < st) red[threadIdx.x] += red[threadIdx.x + st];
        __syncthreads();
    }
    float scale = rsqrtf(red[0] / (float)Q_LORA + 1e-6f);
    for (int i = threadIdx.x; i < Q_LORA; i += 256)
        o[i] = x[i] * scale * w[i];
}

// ---------------- RoPE on q_pe, scatter into q_full rope columns ----------------
__global__ void rope_q_kernel(const float* __restrict__ qpe,
                              const int*   __restrict__ pos_ids,
                              float* __restrict__ qfull)
{
    int s = blockIdx.x;
    int h = blockIdx.y;
    int j = threadIdx.x;            // 0..31
    float pos  = (float)pos_ids[s];
    float invf = powf(10000.0f, -(float)(2 * j) / (float)ROPE_D);
    float ang  = pos * invf;
    float c = cosf(ang), sn = sinf(ang);
    const float* x = qpe + (long long)s * (NH * ROPE_D) + h * ROPE_D;
    float x0 = x[2 * j], x1 = x[2 * j + 1];
    float* out = qfull + ((long long)h * S_LEN + s) * CDIM + KV_LORA;
    out[j]                = x0 * c - x1 * sn;
    out[j + ROPE_D / 2]   = x1 * c + x0 * sn;
}

// ---------------- row softmax over causal prefix of logits [NH*S, S] ----------------
// Only columns [0, ((s>>7)+1)<<7) are stored by the causal QK^T; masked entries
// within that prefix hold -10000, so exp underflows to exactly 0 and the
// denominator equals the full-row softmax denominator.
__global__ void softmax_kernel(float* __restrict__ logits)
{
    long long row = blockIdx.x;
    int s = (int)(row & (S_LEN - 1));
    int limit = ((s >> 7) + 1) << 7;          // causal prefix, multiple of 128
    float* p = logits + row * S_LEN;
    int tid = threadIdx.x;

    float v[8];
    int cnt = 0;
    float m = -1e30f;
    for (int i = tid; i < limit; i += 256) { v[cnt] = p[i]; m = fmaxf(m, v[cnt]); cnt++; }

    __shared__ float red[256];
    red[tid] = m; __syncthreads();
    for (int st = 128; st > 0; st >>= 1) {
        if (tid < st) red[tid] = fmaxf(red[tid], red[tid + st]);
        __syncthreads();
    }
    m = red[0]; __syncthreads();

    float sum = 0.0f;
    for (int j = 0; j < cnt; j++) { v[j] = __expf(v[j] - m); sum += v[j]; }
    red[tid] = sum; __syncthreads();
    for (int st = 128; st > 0; st >>= 1) {
        if (tid < st) red[tid] += red[tid + st];
        __syncthreads();
    }
    float inv = 1.0f / red[0];
    cnt = 0;
    for (int i = tid; i < limit; i += 256) { p[i] = v[cnt] * inv; cnt++; }
}

// ---------------- host launcher ----------------
static void launch_gemm(bool transb, const float* A, const float* B, float* C,
                        int M, int N, int K, int lda, int ldb, int ldc,
                        long long sA, long long sB, long long sC,
                        int batch, float alpha, int mode)
{
    dim3 grid((N + BN - 1) / BN, M / BM, batch);
    if (transb)
        gemm_tc_kernel<true><<<grid, 256>>>(A, B, C, M, N, K, lda, ldb, ldc, sA, sB, sC, alpha, mode);
    else
        gemm_tc_kernel<false><<<grid, 256>>>(A, B, C, M, N, K, lda, ldb, ldc, sA, sB, sC, alpha, mode);
}

extern "C" void kernel_launch(void* const* d_in, const int* in_sizes, int n_in,
                              void* d_out, int out_size)
{
    (void)in_sizes; (void)n_in; (void)out_size;
    const float* X        = (const float*)d_in[0];   // [S, HID]
    const int*   pos      = (const int*)d_in[2];     // [1, S]
    const float* W_kv_a   = (const float*)d_in[3];   // [HID, CDIM]
    const float* W_q_a    = (const float*)d_in[4];   // [HID, Q_LORA]
    const float* q_ln     = (const float*)d_in[5];   // [Q_LORA]
    const float* kv_ln    = (const float*)d_in[6];   // [KV_LORA]
    const float* q_rope_w = (const float*)d_in[7];   // [Q_LORA, NH*ROPE_D]
    const float* fusedqk  = (const float*)d_in[8];   // [NH, Q_LORA, KV_LORA]
    const float* v_up     = (const float*)d_in[9];   // [NH, KV_LORA, V_D]
    const float* W_o      = (const float*)d_in[10];  // [NH*V_D, HID]
    float* out = (float*)d_out;                      // [S, HID]

    float *comp, *qa_pre, *qa, *qpe, *kfull, *qfull, *logits, *ctx, *attnout;
    cudaGetSymbolAddress((void**)&comp,    g_compressed);
    cudaGetSymbolAddress((void**)&qa_pre,  g_qa_pre);
    cudaGetSymbolAddress((void**)&qa,      g_qa);
    cudaGetSymbolAddress((void**)&qpe,     g_qpe);
    cudaGetSymbolAddress((void**)&kfull,   g_kfull);
    cudaGetSymbolAddress((void**)&qfull,   g_qfull);
    cudaGetSymbolAddress((void**)&logits,  g_logits);
    cudaGetSymbolAddress((void**)&ctx,     g_ctx);
    cudaGetSymbolAddress((void**)&attnout, g_attnout);

    const float scale = 1.0f / sqrtf(192.0f);   // 1/sqrt(NOPE_D + ROPE_D)

    // 1) compressed = X @ W_kv_a                      [S, CDIM]
    launch_gemm(false, X, W_kv_a, comp, S_LEN, CDIM, HID, HID, CDIM, CDIM, 0, 0, 0, 1, 1.0f, 0);
    // 2) qa_pre = X @ W_q_a                           [S, Q_LORA]
    launch_gemm(false, X, W_q_a, qa_pre, S_LEN, Q_LORA, HID, HID, Q_LORA, Q_LORA, 0, 0, 0, 1, 1.0f, 0);
    // 3) k_full = concat(rmsnorm(kva), rope(k_pe))    [S, CDIM]
    kva_rms_rope_kernel<<<S_LEN, 128>>>(comp, kv_ln, pos, kfull);
    // 4) qa = rmsnorm(qa_pre)                         [S, Q_LORA]
    qa_rms_kernel<<<S_LEN, 256>>>(qa_pre, q_ln, qa);
    // 5) qpe = qa @ q_rope_w                          [S, NH*ROPE_D]
    launch_gemm(false, qa, q_rope_w, qpe, S_LEN, NH * ROPE_D, Q_LORA,
                Q_LORA, NH * ROPE_D, NH * ROPE_D, 0, 0, 0, 1, 1.0f, 0);
    // 6) rope(q_pe) -> q_full[:, :, 512:576]
    rope_q_kernel<<<dim3(S_LEN, NH), ROPE_D / 2>>>(qpe, pos, qfull);
    // 7) dq = qa @ fusedqk[h] -> q_full[:, :, :512]   (batched over heads)
    launch_gemm(false, qa, fusedqk, qfull, S_LEN, KV_LORA, Q_LORA,
                Q_LORA, KV_LORA, CDIM,
                0, (long long)Q_LORA * KV_LORA, (long long)S_LEN * CDIM,
                NH, 1.0f, 0);
    // 8) logits = scale * q_full @ k_full^T, causal   (batched, TRANSB, skip masked blocks)
    launch_gemm(true, qfull, kfull, logits, S_LEN, S_LEN, CDIM,
                CDIM, CDIM, S_LEN,
                (long long)S_LEN * CDIM, 0, (long long)S_LEN * S_LEN,
                NH, scale, 1);
    // 9) softmax over causal prefix
    softmax_kernel<<<NH * S_LEN, 256>>>(logits);
    // 10) ctx = probs @ kva  (V = first 512 cols of k_full), causal K-limit
    launch_gemm(false, logits, kfull, ctx, S_LEN, KV_LORA, S_LEN,
                S_LEN, CDIM, KV_LORA,
                (long long)S_LEN * S_LEN, 0, (long long)S_LEN * KV_LORA,
                NH, 1.0f, 2);
    // 11) attnout[:, h*128:(h+1)*128] = ctx[h] @ v_up[h]
    launch_gemm(false, ctx, v_up, attnout, S_LEN, V_D, KV_LORA,
                KV_LORA, V_D, NH * V_D,
                (long long)S_LEN * KV_LORA, (long long)KV_LORA * V_D, (long long)V_D,
                NH, 1.0f, 0);
    // 12) out = attnout @ W_o                          [S, HID]
    launch_gemm(false, attnout, W_o, out, S_LEN, HID, NH * V_D,
                NH * V_D, HID, HID, 0, 0, 0, 1, 1.0f, 0);
}

// round 6
// speedup vs baseline: 1.1850x; 1.1555x over previous
#include <cuda_runtime.h>
#include <math.h>
#include <stdint.h>

// ---------------- problem constants ----------------
#define S_LEN   2048
#define HID     7168
#define NH      32
#define Q_LORA  1536
#define KV_LORA 512
#define ROPE_D  64
#define CDIM    576
#define V_D     128
#define MIN_MASKED (-10000.0f)

// ---------------- scratch ----------------
__device__ float g_compressed[(size_t)S_LEN * CDIM];
__device__ float g_qa_pre[(size_t)S_LEN * Q_LORA];
__device__ float g_qa[(size_t)S_LEN * Q_LORA];
__device__ float g_qpe[(size_t)S_LEN * (NH * ROPE_D)];
__device__ float g_kfull[(size_t)S_LEN * CDIM];
__device__ float g_qfull[(size_t)NH * S_LEN * CDIM];
__device__ float g_logits[(size_t)NH * S_LEN * S_LEN];
__device__ float g_ctx[(size_t)NH * S_LEN * KV_LORA];
__device__ float g_attnout[(size_t)S_LEN * (NH * V_D)];
// pre-rounded (tf32-grid) copies of raw inputs
__device__ float g_xr  [(size_t)S_LEN * HID];
__device__ float g_wkvr[(size_t)HID * CDIM];
__device__ float g_wqr [(size_t)HID * Q_LORA];
__device__ float g_qrwr[(size_t)Q_LORA * (NH * ROPE_D)];
__device__ float g_fqkr[(size_t)NH * Q_LORA * KV_LORA];
__device__ float g_vupr[(size_t)NH * KV_LORA * V_D];
__device__ float g_wor [(size_t)(NH * V_D) * HID];

// ---------------- helpers ----------------
__device__ __forceinline__ float rna_tf32(float x) {
    unsigned u;
    asm("cvt.rna.tf32.f32 %0, %1;" : "=r"(u) : "f"(x));
    return __uint_as_float(u);
}
__device__ __forceinline__ void mma_tf32(float (&c)[4], const unsigned (&a)[4], const unsigned (&b)[2]) {
    asm volatile(
        "mma.sync.aligned.m16n8k8.row.col.f32.tf32.tf32.f32 "
        "{%0,%1,%2,%3}, {%4,%5,%6,%7}, {%8,%9}, {%0,%1,%2,%3};"
        : "+f"(c[0]), "+f"(c[1]), "+f"(c[2]), "+f"(c[3])
        : "r"(a[0]), "r"(a[1]), "r"(a[2]), "r"(a[3]), "r"(b[0]), "r"(b[1]));
}
__device__ __forceinline__ void cpasync16(uint32_t dst, const float* src, int srcsize) {
    asm volatile("cp.async.cg.shared.global [%0], [%1], 16, %2;"
                 :: "r"(dst), "l"(src), "r"(srcsize) : "memory");
}
__device__ __forceinline__ void cp_commit() { asm volatile("cp.async.commit_group;" ::: "memory"); }
template<int N> __device__ __forceinline__ void cp_wait() { asm volatile("cp.async.wait_group %0;" :: "n"(N) : "memory"); }

// ---------------- tf32 GEMM, 4-stage cp.async pipeline ----------------
// C[M,N] = alpha * A[M,K] @ B ; all operand buffers hold tf32-grid values.
//   TRANSB=false: B is [K,N] row-major; true: B is [N,K] row-major.
// mode 0 plain; mode 1 causal epilogue + full-block skip; mode 2 kEnd=min(K,row0+128).
// round_out: epilogue stores rna-rounded values (for buffers consumed by GEMMs).
#define ASW 20          // A smem row stride (floats)
#define BSW 136         // B smem row stride, non-trans
#define BTW 20          // B smem row stride, trans
#define A_BYTES (128 * ASW * 4)

template<bool TRANSB>
__global__ void __launch_bounds__(256, 2)
gemm_tc_kernel(const float* __restrict__ A, const float* __restrict__ B,
               float* __restrict__ C,
               int M, int N, int K, int lda, int ldb, int ldc,
               long long sA, long long sB, long long sC,
               float alpha, int mode, int round_out)
{
    constexpr int B_BYTES = TRANSB ? (128 * BTW * 4) : (16 * BSW * 4);
    constexpr int STG = A_BYTES + B_BYTES;
    extern __shared__ char smem[];

    const long long bz = blockIdx.z;
    A += bz * sA;  B += bz * sB;  C += bz * sC;

    const int row0 = blockIdx.x * 128;
    const int col0 = blockIdx.y * 128;
    if (mode == 1 && col0 >= row0 + 128) return;

    const int tid  = threadIdx.x;
    const int lane = tid & 31;
    const int wid  = tid >> 5;
    const int wm   = wid >> 2;
    const int wn   = wid & 3;
    const int g    = lane >> 2;
    const int tig  = lane & 3;

    uint32_t sbase;
    asm("{ .reg .u64 t; cvta.to.shared.u64 t, %1; cvt.u32.u64 %0, t; }" : "=r"(sbase) : "l"(smem));

    int kEnd = (mode == 2) ? min(K, row0 + 128) : K;
    const int T = kEnd >> 4;       // BK = 16

    auto issue = [&](int t) {
        int k0 = t << 4;
        uint32_t ab = sbase + (uint32_t)((t & 3) * STG);
        #pragma unroll
        for (int e = 0; e < 2; e++) {
            int idx = tid + e * 256;
            int r = idx >> 2, q = idx & 3;
            cpasync16(ab + (uint32_t)((r * ASW + 4 * q) * 4),
                      A + (long long)(row0 + r) * lda + k0 + 4 * q, 16);
        }
        uint32_t bb = ab + A_BYTES;
        if (TRANSB) {
            #pragma unroll
            for (int e = 0; e < 2; e++) {
                int idx = tid + e * 256;
                int n = idx >> 2, q = idx & 3;
                bool ok = (col0 + n) < N;
                const float* src = ok ? (B + (long long)(col0 + n) * ldb + k0 + 4 * q) : B;
                cpasync16(bb + (uint32_t)((n * BTW + 4 * q) * 4), src, ok ? 16 : 0);
            }
        } else {
            #pragma unroll
            for (int e = 0; e < 2; e++) {
                int idx = tid + e * 256;
                int k = idx >> 5, nq = idx & 31;
                bool ok = (col0 + 4 * nq) < N;
                const float* src = ok ? (B + (long long)(k0 + k) * ldb + col0 + 4 * nq) : B;
                cpasync16(bb + (uint32_t)((k * BSW + 4 * nq) * 4), src, ok ? 16 : 0);
            }
        }
        cp_commit();
    };

    float acc[4][4][4] = {};

    // prologue: stages 0..2
    issue(0);
    if (1 < T) issue(1);
    if (2 < T) issue(2);

    for (int t = 0; t < T; t++) {
        int rem = T - t - 1;
        if (rem >= 2)      cp_wait<2>();
        else if (rem == 1) cp_wait<1>();
        else               cp_wait<0>();
        __syncthreads();

        if (t + 3 < T) issue(t + 3);

        const float* As = (const float*)(smem + (t & 3) * STG);
        const float* Bs = (const float*)(smem + (t & 3) * STG + A_BYTES);

        #pragma unroll
        for (int kk = 0; kk < 16; kk += 8) {
            unsigned af[4][4], bf[4][2];
            #pragma unroll
            for (int mi = 0; mi < 4; mi++) {
                int mb = wm * 64 + mi * 16 + g;
                af[mi][0] = __float_as_uint(As[(mb    ) * ASW + kk + tig    ]);
                af[mi][1] = __float_as_uint(As[(mb + 8) * ASW + kk + tig    ]);
                af[mi][2] = __float_as_uint(As[(mb    ) * ASW + kk + tig + 4]);
                af[mi][3] = __float_as_uint(As[(mb + 8) * ASW + kk + tig + 4]);
            }
            #pragma unroll
            for (int nj = 0; nj < 4; nj++) {
                int nb = wn * 32 + nj * 8 + g;
                if (TRANSB) {
                    bf[nj][0] = __float_as_uint(Bs[nb * BTW + kk + tig    ]);
                    bf[nj][1] = __float_as_uint(Bs[nb * BTW + kk + tig + 4]);
                } else {
                    bf[nj][0] = __float_as_uint(Bs[(kk + tig    ) * BSW + nb]);
                    bf[nj][1] = __float_as_uint(Bs[(kk + tig + 4) * BSW + nb]);
                }
            }
            #pragma unroll
            for (int mi = 0; mi < 4; mi++)
                #pragma unroll
                for (int nj = 0; nj < 4; nj++)
                    mma_tf32(acc[mi][nj], af[mi], bf[nj]);
        }
        __syncthreads();
    }

    // epilogue (same value path as prior rounds; optional rna for GEMM-consumed outputs)
    #pragma unroll
    for (int mi = 0; mi < 4; mi++) {
        int r = row0 + wm * 64 + mi * 16 + g;
        #pragma unroll
        for (int nj = 0; nj < 4; nj++) {
            int c = col0 + wn * 32 + nj * 8 + tig * 2;
            float v0 = acc[mi][nj][0] * alpha;
            float v1 = acc[mi][nj][1] * alpha;
            float v2 = acc[mi][nj][2] * alpha;
            float v3 = acc[mi][nj][3] * alpha;
            if (mode == 1) {
                v0 = (c     > r    ) ? MIN_MASKED : v0;
                v1 = (c + 1 > r    ) ? MIN_MASKED : v1;
                v2 = (c     > r + 8) ? MIN_MASKED : v2;
                v3 = (c + 1 > r + 8) ? MIN_MASKED : v3;
            }
            if (round_out) {
                v0 = rna_tf32(v0); v1 = rna_tf32(v1);
                v2 = rna_tf32(v2); v3 = rna_tf32(v3);
            }
            if (c < N) {
                float* p0 = C + (long long)r * ldc + c;
                float* p1 = C + (long long)(r + 8) * ldc + c;
                p0[0] = v0; p0[1] = v1;
                p1[0] = v2; p1[1] = v3;
            }
        }
    }
}

// ---------------- rna copy prepass ----------------
__global__ void rna_copy_kernel(const float4* __restrict__ src, float4* __restrict__ dst, int n4)
{
    int i = blockIdx.x * blockDim.x + threadIdx.x;
    int stride = gridDim.x * blockDim.x;
    for (; i < n4; i += stride) {
        float4 v = src[i];
        v.x = rna_tf32(v.x); v.y = rna_tf32(v.y);
        v.z = rna_tf32(v.z); v.w = rna_tf32(v.w);
        dst[i] = v;
    }
}

// ---------------- rmsnorm(kva) + RoPE(k_pe) -> k_full (tf32-grid out) ----------------
__global__ void kva_rms_rope_kernel(const float* __restrict__ comp,
                                    const float* __restrict__ kv_ln,
                                    const int*   __restrict__ pos_ids,
                                    float* __restrict__ kfull)
{
    int s = blockIdx.x;
    const float* x = comp + (long long)s * CDIM;
    float* out = kfull + (long long)s * CDIM;

    __shared__ float red[128];
    float ss = 0.0f;
    for (int i = threadIdx.x; i < KV_LORA; i += 128) { float v = x[i]; ss += v * v; }
    red[threadIdx.x] = ss; __syncthreads();
    for (int st = 64; st > 0; st >>= 1) {
        if (threadIdx.x < st) red[threadIdx.x] += red[threadIdx.x + st];
        __syncthreads();
    }
    float scale = rsqrtf(red[0] / (float)KV_LORA + 1e-6f);

    for (int i = threadIdx.x; i < KV_LORA; i += 128)
        out[i] = rna_tf32(x[i] * scale * kv_ln[i]);

    if (threadIdx.x < ROPE_D / 2) {
        int j = threadIdx.x;
        float pos  = (float)pos_ids[s];
        float invf = powf(10000.0f, -(float)(2 * j) / (float)ROPE_D);
        float ang  = pos * invf;
        float c = cosf(ang), sn = sinf(ang);
        float x0 = x[KV_LORA + 2 * j];
        float x1 = x[KV_LORA + 2 * j + 1];
        out[KV_LORA + j]              = rna_tf32(x0 * c - x1 * sn);
        out[KV_LORA + ROPE_D / 2 + j] = rna_tf32(x1 * c + x0 * sn);
    }
}

// ---------------- rmsnorm(q_a) (tf32-grid out) ----------------
__global__ void qa_rms_kernel(const float* __restrict__ in,
                              const float* __restrict__ w,
                              float* __restrict__ outp)
{
    int s = blockIdx.x;
    const float* x = in + (long long)s * Q_LORA;
    float* o = outp + (long long)s * Q_LORA;

    __shared__ float red[256];
    float ss = 0.0f;
    for (int i = threadIdx.x; i < Q_LORA; i += 256) { float v = x[i]; ss += v * v; }
    red[threadIdx.x] = ss; __syncthreads();
    for (int st = 128; st > 0; st >>= 1) {
        if (threadIdx.x < st) red[threadIdx.x] += red[threadIdx.x + st];
        __syncthreads();
    }
    float scale = rsqrtf(red[0] / (float)Q_LORA + 1e-6f);
    for (int i = threadIdx.x; i < Q_LORA; i += 256)
        o[i] = rna_tf32(x[i] * scale * w[i]);
}

// ---------------- RoPE on q_pe -> q_full rope columns (tf32-grid out) ----------------
__global__ void rope_q_kernel(const float* __restrict__ qpe,
                              const int*   __restrict__ pos_ids,
                              float* __restrict__ qfull)
{
    int s = blockIdx.x;
    int h = blockIdx.y;
    int j = threadIdx.x;            // 0..31
    float pos  = (float)pos_ids[s];
    float invf = powf(10000.0f, -(float)(2 * j) / (float)ROPE_D);
    float ang  = pos * invf;
    float c = cosf(ang), sn = sinf(ang);
    const float* x = qpe + (long long)s * (NH * ROPE_D) + h * ROPE_D;
    float x0 = x[2 * j], x1 = x[2 * j + 1];
    float* out = qfull + ((long long)h * S_LEN + s) * CDIM + KV_LORA;
    out[j]              = rna_tf32(x0 * c - x1 * sn);
    out[j + ROPE_D / 2] = rna_tf32(x1 * c + x0 * sn);
}

// ---------------- row softmax over causal prefix (tf32-grid out) ----------------
__global__ void softmax_kernel(float* __restrict__ logits)
{
    long long row = blockIdx.x;
    int s = (int)(row & (S_LEN - 1));
    int limit = ((s >> 7) + 1) << 7;
    float* p = logits + row * S_LEN;
    int tid = threadIdx.x;

    float v[8];
    int cnt = 0;
    float m = -1e30f;
    for (int i = tid; i < limit; i += 256) { v[cnt] = p[i]; m = fmaxf(m, v[cnt]); cnt++; }

    __shared__ float red[256];
    red[tid] = m; __syncthreads();
    for (int st = 128; st > 0; st >>= 1) {
        if (tid < st) red[tid] = fmaxf(red[tid], red[tid + st]);
        __syncthreads();
    }
    m = red[0]; __syncthreads();

    float sum = 0.0f;
    for (int j = 0; j < cnt; j++) { v[j] = __expf(v[j] - m); sum += v[j]; }
    red[tid] = sum; __syncthreads();
    for (int st = 128; st > 0; st >>= 1) {
        if (tid < st) red[tid] += red[tid + st];
        __syncthreads();
    }
    float inv = 1.0f / red[0];
    cnt = 0;
    for (int i = tid; i < limit; i += 256) { p[i] = rna_tf32(v[cnt] * inv); cnt++; }
}

// ---------------- host launchers ----------------
static void launch_gemm(bool transb, const float* A, const float* B, float* C,
                        int M, int N, int K, int lda, int ldb, int ldc,
                        long long sA, long long sB, long long sC,
                        int batch, float alpha, int mode, int round_out)
{
    dim3 grid(M / 128, (N + 127) / 128, batch);
    if (transb) {
        constexpr int STG = A_BYTES + 128 * BTW * 4;
        cudaFuncSetAttribute(gemm_tc_kernel<true>, cudaFuncAttributeMaxDynamicSharedMemorySize, 4 * STG);
        gemm_tc_kernel<true><<<grid, 256, 4 * STG>>>(A, B, C, M, N, K, lda, ldb, ldc, sA, sB, sC, alpha, mode, round_out);
    } else {
        constexpr int STG = A_BYTES + 16 * BSW * 4;
        cudaFuncSetAttribute(gemm_tc_kernel<false>, cudaFuncAttributeMaxDynamicSharedMemorySize, 4 * STG);
        gemm_tc_kernel<false><<<grid, 256, 4 * STG>>>(A, B, C, M, N, K, lda, ldb, ldc, sA, sB, sC, alpha, mode, round_out);
    }
}

static void launch_rna_copy(const float* src, float* dst, size_t n)
{
    int n4 = (int)(n / 4);
    int blocks = (n4 + 255) / 256;
    if (blocks > 8192) blocks = 8192;
    rna_copy_kernel<<<blocks, 256>>>((const float4*)src, (float4*)dst, n4);
}

extern "C" void kernel_launch(void* const* d_in, const int* in_sizes, int n_in,
                              void* d_out, int out_size)
{
    (void)in_sizes; (void)n_in; (void)out_size;
    const float* X        = (const float*)d_in[0];
    const int*   pos      = (const int*)d_in[2];
    const float* W_kv_a   = (const float*)d_in[3];
    const float* W_q_a    = (const float*)d_in[4];
    const float* q_ln     = (const float*)d_in[5];
    const float* kv_ln    = (const float*)d_in[6];
    const float* q_rope_w = (const float*)d_in[7];
    const float* fusedqk  = (const float*)d_in[8];
    const float* v_up     = (const float*)d_in[9];
    const float* W_o      = (const float*)d_in[10];
    float* out = (float*)d_out;

    float *comp, *qa_pre, *qa, *qpe, *kfull, *qfull, *logits, *ctx, *attnout;
    float *xr, *wkvr, *wqr, *qrwr, *fqkr, *vupr, *wor;
    cudaGetSymbolAddress((void**)&comp,    g_compressed);
    cudaGetSymbolAddress((void**)&qa_pre,  g_qa_pre);
    cudaGetSymbolAddress((void**)&qa,      g_qa);
    cudaGetSymbolAddress((void**)&qpe,     g_qpe);
    cudaGetSymbolAddress((void**)&kfull,   g_kfull);
    cudaGetSymbolAddress((void**)&qfull,   g_qfull);
    cudaGetSymbolAddress((void**)&logits,  g_logits);
    cudaGetSymbolAddress((void**)&ctx,     g_ctx);
    cudaGetSymbolAddress((void**)&attnout, g_attnout);
    cudaGetSymbolAddress((void**)&xr,   g_xr);
    cudaGetSymbolAddress((void**)&wkvr, g_wkvr);
    cudaGetSymbolAddress((void**)&wqr,  g_wqr);
    cudaGetSymbolAddress((void**)&qrwr, g_qrwr);
    cudaGetSymbolAddress((void**)&fqkr, g_fqkr);
    cudaGetSymbolAddress((void**)&vupr, g_vupr);
    cudaGetSymbolAddress((void**)&wor,  g_wor);

    const float scale = 1.0f / sqrtf(192.0f);

    // 0) tf32 pre-rounding of raw inputs
    launch_rna_copy(X,        xr,   (size_t)S_LEN * HID);
    launch_rna_copy(W_kv_a,   wkvr, (size_t)HID * CDIM);
    launch_rna_copy(W_q_a,    wqr,  (size_t)HID * Q_LORA);
    launch_rna_copy(q_rope_w, qrwr, (size_t)Q_LORA * (NH * ROPE_D));
    launch_rna_copy(fusedqk,  fqkr, (size_t)NH * Q_LORA * KV_LORA);
    launch_rna_copy(v_up,     vupr, (size_t)NH * KV_LORA * V_D);
    launch_rna_copy(W_o,      wor,  (size_t)(NH * V_D) * HID);

    // 1) compressed = X @ W_kv_a                (fp32 out: feeds rmsnorm)
    launch_gemm(false, xr, wkvr, comp, S_LEN, CDIM, HID, HID, CDIM, CDIM, 0, 0, 0, 1, 1.0f, 0, 0);
    // 2) qa_pre = X @ W_q_a                     (fp32 out: feeds rmsnorm)
    launch_gemm(false, xr, wqr, qa_pre, S_LEN, Q_LORA, HID, HID, Q_LORA, Q_LORA, 0, 0, 0, 1, 1.0f, 0, 0);
    // 3) k_full (tf32-grid)
    kva_rms_rope_kernel<<<S_LEN, 128>>>(comp, kv_ln, pos, kfull);
    // 4) qa (tf32-grid)
    qa_rms_kernel<<<S_LEN, 256>>>(qa_pre, q_ln, qa);
    // 5) qpe = qa @ q_rope_w                    (fp32 out: feeds rope math)
    launch_gemm(false, qa, qrwr, qpe, S_LEN, NH * ROPE_D, Q_LORA,
                Q_LORA, NH * ROPE_D, NH * ROPE_D, 0, 0, 0, 1, 1.0f, 0, 0);
    // 6) rope(q_pe) -> q_full rope cols (tf32-grid)
    rope_q_kernel<<<dim3(S_LEN, NH), ROPE_D / 2>>>(qpe, pos, qfull);
    // 7) dq = qa @ fusedqk[h] -> q_full nope cols (tf32-grid out)
    launch_gemm(false, qa, fqkr, qfull, S_LEN, KV_LORA, Q_LORA,
                Q_LORA, KV_LORA, CDIM,
                0, (long long)Q_LORA * KV_LORA, (long long)S_LEN * CDIM,
                NH, 1.0f, 0, 1);
    // 8) logits (causal, TRANSB; fp32 out for softmax)
    launch_gemm(true, qfull, kfull, logits, S_LEN, S_LEN, CDIM,
                CDIM, CDIM, S_LEN,
                (long long)S_LEN * CDIM, 0, (long long)S_LEN * S_LEN,
                NH, scale, 1, 0);
    // 9) softmax (tf32-grid probs)
    softmax_kernel<<<NH * S_LEN, 256>>>(logits);
    // 10) ctx = probs @ kva (tf32-grid out)
    launch_gemm(false, logits, kfull, ctx, S_LEN, KV_LORA, S_LEN,
                S_LEN, CDIM, KV_LORA,
                (long long)S_LEN * S_LEN, 0, (long long)S_LEN * KV_LORA,
                NH, 1.0f, 2, 1);
    // 11) attnout = ctx[h] @ v_up[h] (tf32-grid out)
    launch_gemm(false, ctx, vupr, attnout, S_LEN, V_D, KV_LORA,
                KV_LORA, V_D, NH * V_D,
                (long long)S_LEN * KV_LORA, (long long)KV_LORA * V_D, (long long)V_D,
                NH, 1.0f, 0, 1);
    // 12) out = attnout @ W_o (fp32 out)
    launch_gemm(false, attnout, wor, out, S_LEN, HID, NH * V_D,
                NH * V_D, HID, HID, 0, 0, 0, 1, 1.0f, 0, 0);
}

// round 7
// speedup vs baseline: 2.1325x; 1.7996x over previous
#include <cuda_runtime.h>
#include <cuda_fp16.h>
#include <math.h>
#include <stdint.h>

// ---------------- problem constants ----------------
#define S_LEN   2048
#define HID     7168
#define NH      32
#define Q_LORA  1536
#define KV_LORA 512
#define ROPE_D  64
#define CDIM    576
#define V_D     128
#define MIN_MASKED (-10000.0f)

// ---------------- scratch ----------------
__device__ float  g_compressed[(size_t)S_LEN * CDIM];
__device__ float  g_qa_pre[(size_t)S_LEN * Q_LORA];
__device__ float  g_qpe[(size_t)S_LEN * (NH * ROPE_D)];
__device__ float  g_logits[(size_t)NH * S_LEN * S_LEN];
// fp16 operand buffers
__device__ __half g_xh   [(size_t)S_LEN * HID];
__device__ __half g_qah  [(size_t)S_LEN * Q_LORA];
__device__ __half g_kfullh[(size_t)S_LEN * CDIM];
__device__ __half g_kvaT [(size_t)KV_LORA * S_LEN];
__device__ __half g_qfullh[(size_t)NH * S_LEN * CDIM];
__device__ __half g_probsh[(size_t)NH * S_LEN * S_LEN];
__device__ __half g_ctxh [(size_t)NH * S_LEN * KV_LORA];
__device__ __half g_attnh[(size_t)S_LEN * (NH * V_D)];
// transposed fp16 weights ([N][K])
__device__ __half g_wkvT[(size_t)CDIM * HID];
__device__ __half g_wqT [(size_t)Q_LORA * HID];
__device__ __half g_qrwT[(size_t)(NH * ROPE_D) * Q_LORA];
__device__ __half g_fqkT[(size_t)NH * KV_LORA * Q_LORA];
__device__ __half g_vupT[(size_t)NH * V_D * KV_LORA];
__device__ __half g_woT [(size_t)HID * (NH * V_D)];

// ---------------- helpers ----------------
__device__ __forceinline__ void mma16(float (&c)[4], const unsigned (&a)[4], const unsigned (&b)[2]) {
    asm volatile(
        "mma.sync.aligned.m16n8k16.row.col.f32.f16.f16.f32 "
        "{%0,%1,%2,%3}, {%4,%5,%6,%7}, {%8,%9}, {%0,%1,%2,%3};"
        : "+f"(c[0]), "+f"(c[1]), "+f"(c[2]), "+f"(c[3])
        : "r"(a[0]), "r"(a[1]), "r"(a[2]), "r"(a[3]), "r"(b[0]), "r"(b[1]));
}
__device__ __forceinline__ void cpasync16(uint32_t dst, const void* src, int srcsize) {
    asm volatile("cp.async.cg.shared.global [%0], [%1], 16, %2;"
                 :: "r"(dst), "l"(src), "r"(srcsize) : "memory");
}
__device__ __forceinline__ void cp_commit() { asm volatile("cp.async.commit_group;" ::: "memory"); }
template<int N> __device__ __forceinline__ void cp_wait() { asm volatile("cp.async.wait_group %0;" :: "n"(N) : "memory"); }

// ---------------- fp16 tensor-core GEMM, 4-stage cp.async pipeline ----------------
// C[M,N] = alpha * A[M,K] @ B^T, with A fp16 [M][K] (lda), B fp16 [N][K] (ldb).
// mode 0 plain; mode 1 causal epilogue + full-block skip; mode 2 kEnd=min(K,row0+128).
// Tile 128x128, BK=32. Smem: per stage A 8KB + B 8KB, chunk-XOR swizzle.
#define STG_BYTES 16384

template<bool HALF_OUT>
__global__ void __launch_bounds__(256, 2)
gemm16_kernel(const __half* __restrict__ A, const __half* __restrict__ B, void* Cv,
              int M, int N, int K, int lda, int ldb, int ldc,
              long long sA, long long sB, long long sC,
              float alpha, int mode)
{
    extern __shared__ char smem[];
    const long long bz = blockIdx.z;
    A += bz * sA;  B += bz * sB;

    const int row0 = blockIdx.x * 128;
    const int col0 = blockIdx.y * 128;
    if (mode == 1 && col0 >= row0 + 128) return;

    float*  Cf = (float*)Cv  + bz * sC;
    __half* Ch = (__half*)Cv + bz * sC;

    const int tid  = threadIdx.x;
    const int lane = tid & 31;
    const int wid  = tid >> 5;
    const int wm   = wid >> 2;
    const int wn   = wid & 3;
    const int g    = lane >> 2;
    const int tig  = lane & 3;

    uint32_t sbase;
    asm("{ .reg .u64 t; cvta.to.shared.u64 t, %1; cvt.u32.u64 %0, t; }" : "=r"(sbase) : "l"(smem));

    const int kEnd = (mode == 2) ? min(K, row0 + 128) : K;
    const int T = kEnd >> 5;

    auto issue = [&](int t) {
        int k0 = t << 5;
        uint32_t st = sbase + (uint32_t)((t & 3) * STG_BYTES);
        #pragma unroll
        for (int e = 0; e < 2; e++) {           // A: 512 chunks of 16B
            int id = tid + e * 256;
            int r = id >> 2, c = id & 3;
            uint32_t dst = st + (uint32_t)(r * 64 + ((c ^ ((r >> 1) & 3)) * 16));
            cpasync16(dst, A + (long long)(row0 + r) * lda + k0 + c * 8, 16);
        }
        #pragma unroll
        for (int e = 0; e < 2; e++) {           // B: 512 chunks
            int id = tid + e * 256;
            int n = id >> 2, c = id & 3;
            uint32_t dst = st + 8192u + (uint32_t)(n * 64 + ((c ^ ((n >> 1) & 3)) * 16));
            bool ok = (col0 + n) < N;
            const __half* src = ok ? (B + (long long)(col0 + n) * ldb + k0 + c * 8) : B;
            cpasync16(dst, src, ok ? 16 : 0);
        }
        cp_commit();
    };

    float acc[4][4][4] = {};

    issue(0);
    if (1 < T) issue(1);
    if (2 < T) issue(2);

    for (int t = 0; t < T; t++) {
        int rem = T - t - 1;
        if (rem >= 2)      cp_wait<2>();
        else if (rem == 1) cp_wait<1>();
        else               cp_wait<0>();
        __syncthreads();

        if (t + 3 < T) issue(t + 3);

        const char* As = smem + (t & 3) * STG_BYTES;
        const char* Bs = As + 8192;

        #pragma unroll
        for (int kk16 = 0; kk16 < 2; kk16++) {
            unsigned af[4][4], bf[4][2];
            #pragma unroll
            for (int mi = 0; mi < 4; mi++) {
                int mb = wm * 64 + mi * 16 + g;
                int c0 = (kk16 * 2) ^ ((mb >> 1) & 3);   // phys chunk for a0/a1
                const char* rp  = As + mb * 64 + 4 * tig;
                const char* rp8 = As + (mb + 8) * 64 + 4 * tig;   // same swizzle (+8 keeps (r>>1)&3)
                af[mi][0] = *(const unsigned*)(rp  + c0 * 16);
                af[mi][1] = *(const unsigned*)(rp8 + c0 * 16);
                af[mi][2] = *(const unsigned*)(rp  + (c0 ^ 1) * 16);
                af[mi][3] = *(const unsigned*)(rp8 + (c0 ^ 1) * 16);
            }
            #pragma unroll
            for (int nj = 0; nj < 4; nj++) {
                int nb = wn * 32 + nj * 8 + g;
                int c0 = (kk16 * 2) ^ ((nb >> 1) & 3);
                const char* rp = Bs + nb * 64 + 4 * tig;
                bf[nj][0] = *(const unsigned*)(rp + c0 * 16);
                bf[nj][1] = *(const unsigned*)(rp + (c0 ^ 1) * 16);
            }
            #pragma unroll
            for (int mi = 0; mi < 4; mi++)
                #pragma unroll
                for (int nj = 0; nj < 4; nj++)
                    mma16(acc[mi][nj], af[mi], bf[nj]);
        }
        __syncthreads();
    }

    // epilogue
    #pragma unroll
    for (int mi = 0; mi < 4; mi++) {
        int r = row0 + wm * 64 + mi * 16 + g;
        #pragma unroll
        for (int nj = 0; nj < 4; nj++) {
            int c = col0 + wn * 32 + nj * 8 + tig * 2;
            float v0 = acc[mi][nj][0] * alpha;
            float v1 = acc[mi][nj][1] * alpha;
            float v2 = acc[mi][nj][2] * alpha;
            float v3 = acc[mi][nj][3] * alpha;
            if (mode == 1) {
                v0 = (c     > r    ) ? MIN_MASKED : v0;
                v1 = (c + 1 > r    ) ? MIN_MASKED : v1;
                v2 = (c     > r + 8) ? MIN_MASKED : v2;
                v3 = (c + 1 > r + 8) ? MIN_MASKED : v3;
            }
            if (c < N) {
                if (HALF_OUT) {
                    *(__half2*)(Ch + (long long)r * ldc + c) =
                        __halves2half2(__float2half(v0), __float2half(v1));
                    *(__half2*)(Ch + (long long)(r + 8) * ldc + c) =
                        __halves2half2(__float2half(v2), __float2half(v3));
                } else {
                    float* p0 = Cf + (long long)r * ldc + c;
                    float* p1 = Cf + (long long)(r + 8) * ldc + c;
                    p0[0] = v0; p0[1] = v1;
                    p1[0] = v2; p1[1] = v3;
                }
            }
        }
    }
}

// ---------------- prepass: fp32 -> fp16 convert ----------------
__global__ void convert_f2h_kernel(const float4* __restrict__ src, __half2* __restrict__ dst, int n4)
{
    int i = blockIdx.x * blockDim.x + threadIdx.x;
    int stride = gridDim.x * blockDim.x;
    for (; i < n4; i += stride) {
        float4 v = src[i];
        dst[2 * i]     = __floats2half2_rn(v.x, v.y);
        dst[2 * i + 1] = __floats2half2_rn(v.z, v.w);
    }
}

// ---------------- prepass: fp32 [R][C] -> fp16 [C][R] (batched via z) ----------------
__global__ void transpose_f2h_kernel(const float* __restrict__ src, __half* __restrict__ dst,
                                     int R, int C)
{
    long long z = blockIdx.z;
    src += z * (long long)R * C;
    dst += z * (long long)R * C;
    __shared__ float t[32][33];
    int c0 = blockIdx.x * 32, r0 = blockIdx.y * 32;
    int x = threadIdx.x, y = threadIdx.y;    // block (32, 8)
    #pragma unroll
    for (int j = 0; j < 4; j++) {
        int r = r0 + y + 8 * j;
        if (r < R && c0 + x < C) t[y + 8 * j][x] = src[(long long)r * C + c0 + x];
    }
    __syncthreads();
    #pragma unroll
    for (int j = 0; j < 4; j++) {
        int c = c0 + y + 8 * j;
        if (c < C && r0 + x < R) dst[(long long)c * R + r0 + x] = __float2half(t[x][y + 8 * j]);
    }
}

// ---------------- kva^T: kfullh[t][0:512] -> kvaT[c][t], fp16 ----------------
__global__ void transpose_kva_kernel(const __half* __restrict__ src, __half* __restrict__ dst)
{
    __shared__ __half t[32][33];
    int c0 = blockIdx.x * 32, r0 = blockIdx.y * 32;    // c over KV_LORA, r over S
    int x = threadIdx.x, y = threadIdx.y;
    #pragma unroll
    for (int j = 0; j < 4; j++)
        t[y + 8 * j][x] = src[(long long)(r0 + y + 8 * j) * CDIM + c0 + x];
    __syncthreads();
    #pragma unroll
    for (int j = 0; j < 4; j++)
        dst[(long long)(c0 + y + 8 * j) * S_LEN + r0 + x] = t[x][y + 8 * j];
}

// ---------------- rmsnorm(kva) + RoPE(k_pe) -> kfullh (fp16) ----------------
__global__ void kva_rms_rope_kernel(const float* __restrict__ comp,
                                    const float* __restrict__ kv_ln,
                                    const int*   __restrict__ pos_ids,
                                    __half* __restrict__ kfull)
{
    int s = blockIdx.x;
    const float* x = comp + (long long)s * CDIM;
    __half* out = kfull + (long long)s * CDIM;

    __shared__ float red[128];
    float ss = 0.0f;
    for (int i = threadIdx.x; i < KV_LORA; i += 128) { float v = x[i]; ss += v * v; }
    red[threadIdx.x] = ss; __syncthreads();
    for (int st = 64; st > 0; st >>= 1) {
        if (threadIdx.x < st) red[threadIdx.x] += red[threadIdx.x + st];
        __syncthreads();
    }
    float scale = rsqrtf(red[0] / (float)KV_LORA + 1e-6f);

    for (int i = threadIdx.x; i < KV_LORA; i += 128)
        out[i] = __float2half(x[i] * scale * kv_ln[i]);

    if (threadIdx.x < ROPE_D / 2) {
        int j = threadIdx.x;
        float pos  = (float)pos_ids[s];
        float invf = powf(10000.0f, -(float)(2 * j) / (float)ROPE_D);
        float ang  = pos * invf;
        float c = cosf(ang), sn = sinf(ang);
        float x0 = x[KV_LORA + 2 * j];
        float x1 = x[KV_LORA + 2 * j + 1];
        out[KV_LORA + j]              = __float2half(x0 * c - x1 * sn);
        out[KV_LORA + ROPE_D / 2 + j] = __float2half(x1 * c + x0 * sn);
    }
}

// ---------------- rmsnorm(q_a) -> fp16 ----------------
__global__ void qa_rms_kernel(const float* __restrict__ in,
                              const float* __restrict__ w,
                              __half* __restrict__ outp)
{
    int s = blockIdx.x;
    const float* x = in + (long long)s * Q_LORA;
    __half* o = outp + (long long)s * Q_LORA;

    __shared__ float red[256];
    float ss = 0.0f;
    for (int i = threadIdx.x; i < Q_LORA; i += 256) { float v = x[i]; ss += v * v; }
    red[threadIdx.x] = ss; __syncthreads();
    for (int st = 128; st > 0; st >>= 1) {
        if (threadIdx.x < st) red[threadIdx.x] += red[threadIdx.x + st];
        __syncthreads();
    }
    float scale = rsqrtf(red[0] / (float)Q_LORA + 1e-6f);
    for (int i = threadIdx.x; i < Q_LORA; i += 256)
        o[i] = __float2half(x[i] * scale * w[i]);
}

// ---------------- RoPE on q_pe -> qfullh rope columns (fp16) ----------------
__global__ void rope_q_kernel(const float* __restrict__ qpe,
                              const int*   __restrict__ pos_ids,
                              __half* __restrict__ qfull)
{
    int s = blockIdx.x;
    int h = blockIdx.y;
    int j = threadIdx.x;            // 0..31
    float pos  = (float)pos_ids[s];
    float invf = powf(10000.0f, -(float)(2 * j) / (float)ROPE_D);
    float ang  = pos * invf;
    float c = cosf(ang), sn = sinf(ang);
    const float* x = qpe + (long long)s * (NH * ROPE_D) + h * ROPE_D;
    float x0 = x[2 * j], x1 = x[2 * j + 1];
    __half* out = qfull + ((long long)h * S_LEN + s) * CDIM + KV_LORA;
    out[j]              = __float2half(x0 * c - x1 * sn);
    out[j + ROPE_D / 2] = __float2half(x1 * c + x0 * sn);
}

// ---------------- softmax over causal prefix; writes 512*p as fp16 ----------------
// (x512 keeps tiny probs out of fp16 subnormal range; PV epilogue multiplies by 1/512.)
__global__ void softmax_kernel(const float* __restrict__ logits, __half* __restrict__ probs)
{
    long long row = blockIdx.x;
    int s = (int)(row & (S_LEN - 1));
    int limit = ((s >> 7) + 1) << 7;
    const float* p = logits + row * S_LEN;
    __half* q = probs + row * S_LEN;
    int tid = threadIdx.x;

    float v[8];
    int cnt = 0;
    float m = -1e30f;
    for (int i = tid; i < limit; i += 256) { v[cnt] = p[i]; m = fmaxf(m, v[cnt]); cnt++; }

    __shared__ float red[256];
    red[tid] = m; __syncthreads();
    for (int st = 128; st > 0; st >>= 1) {
        if (tid < st) red[tid] = fmaxf(red[tid], red[tid + st]);
        __syncthreads();
    }
    m = red[0]; __syncthreads();

    float sum = 0.0f;
    for (int j = 0; j < cnt; j++) { v[j] = __expf(v[j] - m); sum += v[j]; }
    red[tid] = sum; __syncthreads();
    for (int st = 128; st > 0; st >>= 1) {
        if (tid < st) red[tid] += red[tid + st];
        __syncthreads();
    }
    float inv = 512.0f / red[0];
    cnt = 0;
    for (int i = tid; i < limit; i += 256) { q[i] = __float2half(v[cnt] * inv); cnt++; }
}

// ---------------- host launchers ----------------
static void launch_gemm16(bool half_out, const __half* A, const __half* B, void* C,
                          int M, int N, int K, int lda, int ldb, int ldc,
                          long long sA, long long sB, long long sC,
                          int batch, float alpha, int mode)
{
    dim3 grid(M / 128, (N + 127) / 128, batch);
    if (half_out) {
        cudaFuncSetAttribute(gemm16_kernel<true>, cudaFuncAttributeMaxDynamicSharedMemorySize, 4 * STG_BYTES);
        gemm16_kernel<true><<<grid, 256, 4 * STG_BYTES>>>(A, B, C, M, N, K, lda, ldb, ldc, sA, sB, sC, alpha, mode);
    } else {
        cudaFuncSetAttribute(gemm16_kernel<false>, cudaFuncAttributeMaxDynamicSharedMemorySize, 4 * STG_BYTES);
        gemm16_kernel<false><<<grid, 256, 4 * STG_BYTES>>>(A, B, C, M, N, K, lda, ldb, ldc, sA, sB, sC, alpha, mode);
    }
}

static void launch_transpose(const float* src, __half* dst, int R, int C, int batch)
{
    dim3 grid((C + 31) / 32, (R + 31) / 32, batch);
    transpose_f2h_kernel<<<grid, dim3(32, 8)>>>(src, dst, R, C);
}

extern "C" void kernel_launch(void* const* d_in, const int* in_sizes, int n_in,
                              void* d_out, int out_size)
{
    (void)in_sizes; (void)n_in; (void)out_size;
    const float* X        = (const float*)d_in[0];
    const int*   pos      = (const int*)d_in[2];
    const float* W_kv_a   = (const float*)d_in[3];
    const float* W_q_a    = (const float*)d_in[4];
    const float* q_ln     = (const float*)d_in[5];
    const float* kv_ln    = (const float*)d_in[6];
    const float* q_rope_w = (const float*)d_in[7];
    const float* fusedqk  = (const float*)d_in[8];
    const float* v_up     = (const float*)d_in[9];
    const float* W_o      = (const float*)d_in[10];
    float* out = (float*)d_out;

    float  *comp, *qa_pre, *qpe, *logits;
    __half *xh, *qah, *kfullh, *kvaT, *qfullh, *probsh, *ctxh, *attnh;
    __half *wkvT, *wqT, *qrwT, *fqkT, *vupT, *woT;
    cudaGetSymbolAddress((void**)&comp,   g_compressed);
    cudaGetSymbolAddress((void**)&qa_pre, g_qa_pre);
    cudaGetSymbolAddress((void**)&qpe,    g_qpe);
    cudaGetSymbolAddress((void**)&logits, g_logits);
    cudaGetSymbolAddress((void**)&xh,     g_xh);
    cudaGetSymbolAddress((void**)&qah,    g_qah);
    cudaGetSymbolAddress((void**)&kfullh, g_kfullh);
    cudaGetSymbolAddress((void**)&kvaT,   g_kvaT);
    cudaGetSymbolAddress((void**)&qfullh, g_qfullh);
    cudaGetSymbolAddress((void**)&probsh, g_probsh);
    cudaGetSymbolAddress((void**)&ctxh,   g_ctxh);
    cudaGetSymbolAddress((void**)&attnh,  g_attnh);
    cudaGetSymbolAddress((void**)&wkvT,   g_wkvT);
    cudaGetSymbolAddress((void**)&wqT,    g_wqT);
    cudaGetSymbolAddress((void**)&qrwT,   g_qrwT);
    cudaGetSymbolAddress((void**)&fqkT,   g_fqkT);
    cudaGetSymbolAddress((void**)&vupT,   g_vupT);
    cudaGetSymbolAddress((void**)&woT,    g_woT);

    const float scale = 1.0f / sqrtf(192.0f);

    // 0) prepass: convert X; transpose+convert all weights to [N][K] fp16
    {
        int n4 = (S_LEN * HID) / 4;
        convert_f2h_kernel<<<8192, 256>>>((const float4*)X, (__half2*)xh, n4);
    }
    launch_transpose(W_kv_a,   wkvT, HID,    CDIM,          1);
    launch_transpose(W_q_a,    wqT,  HID,    Q_LORA,        1);
    launch_transpose(q_rope_w, qrwT, Q_LORA, NH * ROPE_D,   1);
    launch_transpose(fusedqk,  fqkT, Q_LORA, KV_LORA,       NH);
    launch_transpose(v_up,     vupT, KV_LORA, V_D,          NH);
    launch_transpose(W_o,      woT,  NH * V_D, HID,         1);

    // 1) comp = X @ W_kv_a            [S,576] f32
    launch_gemm16(false, xh, wkvT, comp, S_LEN, CDIM, HID, HID, HID, CDIM, 0, 0, 0, 1, 1.0f, 0);
    // 2) qa_pre = X @ W_q_a           [S,1536] f32
    launch_gemm16(false, xh, wqT, qa_pre, S_LEN, Q_LORA, HID, HID, HID, Q_LORA, 0, 0, 0, 1, 1.0f, 0);
    // 3) kfullh = concat(rms(kva), rope(k_pe)) fp16
    kva_rms_rope_kernel<<<S_LEN, 128>>>(comp, kv_ln, pos, kfullh);
    // 3b) kvaT fp16 [512][2048]
    {
        dim3 grid(KV_LORA / 32, S_LEN / 32);
        transpose_kva_kernel<<<grid, dim3(32, 8)>>>(kfullh, kvaT);
    }
    // 4) qah = rms(qa_pre) fp16
    qa_rms_kernel<<<S_LEN, 256>>>(qa_pre, q_ln, qah);
    // 5) qpe = qa @ q_rope_w          [S,2048] f32
    launch_gemm16(false, qah, qrwT, qpe, S_LEN, NH * ROPE_D, Q_LORA,
                  Q_LORA, Q_LORA, NH * ROPE_D, 0, 0, 0, 1, 1.0f, 0);
    // 6) rope(q_pe) -> qfullh[:, 512:576]
    rope_q_kernel<<<dim3(S_LEN, NH), ROPE_D / 2>>>(qpe, pos, qfullh);
    // 7) dq = qa @ fusedqk[h] -> qfullh[:, :512] fp16 (batched)
    launch_gemm16(true, qah, fqkT, qfullh, S_LEN, KV_LORA, Q_LORA,
                  Q_LORA, Q_LORA, CDIM,
                  0, (long long)KV_LORA * Q_LORA, (long long)S_LEN * CDIM,
                  NH, 1.0f, 0);
    // 8) logits = scale * qfull @ kfull^T, causal (f32 out)
    launch_gemm16(false, qfullh, kfullh, logits, S_LEN, S_LEN, CDIM,
                  CDIM, CDIM, S_LEN,
                  (long long)S_LEN * CDIM, 0, (long long)S_LEN * S_LEN,
                  NH, scale, 1);
    // 9) softmax -> probsh = 512*p fp16
    softmax_kernel<<<NH * S_LEN, 256>>>(logits, probsh);
    // 10) ctx = (1/512) * probsh @ kva   (fp16 out, causal K cap)
    launch_gemm16(true, probsh, kvaT, ctxh, S_LEN, KV_LORA, S_LEN,
                  S_LEN, S_LEN, KV_LORA,
                  (long long)S_LEN * S_LEN, 0, (long long)S_LEN * KV_LORA,
                  NH, 1.0f / 512.0f, 2);
    // 11) attnh[:, h*128:(h+1)*128] = ctx[h] @ v_up[h] (fp16 out; sC=128 = column offset)
    launch_gemm16(true, ctxh, vupT, attnh, S_LEN, V_D, KV_LORA,
                  KV_LORA, KV_LORA, NH * V_D,
                  (long long)S_LEN * KV_LORA, (long long)V_D * KV_LORA, (long long)V_D,
                  NH, 1.0f, 0);
    // 12) out = attn @ W_o            [S,7168] f32
    launch_gemm16(false, attnh, woT, out, S_LEN, HID, NH * V_D,
                  NH * V_D, NH * V_D, HID, 0, 0, 0, 1, 1.0f, 0);
}

// round 8
// speedup vs baseline: 2.2348x; 1.0480x over previous
#include <cuda_runtime.h>
#include <cuda_fp16.h>
#include <math.h>
#include <stdint.h>

// ---------------- problem constants ----------------
#define S_LEN   2048
#define HID     7168
#define NH      32
#define Q_LORA  1536
#define KV_LORA 512
#define ROPE_D  64
#define CDIM    576
#define V_D     128
#define N12     (Q_LORA + CDIM)     // 2112 merged projection width
#define MIN_MASKED (-10000.0f)

// ---------------- scratch ----------------
__device__ float  g_pre12[(size_t)S_LEN * N12];          // [S][2112]: qa_pre | compressed
__device__ float  g_qpe[(size_t)S_LEN * (NH * ROPE_D)];
__device__ float  g_logits[(size_t)NH * S_LEN * S_LEN];
// fp16 operand buffers
__device__ __half g_xh   [(size_t)S_LEN * HID];
__device__ __half g_qah  [(size_t)S_LEN * Q_LORA];
__device__ __half g_kfullh[(size_t)S_LEN * CDIM];
__device__ __half g_kvaT [(size_t)KV_LORA * S_LEN];
__device__ __half g_qfullh[(size_t)NH * S_LEN * CDIM];
__device__ __half g_probsh[(size_t)NH * S_LEN * S_LEN];
__device__ __half g_ctxh [(size_t)NH * S_LEN * KV_LORA];
__device__ __half g_attnh[(size_t)S_LEN * (NH * V_D)];
// transposed fp16 weights ([N][K])
__device__ __half g_w12T[(size_t)N12 * HID];             // rows 0..1535: W_q^T, 1536..2111: W_kv^T
__device__ __half g_qrwT[(size_t)(NH * ROPE_D) * Q_LORA];
__device__ __half g_fqkT[(size_t)NH * KV_LORA * Q_LORA];
__device__ __half g_vupT[(size_t)NH * V_D * KV_LORA];
__device__ __half g_woT [(size_t)HID * (NH * V_D)];

// ---------------- helpers ----------------
__device__ __forceinline__ void mma16(float (&c)[4], const unsigned (&a)[4], const unsigned (&b)[2]) {
    asm volatile(
        "mma.sync.aligned.m16n8k16.row.col.f32.f16.f16.f32 "
        "{%0,%1,%2,%3}, {%4,%5,%6,%7}, {%8,%9}, {%0,%1,%2,%3};"
        : "+f"(c[0]), "+f"(c[1]), "+f"(c[2]), "+f"(c[3])
        : "r"(a[0]), "r"(a[1]), "r"(a[2]), "r"(a[3]), "r"(b[0]), "r"(b[1]));
}
__device__ __forceinline__ void cpasync16(uint32_t dst, const void* src, int srcsize) {
    asm volatile("cp.async.cg.shared.global [%0], [%1], 16, %2;"
                 :: "r"(dst), "l"(src), "r"(srcsize) : "memory");
}
__device__ __forceinline__ void cp_commit() { asm volatile("cp.async.commit_group;" ::: "memory"); }
template<int N> __device__ __forceinline__ void cp_wait() { asm volatile("cp.async.wait_group %0;" :: "n"(N) : "memory"); }

// ---------------- fp16 tensor-core GEMM, 4-stage cp.async pipeline ----------------
// C[M,N] = alpha * A[M,K] @ B^T, A fp16 [M][K], B fp16 [N][K].
// mode 0 plain; mode 1 causal epilogue + full-block skip; mode 2 kEnd=min(K,row0+128).
#define STG_BYTES 16384

template<bool HALF_OUT>
__global__ void __launch_bounds__(256, 2)
gemm16_kernel(const __half* __restrict__ A, const __half* __restrict__ B, void* Cv,
              int M, int N, int K, int lda, int ldb, int ldc,
              long long sA, long long sB, long long sC,
              float alpha, int mode)
{
    extern __shared__ char smem[];
    const long long bz = blockIdx.z;
    A += bz * sA;  B += bz * sB;

    const int row0 = blockIdx.x * 128;
    const int col0 = blockIdx.y * 128;
    if (mode == 1 && col0 >= row0 + 128) return;

    float*  Cf = (float*)Cv  + bz * sC;
    __half* Ch = (__half*)Cv + bz * sC;

    const int tid  = threadIdx.x;
    const int lane = tid & 31;
    const int wid  = tid >> 5;
    const int wm   = wid >> 2;
    const int wn   = wid & 3;
    const int g    = lane >> 2;
    const int tig  = lane & 3;

    uint32_t sbase;
    asm("{ .reg .u64 t; cvta.to.shared.u64 t, %1; cvt.u32.u64 %0, t; }" : "=r"(sbase) : "l"(smem));

    const int kEnd = (mode == 2) ? min(K, row0 + 128) : K;
    const int T = kEnd >> 5;

    auto issue = [&](int t) {
        int k0 = t << 5;
        uint32_t st = sbase + (uint32_t)((t & 3) * STG_BYTES);
        #pragma unroll
        for (int e = 0; e < 2; e++) {
            int id = tid + e * 256;
            int r = id >> 2, c = id & 3;
            uint32_t dst = st + (uint32_t)(r * 64 + ((c ^ ((r >> 1) & 3)) * 16));
            cpasync16(dst, A + (long long)(row0 + r) * lda + k0 + c * 8, 16);
        }
        #pragma unroll
        for (int e = 0; e < 2; e++) {
            int id = tid + e * 256;
            int n = id >> 2, c = id & 3;
            uint32_t dst = st + 8192u + (uint32_t)(n * 64 + ((c ^ ((n >> 1) & 3)) * 16));
            bool ok = (col0 + n) < N;
            const __half* src = ok ? (B + (long long)(col0 + n) * ldb + k0 + c * 8) : B;
            cpasync16(dst, src, ok ? 16 : 0);
        }
        cp_commit();
    };

    float acc[4][4][4] = {};

    issue(0);
    if (1 < T) issue(1);
    if (2 < T) issue(2);

    for (int t = 0; t < T; t++) {
        int rem = T - t - 1;
        if (rem >= 2)      cp_wait<2>();
        else if (rem == 1) cp_wait<1>();
        else               cp_wait<0>();
        __syncthreads();

        if (t + 3 < T) issue(t + 3);

        const char* As = smem + (t & 3) * STG_BYTES;
        const char* Bs = As + 8192;

        #pragma unroll
        for (int kk16 = 0; kk16 < 2; kk16++) {
            unsigned af[4][4], bf[4][2];
            #pragma unroll
            for (int mi = 0; mi < 4; mi++) {
                int mb = wm * 64 + mi * 16 + g;
                int c0 = (kk16 * 2) ^ ((mb >> 1) & 3);
                const char* rp  = As + mb * 64 + 4 * tig;
                const char* rp8 = As + (mb + 8) * 64 + 4 * tig;
                af[mi][0] = *(const unsigned*)(rp  + c0 * 16);
                af[mi][1] = *(const unsigned*)(rp8 + c0 * 16);
                af[mi][2] = *(const unsigned*)(rp  + (c0 ^ 1) * 16);
                af[mi][3] = *(const unsigned*)(rp8 + (c0 ^ 1) * 16);
            }
            #pragma unroll
            for (int nj = 0; nj < 4; nj++) {
                int nb = wn * 32 + nj * 8 + g;
                int c0 = (kk16 * 2) ^ ((nb >> 1) & 3);
                const char* rp = Bs + nb * 64 + 4 * tig;
                bf[nj][0] = *(const unsigned*)(rp + c0 * 16);
                bf[nj][1] = *(const unsigned*)(rp + (c0 ^ 1) * 16);
            }
            #pragma unroll
            for (int mi = 0; mi < 4; mi++)
                #pragma unroll
                for (int nj = 0; nj < 4; nj++)
                    mma16(acc[mi][nj], af[mi], bf[nj]);
        }
        __syncthreads();
    }

    #pragma unroll
    for (int mi = 0; mi < 4; mi++) {
        int r = row0 + wm * 64 + mi * 16 + g;
        #pragma unroll
        for (int nj = 0; nj < 4; nj++) {
            int c = col0 + wn * 32 + nj * 8 + tig * 2;
            float v0 = acc[mi][nj][0] * alpha;
            float v1 = acc[mi][nj][1] * alpha;
            float v2 = acc[mi][nj][2] * alpha;
            float v3 = acc[mi][nj][3] * alpha;
            if (mode == 1) {
                v0 = (c     > r    ) ? MIN_MASKED : v0;
                v1 = (c + 1 > r    ) ? MIN_MASKED : v1;
                v2 = (c     > r + 8) ? MIN_MASKED : v2;
                v3 = (c + 1 > r + 8) ? MIN_MASKED : v3;
            }
            if (c < N) {    // N always even, c even
                if (HALF_OUT) {
                    *(__half2*)(Ch + (long long)r * ldc + c) =
                        __halves2half2(__float2half(v0), __float2half(v1));
                    *(__half2*)(Ch + (long long)(r + 8) * ldc + c) =
                        __halves2half2(__float2half(v2), __float2half(v3));
                } else {
                    float* p0 = Cf + (long long)r * ldc + c;
                    float* p1 = Cf + (long long)(r + 8) * ldc + c;
                    p0[0] = v0; p0[1] = v1;
                    p1[0] = v2; p1[1] = v3;
                }
            }
        }
    }
}

// ---------------- prepass: fp32 -> fp16 convert ----------------
__global__ void convert_f2h_kernel(const float4* __restrict__ src, __half2* __restrict__ dst, int n4)
{
    int i = blockIdx.x * blockDim.x + threadIdx.x;
    int stride = gridDim.x * blockDim.x;
    for (; i < n4; i += stride) {
        float4 v = src[i];
        dst[2 * i]     = __floats2half2_rn(v.x, v.y);
        dst[2 * i + 1] = __floats2half2_rn(v.z, v.w);
    }
}

// ---------------- fast transpose: fp32 [R][C] -> fp16 [C][R], 64x64 tiles ----------------
// Both phases move full 128B lines per warp; smem pad 73 -> conflict-free phase-2 reads.
__global__ void transpose_f2h_kernel(const float* __restrict__ src, __half* __restrict__ dst,
                                     int R, int C)
{
    long long z = blockIdx.z;
    src += z * (long long)R * C;
    dst += z * (long long)R * C;
    __shared__ __half t[64][73];
    int r0 = blockIdx.y * 64, c0 = blockIdx.x * 64;
    int tid = threadIdx.x;                      // 256
    #pragma unroll
    for (int i = 0; i < 16; i++) {
        int idx = tid + i * 256;
        int ry = idx >> 6, cx = idx & 63;
        t[ry][cx] = __float2half(src[(long long)(r0 + ry) * C + c0 + cx]);
    }
    __syncthreads();
    #pragma unroll
    for (int i = 0; i < 8; i++) {
        int idx = tid + i * 256;
        int cloc = idx >> 5;                    // 0..63
        int rloc = (idx & 31) * 2;
        __half2 v = __halves2half2(t[rloc][cloc], t[rloc + 1][cloc]);
        *(__half2*)(dst + (long long)(c0 + cloc) * R + r0 + rloc) = v;
    }
}

// ---------------- fast transpose: fp16 [R][ld] (first C cols) -> fp16 [C][R] ----------------
__global__ void transpose_h2h_kernel(const __half* __restrict__ src, __half* __restrict__ dst,
                                     int R, int C, int ldsrc)
{
    __shared__ __half t[64][73];
    int r0 = blockIdx.y * 64, c0 = blockIdx.x * 64;
    int tid = threadIdx.x;
    #pragma unroll
    for (int i = 0; i < 16; i++) {
        int idx = tid + i * 256;
        int ry = idx >> 6, cx = idx & 63;
        t[ry][cx] = src[(long long)(r0 + ry) * ldsrc + c0 + cx];
    }
    __syncthreads();
    #pragma unroll
    for (int i = 0; i < 8; i++) {
        int idx = tid + i * 256;
        int cloc = idx >> 5;
        int rloc = (idx & 31) * 2;
        __half2 v = __halves2half2(t[rloc][cloc], t[rloc + 1][cloc]);
        *(__half2*)(dst + (long long)(c0 + cloc) * R + r0 + rloc) = v;
    }
}

// ---------------- rmsnorm(kva) + RoPE(k_pe) -> kfullh (fp16); comp at pre12[:,1536:] ----------------
__global__ void kva_rms_rope_kernel(const float* __restrict__ pre12,
                                    const float* __restrict__ kv_ln,
                                    const int*   __restrict__ pos_ids,
                                    __half* __restrict__ kfull)
{
    int s = blockIdx.x;
    const float* x = pre12 + (long long)s * N12 + Q_LORA;
    __half* out = kfull + (long long)s * CDIM;

    __shared__ float red[128];
    float ss = 0.0f;
    for (int i = threadIdx.x; i < KV_LORA; i += 128) { float v = x[i]; ss += v * v; }
    red[threadIdx.x] = ss; __syncthreads();
    for (int st = 64; st > 0; st >>= 1) {
        if (threadIdx.x < st) red[threadIdx.x] += red[threadIdx.x + st];
        __syncthreads();
    }
    float scale = rsqrtf(red[0] / (float)KV_LORA + 1e-6f);

    for (int i = threadIdx.x; i < KV_LORA; i += 128)
        out[i] = __float2half(x[i] * scale * kv_ln[i]);

    if (threadIdx.x < ROPE_D / 2) {
        int j = threadIdx.x;
        float pos  = (float)pos_ids[s];
        float invf = powf(10000.0f, -(float)(2 * j) / (float)ROPE_D);
        float ang  = pos * invf;
        float c = cosf(ang), sn = sinf(ang);
        float x0 = x[KV_LORA + 2 * j];
        float x1 = x[KV_LORA + 2 * j + 1];
        out[KV_LORA + j]              = __float2half(x0 * c - x1 * sn);
        out[KV_LORA + ROPE_D / 2 + j] = __float2half(x1 * c + x0 * sn);
    }
}

// ---------------- rmsnorm(q_a) -> fp16; input pre12[:,:1536] ----------------
__global__ void qa_rms_kernel(const float* __restrict__ pre12,
                              const float* __restrict__ w,
                              __half* __restrict__ outp)
{
    int s = blockIdx.x;
    const float* x = pre12 + (long long)s * N12;
    __half* o = outp + (long long)s * Q_LORA;

    __shared__ float red[256];
    float ss = 0.0f;
    for (int i = threadIdx.x; i < Q_LORA; i += 256) { float v = x[i]; ss += v * v; }
    red[threadIdx.x] = ss; __syncthreads();
    for (int st = 128; st > 0; st >>= 1) {
        if (threadIdx.x < st) red[threadIdx.x] += red[threadIdx.x + st];
        __syncthreads();
    }
    float scale = rsqrtf(red[0] / (float)Q_LORA + 1e-6f);
    for (int i = threadIdx.x; i < Q_LORA; i += 256)
        o[i] = __float2half(x[i] * scale * w[i]);
}

// ---------------- RoPE on q_pe -> qfullh rope columns (fp16) ----------------
__global__ void rope_q_kernel(const float* __restrict__ qpe,
                              const int*   __restrict__ pos_ids,
                              __half* __restrict__ qfull)
{
    int s = blockIdx.x;
    int h = blockIdx.y;
    int j = threadIdx.x;            // 0..31
    float pos  = (float)pos_ids[s];
    float invf = powf(10000.0f, -(float)(2 * j) / (float)ROPE_D);
    float ang  = pos * invf;
    float c = cosf(ang), sn = sinf(ang);
    const float* x = qpe + (long long)s * (NH * ROPE_D) + h * ROPE_D;
    float x0 = x[2 * j], x1 = x[2 * j + 1];
    __half* out = qfull + ((long long)h * S_LEN + s) * CDIM + KV_LORA;
    out[j]              = __float2half(x0 * c - x1 * sn);
    out[j + ROPE_D / 2] = __float2half(x1 * c + x0 * sn);
}

// ---------------- softmax over causal prefix; writes 512*p as fp16 ----------------
__global__ void softmax_kernel(const float* __restrict__ logits, __half* __restrict__ probs)
{
    long long row = blockIdx.x;
    int s = (int)(row & (S_LEN - 1));
    int limit = ((s >> 7) + 1) << 7;
    const float* p = logits + row * S_LEN;
    __half* q = probs + row * S_LEN;
    int tid = threadIdx.x;

    float v[8];
    int cnt = 0;
    float m = -1e30f;
    for (int i = tid; i < limit; i += 256) { v[cnt] = p[i]; m = fmaxf(m, v[cnt]); cnt++; }

    __shared__ float red[256];
    red[tid] = m; __syncthreads();
    for (int st = 128; st > 0; st >>= 1) {
        if (tid < st) red[tid] = fmaxf(red[tid], red[tid + st]);
        __syncthreads();
    }
    m = red[0]; __syncthreads();

    float sum = 0.0f;
    for (int j = 0; j < cnt; j++) { v[j] = __expf(v[j] - m); sum += v[j]; }
    red[tid] = sum; __syncthreads();
    for (int st = 128; st > 0; st >>= 1) {
        if (tid < st) red[tid] += red[tid + st];
        __syncthreads();
    }
    float inv = 512.0f / red[0];
    cnt = 0;
    for (int i = tid; i < limit; i += 256) { q[i] = __float2half(v[cnt] * inv); cnt++; }
}

// ---------------- host launchers ----------------
static void launch_gemm16(bool half_out, const __half* A, const __half* B, void* C,
                          int M, int N, int K, int lda, int ldb, int ldc,
                          long long sA, long long sB, long long sC,
                          int batch, float alpha, int mode)
{
    dim3 grid(M / 128, (N + 127) / 128, batch);
    if (half_out) {
        cudaFuncSetAttribute(gemm16_kernel<true>, cudaFuncAttributeMaxDynamicSharedMemorySize, 4 * STG_BYTES);
        gemm16_kernel<true><<<grid, 256, 4 * STG_BYTES>>>(A, B, C, M, N, K, lda, ldb, ldc, sA, sB, sC, alpha, mode);
    } else {
        cudaFuncSetAttribute(gemm16_kernel<false>, cudaFuncAttributeMaxDynamicSharedMemorySize, 4 * STG_BYTES);
        gemm16_kernel<false><<<grid, 256, 4 * STG_BYTES>>>(A, B, C, M, N, K, lda, ldb, ldc, sA, sB, sC, alpha, mode);
    }
}

static void launch_transpose(const float* src, __half* dst, int R, int C, int batch)
{
    dim3 grid(C / 64, R / 64, batch);
    transpose_f2h_kernel<<<grid, 256>>>(src, dst, R, C);
}

extern "C" void kernel_launch(void* const* d_in, const int* in_sizes, int n_in,
                              void* d_out, int out_size)
{
    (void)in_sizes; (void)n_in; (void)out_size;
    const float* X        = (const float*)d_in[0];
    const int*   pos      = (const int*)d_in[2];
    const float* W_kv_a   = (const float*)d_in[3];
    const float* W_q_a    = (const float*)d_in[4];
    const float* q_ln     = (const float*)d_in[5];
    const float* kv_ln    = (const float*)d_in[6];
    const float* q_rope_w = (const float*)d_in[7];
    const float* fusedqk  = (const float*)d_in[8];
    const float* v_up     = (const float*)d_in[9];
    const float* W_o      = (const float*)d_in[10];
    float* out = (float*)d_out;

    float  *pre12, *qpe, *logits;
    __half *xh, *qah, *kfullh, *kvaT, *qfullh, *probsh, *ctxh, *attnh;
    __half *w12T, *qrwT, *fqkT, *vupT, *woT;
    cudaGetSymbolAddress((void**)&pre12,  g_pre12);
    cudaGetSymbolAddress((void**)&qpe,    g_qpe);
    cudaGetSymbolAddress((void**)&logits, g_logits);
    cudaGetSymbolAddress((void**)&xh,     g_xh);
    cudaGetSymbolAddress((void**)&qah,    g_qah);
    cudaGetSymbolAddress((void**)&kfullh, g_kfullh);
    cudaGetSymbolAddress((void**)&kvaT,   g_kvaT);
    cudaGetSymbolAddress((void**)&qfullh, g_qfullh);
    cudaGetSymbolAddress((void**)&probsh, g_probsh);
    cudaGetSymbolAddress((void**)&ctxh,   g_ctxh);
    cudaGetSymbolAddress((void**)&attnh,  g_attnh);
    cudaGetSymbolAddress((void**)&w12T,   g_w12T);
    cudaGetSymbolAddress((void**)&qrwT,   g_qrwT);
    cudaGetSymbolAddress((void**)&fqkT,   g_fqkT);
    cudaGetSymbolAddress((void**)&vupT,   g_vupT);
    cudaGetSymbolAddress((void**)&woT,    g_woT);

    const float scale = 1.0f / sqrtf(192.0f);

    // 0) prepass: convert X; transpose+convert weights into [N][K] fp16
    {
        int n4 = (S_LEN * HID) / 4;
        convert_f2h_kernel<<<4096, 256>>>((const float4*)X, (__half2*)xh, n4);
    }
    launch_transpose(W_q_a,    w12T,                          HID,      Q_LORA,      1);
    launch_transpose(W_kv_a,   w12T + (size_t)Q_LORA * HID,   HID,      CDIM,        1);
    launch_transpose(q_rope_w, qrwT,                          Q_LORA,   NH * ROPE_D, 1);
    launch_transpose(fusedqk,  fqkT,                          Q_LORA,   KV_LORA,     NH);
    launch_transpose(v_up,     vupT,                          KV_LORA,  V_D,         NH);
    launch_transpose(W_o,      woT,                           NH * V_D, HID,         1);

    // 1+2 merged) pre12 = X @ [W_q | W_kv]   [S,2112] f32
    launch_gemm16(false, xh, w12T, pre12, S_LEN, N12, HID, HID, HID, N12, 0, 0, 0, 1, 1.0f, 0);
    // 3) kfullh = concat(rms(kva), rope(k_pe)) fp16
    kva_rms_rope_kernel<<<S_LEN, 128>>>(pre12, kv_ln, pos, kfullh);
    // 3b) kvaT fp16 [512][2048]
    {
        dim3 grid(KV_LORA / 64, S_LEN / 64);
        transpose_h2h_kernel<<<grid, 256>>>(kfullh, kvaT, S_LEN, KV_LORA, CDIM);
    }
    // 4) qah = rms(qa_pre) fp16
    qa_rms_kernel<<<S_LEN, 256>>>(pre12, q_ln, qah);
    // 5) qpe = qa @ q_rope_w          [S,2048] f32
    launch_gemm16(false, qah, qrwT, qpe, S_LEN, NH * ROPE_D, Q_LORA,
                  Q_LORA, Q_LORA, NH * ROPE_D, 0, 0, 0, 1, 1.0f, 0);
    // 6) rope(q_pe) -> qfullh[:, 512:576]
    rope_q_kernel<<<dim3(S_LEN, NH), ROPE_D / 2>>>(qpe, pos, qfullh);
    // 7) dq = qa @ fusedqk[h] -> qfullh[:, :512] fp16 (batched)
    launch_gemm16(true, qah, fqkT, qfullh, S_LEN, KV_LORA, Q_LORA,
                  Q_LORA, Q_LORA, CDIM,
                  0, (long long)KV_LORA * Q_LORA, (long long)S_LEN * CDIM,
                  NH, 1.0f, 0);
    // 8) logits = scale * qfull @ kfull^T, causal (f32 out)
    launch_gemm16(false, qfullh, kfullh, logits, S_LEN, S_LEN, CDIM,
                  CDIM, CDIM, S_LEN,
                  (long long)S_LEN * CDIM, 0, (long long)S_LEN * S_LEN,
                  NH, scale, 1);
    // 9) softmax -> probsh = 512*p fp16
    softmax_kernel<<<NH * S_LEN, 256>>>(logits, probsh);
    // 10) ctx = (1/512) * probsh @ kva   (fp16 out, causal K cap)
    launch_gemm16(true, probsh, kvaT, ctxh, S_LEN, KV_LORA, S_LEN,
                  S_LEN, S_LEN, KV_LORA,
                  (long long)S_LEN * S_LEN, 0, (long long)S_LEN * KV_LORA,
                  NH, 1.0f / 512.0f, 2);
    // 11) attnh[:, h*128:(h+1)*128] = ctx[h] @ v_up[h] (fp16 out)
    launch_gemm16(true, ctxh, vupT, attnh, S_LEN, V_D, KV_LORA,
                  KV_LORA, KV_LORA, NH * V_D,
                  (long long)S_LEN * KV_LORA, (long long)V_D * KV_LORA, (long long)V_D,
                  NH, 1.0f, 0);
    // 12) out = attn @ W_o            [S,7168] f32
    launch_gemm16(false, attnh, woT, out, S_LEN, HID, NH * V_D,
                  NH * V_D, NH * V_D, HID, 0, 0, 0, 1, 1.0f, 0);
}

// round 9
// speedup vs baseline: 2.6620x; 1.1911x over previous
#include <cuda_runtime.h>
#include <cuda_fp16.h>
#include <math.h>
#include <stdint.h>

// ---------------- problem constants ----------------
#define S_LEN   2048
#define HID     7168
#define NH      32
#define Q_LORA  1536
#define KV_LORA 512
#define ROPE_D  64
#define CDIM    576
#define V_D     128
#define N12     (Q_LORA + CDIM)     // 2112 merged projection width
#define MIN_MASKED (-10000.0f)

// ---------------- scratch ----------------
__device__ float  g_pre12[(size_t)S_LEN * N12];          // [S][2112]: qa_pre | compressed
__device__ float  g_qpe[(size_t)S_LEN * (NH * ROPE_D)];
__device__ float  g_logits[(size_t)NH * S_LEN * S_LEN];
// fp16 operand buffers
__device__ __half g_xh   [(size_t)S_LEN * HID];
__device__ __half g_qah  [(size_t)S_LEN * Q_LORA];
__device__ __half g_kfullh[(size_t)S_LEN * CDIM];
__device__ __half g_qfullh[(size_t)NH * S_LEN * CDIM];
__device__ __half g_probsh[(size_t)NH * S_LEN * S_LEN];
__device__ __half g_ctxh [(size_t)NH * S_LEN * KV_LORA];
__device__ __half g_attnh[(size_t)S_LEN * (NH * V_D)];
// fp16 weights in NATURAL [K][N] layout
__device__ __half g_w12h[(size_t)HID * N12];             // cols 0..1535 W_q, 1536..2111 W_kv
__device__ __half g_qrwh[(size_t)Q_LORA * (NH * ROPE_D)];
__device__ __half g_fqkh[(size_t)NH * Q_LORA * KV_LORA];
__device__ __half g_vuph[(size_t)NH * KV_LORA * V_D];
__device__ __half g_woh [(size_t)(NH * V_D) * HID];

// ---------------- helpers ----------------
__device__ __forceinline__ void mma16(float (&c)[4], const unsigned (&a)[4], const unsigned (&b)[2]) {
    asm volatile(
        "mma.sync.aligned.m16n8k16.row.col.f32.f16.f16.f32 "
        "{%0,%1,%2,%3}, {%4,%5,%6,%7}, {%8,%9}, {%0,%1,%2,%3};"
        : "+f"(c[0]), "+f"(c[1]), "+f"(c[2]), "+f"(c[3])
        : "r"(a[0]), "r"(a[1]), "r"(a[2]), "r"(a[3]), "r"(b[0]), "r"(b[1]));
}
__device__ __forceinline__ void ldsm4(unsigned &r0, unsigned &r1, unsigned &r2, unsigned &r3, uint32_t a) {
    asm volatile("ldmatrix.sync.aligned.m8n8.x4.shared.b16 {%0,%1,%2,%3}, [%4];"
                 : "=r"(r0), "=r"(r1), "=r"(r2), "=r"(r3) : "r"(a));
}
__device__ __forceinline__ void ldsm4t(unsigned &r0, unsigned &r1, unsigned &r2, unsigned &r3, uint32_t a) {
    asm volatile("ldmatrix.sync.aligned.m8n8.x4.trans.shared.b16 {%0,%1,%2,%3}, [%4];"
                 : "=r"(r0), "=r"(r1), "=r"(r2), "=r"(r3) : "r"(a));
}
__device__ __forceinline__ void cpasync16(uint32_t dst, const void* src, int srcsize) {
    asm volatile("cp.async.cg.shared.global [%0], [%1], 16, %2;"
                 :: "r"(dst), "l"(src), "r"(srcsize) : "memory");
}
__device__ __forceinline__ void cp_commit() { asm volatile("cp.async.commit_group;" ::: "memory"); }
template<int N> __device__ __forceinline__ void cp_wait() { asm volatile("cp.async.wait_group %0;" :: "n"(N) : "memory"); }

// ---------------- fp16 tensor-core GEMM, 4-stage cp.async pipeline ----------------
// C[M,N] = alpha * A[M,K] @ B, A fp16 [M][K].
//   BKN=false: B fp16 [N][K] (ldb = row stride in K)  -> ldmatrix
//   BKN=true : B fp16 [K][N] (ldb = row stride in N)  -> ldmatrix.trans
// mode 0 plain; mode 1 causal epilogue + full-block skip; mode 2 kEnd=min(K,row0+128).
#define STG_BYTES 16384

template<bool HALF_OUT, bool BKN>
__global__ void __launch_bounds__(256, 2)
gemm16_kernel(const __half* __restrict__ A, const __half* __restrict__ B, void* Cv,
              int M, int N, int K, int lda, int ldb, int ldc,
              long long sA, long long sB, long long sC,
              float alpha, int mode)
{
    extern __shared__ char smem[];
    const long long bz = blockIdx.z;
    A += bz * sA;  B += bz * sB;

    const int row0 = blockIdx.x * 128;
    const int col0 = blockIdx.y * 128;
    if (mode == 1 && col0 >= row0 + 128) return;

    float*  Cf = (float*)Cv  + bz * sC;
    __half* Ch = (__half*)Cv + bz * sC;

    const int tid  = threadIdx.x;
    const int lane = tid & 31;
    const int wid  = tid >> 5;
    const int wm   = wid >> 2;
    const int wn   = wid & 3;
    const int g    = lane >> 2;
    const int tig  = lane & 3;

    uint32_t sbase;
    asm("{ .reg .u64 t; cvta.to.shared.u64 t, %1; cvt.u32.u64 %0, t; }" : "=r"(sbase) : "l"(smem));

    const int kEnd = (mode == 2) ? min(K, row0 + 128) : K;
    const int T = kEnd >> 5;

    auto issue = [&](int t) {
        int k0 = t << 5;
        uint32_t st = sbase + (uint32_t)((t & 3) * STG_BYTES);
        #pragma unroll
        for (int e = 0; e < 2; e++) {           // A tile: 128 rows x 64B
            int id = tid + e * 256;
            int r = id >> 2, c = id & 3;
            uint32_t dst = st + (uint32_t)(r * 64 + ((c ^ ((r >> 1) & 3)) * 16));
            cpasync16(dst, A + (long long)(row0 + r) * lda + k0 + c * 8, 16);
        }
        if (!BKN) {
            #pragma unroll
            for (int e = 0; e < 2; e++) {       // B [N][K]: 128 rows x 64B
                int id = tid + e * 256;
                int n = id >> 2, c = id & 3;
                uint32_t dst = st + 8192u + (uint32_t)(n * 64 + ((c ^ ((n >> 1) & 3)) * 16));
                bool ok = (col0 + n) < N;
                const __half* src = ok ? (B + (long long)(col0 + n) * ldb + k0 + c * 8) : B;
                cpasync16(dst, src, ok ? 16 : 0);
            }
        } else {
            #pragma unroll
            for (int e = 0; e < 2; e++) {       // B [K][N]: 32 rows x 256B
                int id = tid + e * 256;
                int k = id >> 4, c = id & 15;
                uint32_t dst = st + 8192u + (uint32_t)(k * 256 + ((c ^ (k & 7)) * 16));
                bool ok = (col0 + c * 8) < N;
                const __half* src = ok ? (B + (long long)(k0 + k) * ldb + col0 + c * 8) : B;
                cpasync16(dst, src, ok ? 16 : 0);
            }
        }
        cp_commit();
    };

    float acc[4][4][4] = {};

    issue(0);
    if (1 < T) issue(1);
    if (2 < T) issue(2);

    // lane-invariant fragment address pieces
    const int rbA = wm * 64 + ((lane >> 3) & 1) * 8 + (lane & 7);    // A row base
    const int ksel = lane >> 4;                                      // 0/1: k-chunk select (A)

    for (int t = 0; t < T; t++) {
        int rem = T - t - 1;
        if (rem >= 2)      cp_wait<2>();
        else if (rem == 1) cp_wait<1>();
        else               cp_wait<0>();
        __syncthreads();

        if (t + 3 < T) issue(t + 3);

        uint32_t stA = sbase + (uint32_t)((t & 3) * STG_BYTES);
        uint32_t stB = stA + 8192u;

        #pragma unroll
        for (int kk16 = 0; kk16 < 2; kk16++) {
            unsigned af[4][4], bf[4][2];
            // A fragments: ldmatrix x4 per 16x16 tile
            int cA = kk16 * 2 + ksel;
            #pragma unroll
            for (int mi = 0; mi < 4; mi++) {
                int r = rbA + mi * 16;
                uint32_t ad = stA + (uint32_t)(r * 64 + ((cA ^ ((r >> 1) & 3)) << 4));
                ldsm4(af[mi][0], af[mi][1], af[mi][2], af[mi][3], ad);
            }
            // B fragments: ldmatrix x4 per nj pair
            if (!BKN) {
                int kc = (lane >> 3) & 1;
                int cB = kk16 * 2 + kc;
                #pragma unroll
                for (int njp = 0; njp < 2; njp++) {
                    int n = wn * 32 + njp * 16 + (lane >> 4) * 8 + (lane & 7);
                    uint32_t ad = stB + (uint32_t)(n * 64 + ((cB ^ ((n >> 1) & 3)) << 4));
                    ldsm4(bf[2 * njp][0], bf[2 * njp][1], bf[2 * njp + 1][0], bf[2 * njp + 1][1], ad);
                }
            } else {
                int kr = kk16 * 16 + ((lane >> 3) & 1) * 8 + (lane & 7);
                #pragma unroll
                for (int njp = 0; njp < 2; njp++) {
                    int nch = wn * 4 + njp * 2 + (lane >> 4);
                    uint32_t ad = stB + (uint32_t)(kr * 256 + ((nch ^ (kr & 7)) << 4));
                    ldsm4t(bf[2 * njp][0], bf[2 * njp][1], bf[2 * njp + 1][0], bf[2 * njp + 1][1], ad);
                }
            }
            #pragma unroll
            for (int mi = 0; mi < 4; mi++)
                #pragma unroll
                for (int nj = 0; nj < 4; nj++)
                    mma16(acc[mi][nj], af[mi], bf[nj]);
        }
        __syncthreads();
    }

    #pragma unroll
    for (int mi = 0; mi < 4; mi++) {
        int r = row0 + wm * 64 + mi * 16 + g;
        #pragma unroll
        for (int nj = 0; nj < 4; nj++) {
            int c = col0 + wn * 32 + nj * 8 + tig * 2;
            float v0 = acc[mi][nj][0] * alpha;
            float v1 = acc[mi][nj][1] * alpha;
            float v2 = acc[mi][nj][2] * alpha;
            float v3 = acc[mi][nj][3] * alpha;
            if (mode == 1) {
                v0 = (c     > r    ) ? MIN_MASKED : v0;
                v1 = (c + 1 > r    ) ? MIN_MASKED : v1;
                v2 = (c     > r + 8) ? MIN_MASKED : v2;
                v3 = (c + 1 > r + 8) ? MIN_MASKED : v3;
            }
            if (c < N) {    // N always even, c even
                if (HALF_OUT) {
                    *(__half2*)(Ch + (long long)r * ldc + c) =
                        __halves2half2(__float2half(v0), __float2half(v1));
                    *(__half2*)(Ch + (long long)(r + 8) * ldc + c) =
                        __halves2half2(__float2half(v2), __float2half(v3));
                } else {
                    float* p0 = Cf + (long long)r * ldc + c;
                    float* p1 = Cf + (long long)(r + 8) * ldc + c;
                    p0[0] = v0; p0[1] = v1;
                    p1[0] = v2; p1[1] = v3;
                }
            }
        }
    }
}

// ---------------- prepass: fp32 -> fp16 convert (contiguous) ----------------
__global__ void convert_f2h_kernel(const float4* __restrict__ src, __half2* __restrict__ dst, int n4)
{
    int i = blockIdx.x * blockDim.x + threadIdx.x;
    int stride = gridDim.x * blockDim.x;
    for (; i < n4; i += stride) {
        float4 v = src[i];
        dst[2 * i]     = __floats2half2_rn(v.x, v.y);
        dst[2 * i + 1] = __floats2half2_rn(v.z, v.w);
    }
}

// ---------------- prepass: fp32 [rows][C] -> fp16 packed into dst[r][off..off+C) ----------------
__global__ void pack_f2h_kernel(const float* __restrict__ src, __half* __restrict__ dst,
                                int C, int ldd, int off)
{
    int c2 = blockIdx.x * blockDim.x + threadIdx.x;     // column pair
    int r  = blockIdx.y;
    if (c2 < C / 2) {
        float2 v = *(const float2*)(src + (long long)r * C + 2 * c2);
        *(__half2*)(dst + (long long)r * ldd + off + 2 * c2) = __floats2half2_rn(v.x, v.y);
    }
}

// ---------------- rmsnorm(kva) + RoPE(k_pe) -> kfullh (fp16); comp at pre12[:,1536:] ----------------
__global__ void kva_rms_rope_kernel(const float* __restrict__ pre12,
                                    const float* __restrict__ kv_ln,
                                    const int*   __restrict__ pos_ids,
                                    __half* __restrict__ kfull)
{
    int s = blockIdx.x;
    const float* x = pre12 + (long long)s * N12 + Q_LORA;
    __half* out = kfull + (long long)s * CDIM;

    __shared__ float red[128];
    float ss = 0.0f;
    for (int i = threadIdx.x; i < KV_LORA; i += 128) { float v = x[i]; ss += v * v; }
    red[threadIdx.x] = ss; __syncthreads();
    for (int st = 64; st > 0; st >>= 1) {
        if (threadIdx.x < st) red[threadIdx.x] += red[threadIdx.x + st];
        __syncthreads();
    }
    float scale = rsqrtf(red[0] / (float)KV_LORA + 1e-6f);

    for (int i = threadIdx.x; i < KV_LORA; i += 128)
        out[i] = __float2half(x[i] * scale * kv_ln[i]);

    if (threadIdx.x < ROPE_D / 2) {
        int j = threadIdx.x;
        float pos  = (float)pos_ids[s];
        float invf = powf(10000.0f, -(float)(2 * j) / (float)ROPE_D);
        float ang  = pos * invf;
        float c = cosf(ang), sn = sinf(ang);
        float x0 = x[KV_LORA + 2 * j];
        float x1 = x[KV_LORA + 2 * j + 1];
        out[KV_LORA + j]              = __float2half(x0 * c - x1 * sn);
        out[KV_LORA + ROPE_D / 2 + j] = __float2half(x1 * c + x0 * sn);
    }
}

// ---------------- rmsnorm(q_a) -> fp16; input pre12[:,:1536] ----------------
__global__ void qa_rms_kernel(const float* __restrict__ pre12,
                              const float* __restrict__ w,
                              __half* __restrict__ outp)
{
    int s = blockIdx.x;
    const float* x = pre12 + (long long)s * N12;
    __half* o = outp + (long long)s * Q_LORA;

    __shared__ float red[256];
    float ss = 0.0f;
    for (int i = threadIdx.x; i < Q_LORA; i += 256) { float v = x[i]; ss += v * v; }
    red[threadIdx.x] = ss; __syncthreads();
    for (int st = 128; st > 0; st >>= 1) {
        if (threadIdx.x < st) red[threadIdx.x] += red[threadIdx.x + st];
        __syncthreads();
    }
    float scale = rsqrtf(red[0] / (float)Q_LORA + 1e-6f);
    for (int i = threadIdx.x; i < Q_LORA; i += 256)
        o[i] = __float2half(x[i] * scale * w[i]);
}

// ---------------- RoPE on q_pe -> qfullh rope columns (fp16) ----------------
__global__ void rope_q_kernel(const float* __restrict__ qpe,
                              const int*   __restrict__ pos_ids,
                              __half* __restrict__ qfull)
{
    int s = blockIdx.x;
    int h = blockIdx.y;
    int j = threadIdx.x;            // 0..31
    float pos  = (float)pos_ids[s];
    float invf = powf(10000.0f, -(float)(2 * j) / (float)ROPE_D);
    float ang  = pos * invf;
    float c = cosf(ang), sn = sinf(ang);
    const float* x = qpe + (long long)s * (NH * ROPE_D) + h * ROPE_D;
    float x0 = x[2 * j], x1 = x[2 * j + 1];
    __half* out = qfull + ((long long)h * S_LEN + s) * CDIM + KV_LORA;
    out[j]              = __float2half(x0 * c - x1 * sn);
    out[j + ROPE_D / 2] = __float2half(x1 * c + x0 * sn);
}

// ---------------- softmax over causal prefix; writes 512*p as fp16 ----------------
__global__ void softmax_kernel(const float* __restrict__ logits, __half* __restrict__ probs)
{
    long long row = blockIdx.x;
    int s = (int)(row & (S_LEN - 1));
    int limit = ((s >> 7) + 1) << 7;
    const float* p = logits + row * S_LEN;
    __half* q = probs + row * S_LEN;
    int tid = threadIdx.x;

    float v[8];
    int cnt = 0;
    float m = -1e30f;
    for (int i = tid; i < limit; i += 256) { v[cnt] = p[i]; m = fmaxf(m, v[cnt]); cnt++; }

    __shared__ float red[256];
    red[tid] = m; __syncthreads();
    for (int st = 128; st > 0; st >>= 1) {
        if (tid < st) red[tid] = fmaxf(red[tid], red[tid + st]);
        __syncthreads();
    }
    m = red[0]; __syncthreads();

    float sum = 0.0f;
    for (int j = 0; j < cnt; j++) { v[j] = __expf(v[j] - m); sum += v[j]; }
    red[tid] = sum; __syncthreads();
    for (int st = 128; st > 0; st >>= 1) {
        if (tid < st) red[tid] += red[tid + st];
        __syncthreads();
    }
    float inv = 512.0f / red[0];
    cnt = 0;
    for (int i = tid; i < limit; i += 256) { q[i] = __float2half(v[cnt] * inv); cnt++; }
}

// ---------------- host launchers ----------------
template<bool HALF_OUT, bool BKN>
static void launch_gemm16_t(const __half* A, const __half* B, void* C,
                            int M, int N, int K, int lda, int ldb, int ldc,
                            long long sA, long long sB, long long sC,
                            int batch, float alpha, int mode)
{
    dim3 grid(M / 128, (N + 127) / 128, batch);
    cudaFuncSetAttribute(gemm16_kernel<HALF_OUT, BKN>, cudaFuncAttributeMaxDynamicSharedMemorySize, 4 * STG_BYTES);
    gemm16_kernel<HALF_OUT, BKN><<<grid, 256, 4 * STG_BYTES>>>(A, B, C, M, N, K, lda, ldb, ldc, sA, sB, sC, alpha, mode);
}

static void launch_convert(const float* src, __half* dst, size_t n)
{
    int n4 = (int)(n / 4);
    int blocks = (n4 + 255) / 256;
    if (blocks > 4096) blocks = 4096;
    convert_f2h_kernel<<<blocks, 256>>>((const float4*)src, (__half2*)dst, n4);
}

extern "C" void kernel_launch(void* const* d_in, const int* in_sizes, int n_in,
                              void* d_out, int out_size)
{
    (void)in_sizes; (void)n_in; (void)out_size;
    const float* X        = (const float*)d_in[0];
    const int*   pos      = (const int*)d_in[2];
    const float* W_kv_a   = (const float*)d_in[3];
    const float* W_q_a    = (const float*)d_in[4];
    const float* q_ln     = (const float*)d_in[5];
    const float* kv_ln    = (const float*)d_in[6];
    const float* q_rope_w = (const float*)d_in[7];
    const float* fusedqk  = (const float*)d_in[8];
    const float* v_up     = (const float*)d_in[9];
    const float* W_o      = (const float*)d_in[10];
    float* out = (float*)d_out;

    float  *pre12, *qpe, *logits;
    __half *xh, *qah, *kfullh, *qfullh, *probsh, *ctxh, *attnh;
    __half *w12h, *qrwh, *fqkh, *vuph, *woh;
    cudaGetSymbolAddress((void**)&pre12,  g_pre12);
    cudaGetSymbolAddress((void**)&qpe,    g_qpe);
    cudaGetSymbolAddress((void**)&logits, g_logits);
    cudaGetSymbolAddress((void**)&xh,     g_xh);
    cudaGetSymbolAddress((void**)&qah,    g_qah);
    cudaGetSymbolAddress((void**)&kfullh, g_kfullh);
    cudaGetSymbolAddress((void**)&qfullh, g_qfullh);
    cudaGetSymbolAddress((void**)&probsh, g_probsh);
    cudaGetSymbolAddress((void**)&ctxh,   g_ctxh);
    cudaGetSymbolAddress((void**)&attnh,  g_attnh);
    cudaGetSymbolAddress((void**)&w12h,   g_w12h);
    cudaGetSymbolAddress((void**)&qrwh,   g_qrwh);
    cudaGetSymbolAddress((void**)&fqkh,   g_fqkh);
    cudaGetSymbolAddress((void**)&vuph,   g_vuph);
    cudaGetSymbolAddress((void**)&woh,    g_woh);

    const float scale = 1.0f / sqrtf(192.0f);

    // 0) prepass: fp32 -> fp16 (natural layouts; W_q/W_kv packed side-by-side)
    launch_convert(X,        xh,   (size_t)S_LEN * HID);
    pack_f2h_kernel<<<dim3((Q_LORA / 2 + 255) / 256, HID), 256>>>(W_q_a,  w12h, Q_LORA, N12, 0);
    pack_f2h_kernel<<<dim3((CDIM   / 2 + 255) / 256, HID), 256>>>(W_kv_a, w12h, CDIM,   N12, Q_LORA);
    launch_convert(q_rope_w, qrwh, (size_t)Q_LORA * (NH * ROPE_D));
    launch_convert(fusedqk,  fqkh, (size_t)NH * Q_LORA * KV_LORA);
    launch_convert(v_up,     vuph, (size_t)NH * KV_LORA * V_D);
    launch_convert(W_o,      woh,  (size_t)(NH * V_D) * HID);

    // 1+2 merged) pre12 = X @ [W_q | W_kv]   [S,2112] f32   (B [K][N])
    launch_gemm16_t<false, true>(xh, w12h, pre12, S_LEN, N12, HID,
                                 HID, N12, N12, 0, 0, 0, 1, 1.0f, 0);
    // 3) kfullh = concat(rms(kva), rope(k_pe)) fp16
    kva_rms_rope_kernel<<<S_LEN, 128>>>(pre12, kv_ln, pos, kfullh);
    // 4) qah = rms(qa_pre) fp16
    qa_rms_kernel<<<S_LEN, 256>>>(pre12, q_ln, qah);
    // 5) qpe = qa @ q_rope_w          [S,2048] f32   (B [K][N])
    launch_gemm16_t<false, true>(qah, qrwh, qpe, S_LEN, NH * ROPE_D, Q_LORA,
                                 Q_LORA, NH * ROPE_D, NH * ROPE_D, 0, 0, 0, 1, 1.0f, 0);
    // 6) rope(q_pe) -> qfullh[:, 512:576]
    rope_q_kernel<<<dim3(S_LEN, NH), ROPE_D / 2>>>(qpe, pos, qfullh);
    // 7) dq = qa @ fusedqk[h] -> qfullh[:, :512] fp16 (batched, B [K][N])
    launch_gemm16_t<true, true>(qah, fqkh, qfullh, S_LEN, KV_LORA, Q_LORA,
                                Q_LORA, KV_LORA, CDIM,
                                0, (long long)Q_LORA * KV_LORA, (long long)S_LEN * CDIM,
                                NH, 1.0f, 0);
    // 8) logits = scale * qfull @ kfull^T, causal (f32 out, B [N][K])
    launch_gemm16_t<false, false>(qfullh, kfullh, logits, S_LEN, S_LEN, CDIM,
                                  CDIM, CDIM, S_LEN,
                                  (long long)S_LEN * CDIM, 0, (long long)S_LEN * S_LEN,
                                  NH, scale, 1);
    // 9) softmax -> probsh = 512*p fp16
    softmax_kernel<<<NH * S_LEN, 256>>>(logits, probsh);
    // 10) ctx = (1/512) * probs @ kva   (fp16 out, B = kfullh[:, :512] as [K][N], ldb=CDIM)
    launch_gemm16_t<true, true>(probsh, kfullh, ctxh, S_LEN, KV_LORA, S_LEN,
                                S_LEN, CDIM, KV_LORA,
                                (long long)S_LEN * S_LEN, 0, (long long)S_LEN * KV_LORA,
                                NH, 1.0f / 512.0f, 2);
    // 11) attnh[:, h*128:(h+1)*128] = ctx[h] @ v_up[h]  (fp16 out, B [K][N])
    launch_gemm16_t<true, true>(ctxh, vuph, attnh, S_LEN, V_D, KV_LORA,
                                KV_LORA, V_D, NH * V_D,
                                (long long)S_LEN * KV_LORA, (long long)KV_LORA * V_D, (long long)V_D,
                                NH, 1.0f, 0);
    // 12) out = attn @ W_o            [S,7168] f32 (B [K][N])
    launch_gemm16_t<false, true>(attnh, woh, out, S_LEN, HID, NH * V_D,
                                 NH * V_D, HID, HID, 0, 0, 0, 1, 1.0f, 0);
}

// round 10
// speedup vs baseline: 2.8413x; 1.0674x over previous
#include <cuda_runtime.h>
#include <cuda_fp16.h>
#include <math.h>
#include <stdint.h>

// ---------------- problem constants ----------------
#define S_LEN   2048
#define HID     7168
#define NH      32
#define Q_LORA  1536
#define KV_LORA 512
#define ROPE_D  64
#define CDIM    576
#define V_D     128
#define N12     (Q_LORA + CDIM)     // 2112 merged projection width
#define MIN_MASKED (-10000.0f)

// ---------------- scratch ----------------
__device__ float  g_pre12[(size_t)S_LEN * N12];
__device__ float  g_qpe[(size_t)S_LEN * (NH * ROPE_D)];
__device__ float  g_logits[(size_t)NH * S_LEN * S_LEN];
__device__ __half g_xh   [(size_t)S_LEN * HID];
__device__ __half g_qah  [(size_t)S_LEN * Q_LORA];
__device__ __half g_kfullh[(size_t)S_LEN * CDIM];
__device__ __half g_qfullh[(size_t)NH * S_LEN * CDIM];
__device__ __half g_probsh[(size_t)NH * S_LEN * S_LEN];
__device__ __half g_ctxh [(size_t)NH * S_LEN * KV_LORA];
__device__ __half g_attnh[(size_t)S_LEN * (NH * V_D)];
__device__ __half g_w12h[(size_t)HID * N12];
__device__ __half g_qrwh[(size_t)Q_LORA * (NH * ROPE_D)];
__device__ __half g_fqkh[(size_t)NH * Q_LORA * KV_LORA];
__device__ __half g_vuph[(size_t)NH * KV_LORA * V_D];
__device__ __half g_woh [(size_t)(NH * V_D) * HID];

// ---------------- helpers ----------------
__device__ __forceinline__ void mma16(float (&c)[4], const unsigned (&a)[4], const unsigned (&b)[2]) {
    asm volatile(
        "mma.sync.aligned.m16n8k16.row.col.f32.f16.f16.f32 "
        "{%0,%1,%2,%3}, {%4,%5,%6,%7}, {%8,%9}, {%0,%1,%2,%3};"
        : "+f"(c[0]), "+f"(c[1]), "+f"(c[2]), "+f"(c[3])
        : "r"(a[0]), "r"(a[1]), "r"(a[2]), "r"(a[3]), "r"(b[0]), "r"(b[1]));
}
__device__ __forceinline__ void ldsm4(unsigned &r0, unsigned &r1, unsigned &r2, unsigned &r3, uint32_t a) {
    asm volatile("ldmatrix.sync.aligned.m8n8.x4.shared.b16 {%0,%1,%2,%3}, [%4];"
                 : "=r"(r0), "=r"(r1), "=r"(r2), "=r"(r3) : "r"(a));
}
__device__ __forceinline__ void ldsm4t(unsigned &r0, unsigned &r1, unsigned &r2, unsigned &r3, uint32_t a) {
    asm volatile("ldmatrix.sync.aligned.m8n8.x4.trans.shared.b16 {%0,%1,%2,%3}, [%4];"
                 : "=r"(r0), "=r"(r1), "=r"(r2), "=r"(r3) : "r"(a));
}
__device__ __forceinline__ void cpasync16(uint32_t dst, const void* src, int srcsize) {
    asm volatile("cp.async.cg.shared.global [%0], [%1], 16, %2;"
                 :: "r"(dst), "l"(src), "r"(srcsize) : "memory");
}
__device__ __forceinline__ void cp_commit() { asm volatile("cp.async.commit_group;" ::: "memory"); }
template<int N> __device__ __forceinline__ void cp_wait() { asm volatile("cp.async.wait_group %0;" :: "n"(N) : "memory"); }

// ---------------- fp16 tensor-core GEMM, BK=64, 3-stage cp.async pipeline ----------------
// C[M,N] = alpha * A[M,K] @ B, A fp16 [M][K].
//   BKN=false: B fp16 [N][K]  -> ldmatrix
//   BKN=true : B fp16 [K][N]  -> ldmatrix.trans
// mode 0 plain; mode 1 causal epilogue + full-block skip; mode 2 kEnd=min(K,row0+128).
// Per stage: A 128 rows x 128B (16KB) + B 16KB; swizzle chunk c -> c ^ (row & 7).
#define STG_BYTES 32768

template<bool HALF_OUT, bool BKN>
__global__ void __launch_bounds__(256, 2)
gemm16_kernel(const __half* __restrict__ A, const __half* __restrict__ B, void* Cv,
              int M, int N, int K, int lda, int ldb, int ldc,
              long long sA, long long sB, long long sC,
              float alpha, int mode)
{
    extern __shared__ char smem[];
    const long long bz = blockIdx.z;
    A += bz * sA;  B += bz * sB;

    const int row0 = blockIdx.x * 128;
    const int col0 = blockIdx.y * 128;
    if (mode == 1 && col0 >= row0 + 128) return;

    float*  Cf = (float*)Cv  + bz * sC;
    __half* Ch = (__half*)Cv + bz * sC;

    const int tid  = threadIdx.x;
    const int lane = tid & 31;
    const int wid  = tid >> 5;
    const int wm   = wid >> 2;
    const int wn   = wid & 3;
    const int g    = lane >> 2;
    const int tig  = lane & 3;

    uint32_t sbase;
    asm("{ .reg .u64 t; cvta.to.shared.u64 t, %1; cvt.u32.u64 %0, t; }" : "=r"(sbase) : "l"(smem));

    const int kEnd = (mode == 2) ? min(K, row0 + 128) : K;
    const int T = kEnd >> 6;        // BK = 64

    auto issue = [&](int t) {
        int k0 = t << 6;
        uint32_t st = sbase + (uint32_t)((t % 3) * STG_BYTES);
        #pragma unroll
        for (int e = 0; e < 4; e++) {           // A: 128 rows x 8 chunks
            int id = tid + e * 256;
            int r = id >> 3, c = id & 7;
            uint32_t dst = st + (uint32_t)(r * 128 + ((c ^ (r & 7)) * 16));
            cpasync16(dst, A + (long long)(row0 + r) * lda + k0 + c * 8, 16);
        }
        if (!BKN) {
            #pragma unroll
            for (int e = 0; e < 4; e++) {       // B [N][K]: 128 rows x 8 chunks
                int id = tid + e * 256;
                int n = id >> 3, c = id & 7;
                uint32_t dst = st + 16384u + (uint32_t)(n * 128 + ((c ^ (n & 7)) * 16));
                bool ok = (col0 + n) < N;
                const __half* src = ok ? (B + (long long)(col0 + n) * ldb + k0 + c * 8) : B;
                cpasync16(dst, src, ok ? 16 : 0);
            }
        } else {
            #pragma unroll
            for (int e = 0; e < 4; e++) {       // B [K][N]: 64 rows x 16 chunks
                int id = tid + e * 256;
                int k = id >> 4, c = id & 15;
                uint32_t dst = st + 16384u + (uint32_t)(k * 256 + ((c ^ (k & 7)) * 16));
                bool ok = (col0 + c * 8) < N;
                const __half* src = ok ? (B + (long long)(k0 + k) * ldb + col0 + c * 8) : B;
                cpasync16(dst, src, ok ? 16 : 0);
            }
        }
        cp_commit();
    };

    float acc[4][4][4] = {};

    issue(0);
    if (1 < T) issue(1);

    const int rbA  = wm * 64 + ((lane >> 3) & 1) * 8 + (lane & 7);
    const int ksel = lane >> 4;

    for (int t = 0; t < T; t++) {
        if (t + 2 < T) issue(t + 2);
        int rem = T - 1 - t;
        if (rem >= 2)      cp_wait<2>();
        else if (rem == 1) cp_wait<1>();
        else               cp_wait<0>();
        __syncthreads();

        uint32_t stA = sbase + (uint32_t)((t % 3) * STG_BYTES);
        uint32_t stB = stA + 16384u;

        #pragma unroll
        for (int kk16 = 0; kk16 < 4; kk16++) {
            unsigned af[4][4], bf[4][2];
            int cA = kk16 * 2 + ksel;
            #pragma unroll
            for (int mi = 0; mi < 4; mi++) {
                int r = rbA + mi * 16;
                uint32_t ad = stA + (uint32_t)(r * 128 + ((cA ^ (r & 7)) << 4));
                ldsm4(af[mi][0], af[mi][1], af[mi][2], af[mi][3], ad);
            }
            if (!BKN) {
                int cB = kk16 * 2 + ((lane >> 3) & 1);
                #pragma unroll
                for (int njp = 0; njp < 2; njp++) {
                    int n = wn * 32 + njp * 16 + (lane >> 4) * 8 + (lane & 7);
                    uint32_t ad = stB + (uint32_t)(n * 128 + ((cB ^ (n & 7)) << 4));
                    ldsm4(bf[2 * njp][0], bf[2 * njp][1], bf[2 * njp + 1][0], bf[2 * njp + 1][1], ad);
                }
            } else {
                int kr = kk16 * 16 + ((lane >> 3) & 1) * 8 + (lane & 7);
                #pragma unroll
                for (int njp = 0; njp < 2; njp++) {
                    int nch = wn * 4 + njp * 2 + (lane >> 4);
                    uint32_t ad = stB + (uint32_t)(kr * 256 + ((nch ^ (kr & 7)) << 4));
                    ldsm4t(bf[2 * njp][0], bf[2 * njp][1], bf[2 * njp + 1][0], bf[2 * njp + 1][1], ad);
                }
            }
            #pragma unroll
            for (int mi = 0; mi < 4; mi++)
                #pragma unroll
                for (int nj = 0; nj < 4; nj++)
                    mma16(acc[mi][nj], af[mi], bf[nj]);
        }
        __syncthreads();
    }

    #pragma unroll
    for (int mi = 0; mi < 4; mi++) {
        int r = row0 + wm * 64 + mi * 16 + g;
        #pragma unroll
        for (int nj = 0; nj < 4; nj++) {
            int c = col0 + wn * 32 + nj * 8 + tig * 2;
            float v0 = acc[mi][nj][0] * alpha;
            float v1 = acc[mi][nj][1] * alpha;
            float v2 = acc[mi][nj][2] * alpha;
            float v3 = acc[mi][nj][3] * alpha;
            if (mode == 1) {
                v0 = (c     > r    ) ? MIN_MASKED : v0;
                v1 = (c + 1 > r    ) ? MIN_MASKED : v1;
                v2 = (c     > r + 8) ? MIN_MASKED : v2;
                v3 = (c + 1 > r + 8) ? MIN_MASKED : v3;
            }
            if (c < N) {
                if (HALF_OUT) {
                    *(__half2*)(Ch + (long long)r * ldc + c) =
                        __halves2half2(__float2half(v0), __float2half(v1));
                    *(__half2*)(Ch + (long long)(r + 8) * ldc + c) =
                        __halves2half2(__float2half(v2), __float2half(v3));
                } else {
                    *(float2*)(Cf + (long long)r * ldc + c)       = make_float2(v0, v1);
                    *(float2*)(Cf + (long long)(r + 8) * ldc + c) = make_float2(v2, v3);
                }
            }
        }
    }
}

// ---------------- prepass: fp32 -> fp16 convert (8 elems/iter, STG.128) ----------------
__global__ void convert_f2h_kernel(const float4* __restrict__ src, uint4* __restrict__ dst, int n8)
{
    int i = blockIdx.x * blockDim.x + threadIdx.x;
    int stride = gridDim.x * blockDim.x;
    for (; i < n8; i += stride) {
        float4 a = src[2 * i], b = src[2 * i + 1];
        __half2 h0 = __floats2half2_rn(a.x, a.y);
        __half2 h1 = __floats2half2_rn(a.z, a.w);
        __half2 h2 = __floats2half2_rn(b.x, b.y);
        __half2 h3 = __floats2half2_rn(b.z, b.w);
        uint4 o;
        o.x = *(unsigned*)&h0; o.y = *(unsigned*)&h1;
        o.z = *(unsigned*)&h2; o.w = *(unsigned*)&h3;
        dst[i] = o;
    }
}

// ---------------- prepass: fp32 [rows][C] -> fp16 packed into dst[r][off..off+C) ----------------
__global__ void pack_f2h_kernel(const float* __restrict__ src, __half* __restrict__ dst,
                                int C, int ldd, int off)
{
    int c4 = blockIdx.x * blockDim.x + threadIdx.x;     // column quad
    int r  = blockIdx.y;
    if (c4 < C / 4) {
        float4 v = *(const float4*)(src + (long long)r * C + 4 * c4);
        __half2 h0 = __floats2half2_rn(v.x, v.y);
        __half2 h1 = __floats2half2_rn(v.z, v.w);
        uint2 o; o.x = *(unsigned*)&h0; o.y = *(unsigned*)&h1;
        *(uint2*)(dst + (long long)r * ldd + off + 4 * c4) = o;
    }
}

// ---------------- rmsnorm(kva) + RoPE(k_pe) -> kfullh ----------------
__global__ void kva_rms_rope_kernel(const float* __restrict__ pre12,
                                    const float* __restrict__ kv_ln,
                                    const int*   __restrict__ pos_ids,
                                    __half* __restrict__ kfull)
{
    int s = blockIdx.x;
    const float* x = pre12 + (long long)s * N12 + Q_LORA;
    __half* out = kfull + (long long)s * CDIM;

    __shared__ float red[128];
    float ss = 0.0f;
    for (int i = threadIdx.x; i < KV_LORA; i += 128) { float v = x[i]; ss += v * v; }
    red[threadIdx.x] = ss; __syncthreads();
    for (int st = 64; st > 0; st >>= 1) {
        if (threadIdx.x < st) red[threadIdx.x] += red[threadIdx.x + st];
        __syncthreads();
    }
    float scale = rsqrtf(red[0] / (float)KV_LORA + 1e-6f);

    for (int i = threadIdx.x; i < KV_LORA; i += 128)
        out[i] = __float2half(x[i] * scale * kv_ln[i]);

    if (threadIdx.x < ROPE_D / 2) {
        int j = threadIdx.x;
        float pos  = (float)pos_ids[s];
        float invf = powf(10000.0f, -(float)(2 * j) / (float)ROPE_D);
        float ang  = pos * invf;
        float c = cosf(ang), sn = sinf(ang);
        float x0 = x[KV_LORA + 2 * j];
        float x1 = x[KV_LORA + 2 * j + 1];
        out[KV_LORA + j]              = __float2half(x0 * c - x1 * sn);
        out[KV_LORA + ROPE_D / 2 + j] = __float2half(x1 * c + x0 * sn);
    }
}

// ---------------- rmsnorm(q_a) -> fp16 ----------------
__global__ void qa_rms_kernel(const float* __restrict__ pre12,
                              const float* __restrict__ w,
                              __half* __restrict__ outp)
{
    int s = blockIdx.x;
    const float* x = pre12 + (long long)s * N12;
    __half* o = outp + (long long)s * Q_LORA;

    __shared__ float red[256];
    float ss = 0.0f;
    for (int i = threadIdx.x; i < Q_LORA; i += 256) { float v = x[i]; ss += v * v; }
    red[threadIdx.x] = ss; __syncthreads();
    for (int st = 128; st > 0; st >>= 1) {
        if (threadIdx.x < st) red[threadIdx.x] += red[threadIdx.x + st];
        __syncthreads();
    }
    float scale = rsqrtf(red[0] / (float)Q_LORA + 1e-6f);
    for (int i = threadIdx.x; i < Q_LORA; i += 256)
        o[i] = __float2half(x[i] * scale * w[i]);
}

// ---------------- RoPE on q_pe -> qfullh rope columns ----------------
__global__ void rope_q_kernel(const float* __restrict__ qpe,
                              const int*   __restrict__ pos_ids,
                              __half* __restrict__ qfull)
{
    int s = blockIdx.x;
    int h = blockIdx.y;
    int j = threadIdx.x;
    float pos  = (float)pos_ids[s];
    float invf = powf(10000.0f, -(float)(2 * j) / (float)ROPE_D);
    float ang  = pos * invf;
    float c = cosf(ang), sn = sinf(ang);
    const float* x = qpe + (long long)s * (NH * ROPE_D) + h * ROPE_D;
    float x0 = x[2 * j], x1 = x[2 * j + 1];
    __half* out = qfull + ((long long)h * S_LEN + s) * CDIM + KV_LORA;
    out[j]              = __float2half(x0 * c - x1 * sn);
    out[j + ROPE_D / 2] = __float2half(x1 * c + x0 * sn);
}

// ---------------- softmax over causal prefix; writes 512*p as fp16 ----------------
__global__ void softmax_kernel(const float* __restrict__ logits, __half* __restrict__ probs)
{
    long long row = blockIdx.x;
    int s = (int)(row & (S_LEN - 1));
    int limit = ((s >> 7) + 1) << 7;
    const float* p = logits + row * S_LEN;
    __half* q = probs + row * S_LEN;
    int tid = threadIdx.x;

    float v[8];
    int cnt = 0;
    float m = -1e30f;
    for (int i = tid; i < limit; i += 256) { v[cnt] = p[i]; m = fmaxf(m, v[cnt]); cnt++; }

    __shared__ float red[256];
    red[tid] = m; __syncthreads();
    for (int st = 128; st > 0; st >>= 1) {
        if (tid < st) red[tid] = fmaxf(red[tid], red[tid + st]);
        __syncthreads();
    }
    m = red[0]; __syncthreads();

    float sum = 0.0f;
    for (int j = 0; j < cnt; j++) { v[j] = __expf(v[j] - m); sum += v[j]; }
    red[tid] = sum; __syncthreads();
    for (int st = 128; st > 0; st >>= 1) {
        if (tid < st) red[tid] += red[tid + st];
        __syncthreads();
    }
    float inv = 512.0f / red[0];
    cnt = 0;
    for (int i = tid; i < limit; i += 256) { q[i] = __float2half(v[cnt] * inv); cnt++; }
}

// ---------------- host launchers ----------------
template<bool HALF_OUT, bool BKN>
static void launch_gemm16_t(const __half* A, const __half* B, void* C,
                            int M, int N, int K, int lda, int ldb, int ldc,
                            long long sA, long long sB, long long sC,
                            int batch, float alpha, int mode)
{
    dim3 grid(M / 128, (N + 127) / 128, batch);
    cudaFuncSetAttribute(gemm16_kernel<HALF_OUT, BKN>, cudaFuncAttributeMaxDynamicSharedMemorySize, 3 * STG_BYTES);
    gemm16_kernel<HALF_OUT, BKN><<<grid, 256, 3 * STG_BYTES>>>(A, B, C, M, N, K, lda, ldb, ldc, sA, sB, sC, alpha, mode);
}

static void launch_convert(const float* src, __half* dst, size_t n)
{
    int n8 = (int)(n / 8);
    int blocks = (n8 + 255) / 256;
    if (blocks > 2048) blocks = 2048;
    convert_f2h_kernel<<<blocks, 256>>>((const float4*)src, (uint4*)dst, n8);
}

extern "C" void kernel_launch(void* const* d_in, const int* in_sizes, int n_in,
                              void* d_out, int out_size)
{
    (void)in_sizes; (void)n_in; (void)out_size;
    const float* X        = (const float*)d_in[0];
    const int*   pos      = (const int*)d_in[2];
    const float* W_kv_a   = (const float*)d_in[3];
    const float* W_q_a    = (const float*)d_in[4];
    const float* q_ln     = (const float*)d_in[5];
    const float* kv_ln    = (const float*)d_in[6];
    const float* q_rope_w = (const float*)d_in[7];
    const float* fusedqk  = (const float*)d_in[8];
    const float* v_up     = (const float*)d_in[9];
    const float* W_o      = (const float*)d_in[10];
    float* out = (float*)d_out;

    float  *pre12, *qpe, *logits;
    __half *xh, *qah, *kfullh, *qfullh, *probsh, *ctxh, *attnh;
    __half *w12h, *qrwh, *fqkh, *vuph, *woh;
    cudaGetSymbolAddress((void**)&pre12,  g_pre12);
    cudaGetSymbolAddress((void**)&qpe,    g_qpe);
    cudaGetSymbolAddress((void**)&logits, g_logits);
    cudaGetSymbolAddress((void**)&xh,     g_xh);
    cudaGetSymbolAddress((void**)&qah,    g_qah);
    cudaGetSymbolAddress((void**)&kfullh, g_kfullh);
    cudaGetSymbolAddress((void**)&qfullh, g_qfullh);
    cudaGetSymbolAddress((void**)&probsh, g_probsh);
    cudaGetSymbolAddress((void**)&ctxh,   g_ctxh);
    cudaGetSymbolAddress((void**)&attnh,  g_attnh);
    cudaGetSymbolAddress((void**)&w12h,   g_w12h);
    cudaGetSymbolAddress((void**)&qrwh,   g_qrwh);
    cudaGetSymbolAddress((void**)&fqkh,   g_fqkh);
    cudaGetSymbolAddress((void**)&vuph,   g_vuph);
    cudaGetSymbolAddress((void**)&woh,    g_woh);

    const float scale = 1.0f / sqrtf(192.0f);

    // 0) prepass converts (natural layouts)
    launch_convert(X,        xh,   (size_t)S_LEN * HID);
    pack_f2h_kernel<<<dim3((Q_LORA / 4 + 255) / 256, HID), 256>>>(W_q_a,  w12h, Q_LORA, N12, 0);
    pack_f2h_kernel<<<dim3((CDIM   / 4 + 255) / 256, HID), 256>>>(W_kv_a, w12h, CDIM,   N12, Q_LORA);
    launch_convert(q_rope_w, qrwh, (size_t)Q_LORA * (NH * ROPE_D));
    launch_convert(fusedqk,  fqkh, (size_t)NH * Q_LORA * KV_LORA);
    launch_convert(v_up,     vuph, (size_t)NH * KV_LORA * V_D);
    launch_convert(W_o,      woh,  (size_t)(NH * V_D) * HID);

    // 1+2) pre12 = X @ [W_q | W_kv]   [S,2112] f32
    launch_gemm16_t<false, true>(xh, w12h, pre12, S_LEN, N12, HID,
                                 HID, N12, N12, 0, 0, 0, 1, 1.0f, 0);
    // 3) kfullh
    kva_rms_rope_kernel<<<S_LEN, 128>>>(pre12, kv_ln, pos, kfullh);
    // 4) qah
    qa_rms_kernel<<<S_LEN, 256>>>(pre12, q_ln, qah);
    // 5) qpe = qa @ q_rope_w
    launch_gemm16_t<false, true>(qah, qrwh, qpe, S_LEN, NH * ROPE_D, Q_LORA,
                                 Q_LORA, NH * ROPE_D, NH * ROPE_D, 0, 0, 0, 1, 1.0f, 0);
    // 6) rope(q_pe)
    rope_q_kernel<<<dim3(S_LEN, NH), ROPE_D / 2>>>(qpe, pos, qfullh);
    // 7) dq = qa @ fusedqk[h]
    launch_gemm16_t<true, true>(qah, fqkh, qfullh, S_LEN, KV_LORA, Q_LORA,
                                Q_LORA, KV_LORA, CDIM,
                                0, (long long)Q_LORA * KV_LORA, (long long)S_LEN * CDIM,
                                NH, 1.0f, 0);
    // 8) logits = scale * qfull @ kfull^T, causal
    launch_gemm16_t<false, false>(qfullh, kfullh, logits, S_LEN, S_LEN, CDIM,
                                  CDIM, CDIM, S_LEN,
                                  (long long)S_LEN * CDIM, 0, (long long)S_LEN * S_LEN,
                                  NH, scale, 1);
    // 9) softmax
    softmax_kernel<<<NH * S_LEN, 256>>>(logits, probsh);
    // 10) ctx = (1/512) * probs @ kva
    launch_gemm16_t<true, true>(probsh, kfullh, ctxh, S_LEN, KV_LORA, S_LEN,
                                S_LEN, CDIM, KV_LORA,
                                (long long)S_LEN * S_LEN, 0, (long long)S_LEN * KV_LORA,
                                NH, 1.0f / 512.0f, 2);
    // 11) attnh = ctx[h] @ v_up[h]
    launch_gemm16_t<true, true>(ctxh, vuph, attnh, S_LEN, V_D, KV_LORA,
                                KV_LORA, V_D, NH * V_D,
                                (long long)S_LEN * KV_LORA, (long long)KV_LORA * V_D, (long long)V_D,
                                NH, 1.0f, 0);
    // 12) out = attn @ W_o
    launch_gemm16_t<false, true>(attnh, woh, out, S_LEN, HID, NH * V_D,
                                 NH * V_D, HID, HID, 0, 0, 0, 1, 1.0f, 0);
}

// round 11
// speedup vs baseline: 3.1577x; 1.1114x over previous
#include <cuda_runtime.h>
#include <cuda_fp16.h>
#include <math.h>
#include <stdint.h>

// ---------------- problem constants ----------------
#define S_LEN   2048
#define HID     7168
#define NH      32
#define Q_LORA  1536
#define KV_LORA 512
#define ROPE_D  64
#define CDIM    576
#define V_D     128
#define N12     (Q_LORA + CDIM)     // 2112 merged projection width
#define MIN_MASKED (-10000.0f)

// ---------------- scratch ----------------
__device__ float  g_pre12[(size_t)S_LEN * N12];
__device__ float  g_qpe[(size_t)S_LEN * (NH * ROPE_D)];
__device__ float  g_logits[(size_t)NH * S_LEN * S_LEN];
__device__ __half g_xh   [(size_t)S_LEN * HID];
__device__ __half g_qah  [(size_t)S_LEN * Q_LORA];
__device__ __half g_kfullh[(size_t)S_LEN * CDIM];
__device__ __half g_qfullh[(size_t)NH * S_LEN * CDIM];
__device__ __half g_probsh[(size_t)NH * S_LEN * S_LEN];
__device__ __half g_vkva [(size_t)NH * S_LEN * V_D];     // kva @ v_up[h], fp16
__device__ __half g_attnh[(size_t)S_LEN * (NH * V_D)];
__device__ __half g_w12h[(size_t)HID * N12];
__device__ __half g_qrwh[(size_t)Q_LORA * (NH * ROPE_D)];
__device__ __half g_fqkh[(size_t)NH * Q_LORA * KV_LORA];
__device__ __half g_vuph[(size_t)NH * KV_LORA * V_D];
__device__ __half g_woh [(size_t)(NH * V_D) * HID];

// ---------------- helpers ----------------
__device__ __forceinline__ void mma16(float (&c)[4], const unsigned (&a)[4], const unsigned (&b)[2]) {
    asm volatile(
        "mma.sync.aligned.m16n8k16.row.col.f32.f16.f16.f32 "
        "{%0,%1,%2,%3}, {%4,%5,%6,%7}, {%8,%9}, {%0,%1,%2,%3};"
        : "+f"(c[0]), "+f"(c[1]), "+f"(c[2]), "+f"(c[3])
        : "r"(a[0]), "r"(a[1]), "r"(a[2]), "r"(a[3]), "r"(b[0]), "r"(b[1]));
}
__device__ __forceinline__ void ldsm4(unsigned &r0, unsigned &r1, unsigned &r2, unsigned &r3, uint32_t a) {
    asm volatile("ldmatrix.sync.aligned.m8n8.x4.shared.b16 {%0,%1,%2,%3}, [%4];"
                 : "=r"(r0), "=r"(r1), "=r"(r2), "=r"(r3) : "r"(a));
}
__device__ __forceinline__ void ldsm4t(unsigned &r0, unsigned &r1, unsigned &r2, unsigned &r3, uint32_t a) {
    asm volatile("ldmatrix.sync.aligned.m8n8.x4.trans.shared.b16 {%0,%1,%2,%3}, [%4];"
                 : "=r"(r0), "=r"(r1), "=r"(r2), "=r"(r3) : "r"(a));
}
__device__ __forceinline__ void cpasync16(uint32_t dst, const void* src, int srcsize) {
    asm volatile("cp.async.cg.shared.global [%0], [%1], 16, %2;"
                 :: "r"(dst), "l"(src), "r"(srcsize) : "memory");
}
__device__ __forceinline__ void cp_commit() { asm volatile("cp.async.commit_group;" ::: "memory"); }
template<int N> __device__ __forceinline__ void cp_wait() { asm volatile("cp.async.wait_group %0;" :: "n"(N) : "memory"); }

// ---------------- fp16 tensor-core GEMM, BK=64, 3-stage cp.async pipeline ----------------
// C[M,N] = alpha * A[M,K] @ B, A fp16 [M][K].
//   BKN=false: B fp16 [N][K]  -> ldmatrix
//   BKN=true : B fp16 [K][N]  -> ldmatrix.trans
// mode 0 plain; mode 1 causal epilogue + full-block skip; mode 2 kEnd=min(K,row0+128).
#define STG_BYTES 32768

template<bool HALF_OUT, bool BKN>
__global__ void __launch_bounds__(256, 2)
gemm16_kernel(const __half* __restrict__ A, const __half* __restrict__ B, void* Cv,
              int M, int N, int K, int lda, int ldb, int ldc,
              long long sA, long long sB, long long sC,
              float alpha, int mode)
{
    extern __shared__ char smem[];
    const long long bz = blockIdx.z;
    A += bz * sA;  B += bz * sB;

    const int row0 = blockIdx.x * 128;
    const int col0 = blockIdx.y * 128;
    if (mode == 1 && col0 >= row0 + 128) return;

    float*  Cf = (float*)Cv  + bz * sC;
    __half* Ch = (__half*)Cv + bz * sC;

    const int tid  = threadIdx.x;
    const int lane = tid & 31;
    const int wid  = tid >> 5;
    const int wm   = wid >> 2;
    const int wn   = wid & 3;
    const int g    = lane >> 2;
    const int tig  = lane & 3;

    uint32_t sbase;
    asm("{ .reg .u64 t; cvta.to.shared.u64 t, %1; cvt.u32.u64 %0, t; }" : "=r"(sbase) : "l"(smem));

    const int kEnd = (mode == 2) ? min(K, row0 + 128) : K;
    const int T = kEnd >> 6;        // BK = 64

    auto issue = [&](int t) {
        int k0 = t << 6;
        uint32_t st = sbase + (uint32_t)((t % 3) * STG_BYTES);
        #pragma unroll
        for (int e = 0; e < 4; e++) {           // A: 128 rows x 8 chunks
            int id = tid + e * 256;
            int r = id >> 3, c = id & 7;
            uint32_t dst = st + (uint32_t)(r * 128 + ((c ^ (r & 7)) * 16));
            cpasync16(dst, A + (long long)(row0 + r) * lda + k0 + c * 8, 16);
        }
        if (!BKN) {
            #pragma unroll
            for (int e = 0; e < 4; e++) {       // B [N][K]: 128 rows x 8 chunks
                int id = tid + e * 256;
                int n = id >> 3, c = id & 7;
                uint32_t dst = st + 16384u + (uint32_t)(n * 128 + ((c ^ (n & 7)) * 16));
                bool ok = (col0 + n) < N;
                const __half* src = ok ? (B + (long long)(col0 + n) * ldb + k0 + c * 8) : B;
                cpasync16(dst, src, ok ? 16 : 0);
            }
        } else {
            #pragma unroll
            for (int e = 0; e < 4; e++) {       // B [K][N]: 64 rows x 16 chunks
                int id = tid + e * 256;
                int k = id >> 4, c = id & 15;
                uint32_t dst = st + 16384u + (uint32_t)(k * 256 + ((c ^ (k & 7)) * 16));
                bool ok = (col0 + c * 8) < N;
                const __half* src = ok ? (B + (long long)(k0 + k) * ldb + col0 + c * 8) : B;
                cpasync16(dst, src, ok ? 16 : 0);
            }
        }
        cp_commit();
    };

    float acc[4][4][4] = {};

    issue(0);
    if (1 < T) issue(1);

    const int rbA  = wm * 64 + ((lane >> 3) & 1) * 8 + (lane & 7);
    const int ksel = lane >> 4;

    for (int t = 0; t < T; t++) {
        if (t + 2 < T) issue(t + 2);
        int rem = T - 1 - t;
        if (rem >= 2)      cp_wait<2>();
        else if (rem == 1) cp_wait<1>();
        else               cp_wait<0>();
        __syncthreads();

        uint32_t stA = sbase + (uint32_t)((t % 3) * STG_BYTES);
        uint32_t stB = stA + 16384u;

        #pragma unroll
        for (int kk16 = 0; kk16 < 4; kk16++) {
            unsigned af[4][4], bf[4][2];
            int cA = kk16 * 2 + ksel;
            #pragma unroll
            for (int mi = 0; mi < 4; mi++) {
                int r = rbA + mi * 16;
                uint32_t ad = stA + (uint32_t)(r * 128 + ((cA ^ (r & 7)) << 4));
                ldsm4(af[mi][0], af[mi][1], af[mi][2], af[mi][3], ad);
            }
            if (!BKN) {
                int cB = kk16 * 2 + ((lane >> 3) & 1);
                #pragma unroll
                for (int njp = 0; njp < 2; njp++) {
                    int n = wn * 32 + njp * 16 + (lane >> 4) * 8 + (lane & 7);
                    uint32_t ad = stB + (uint32_t)(n * 128 + ((cB ^ (n & 7)) << 4));
                    ldsm4(bf[2 * njp][0], bf[2 * njp][1], bf[2 * njp + 1][0], bf[2 * njp + 1][1], ad);
                }
            } else {
                int kr = kk16 * 16 + ((lane >> 3) & 1) * 8 + (lane & 7);
                #pragma unroll
                for (int njp = 0; njp < 2; njp++) {
                    int nch = wn * 4 + njp * 2 + (lane >> 4);
                    uint32_t ad = stB + (uint32_t)(kr * 256 + ((nch ^ (kr & 7)) << 4));
                    ldsm4t(bf[2 * njp][0], bf[2 * njp][1], bf[2 * njp + 1][0], bf[2 * njp + 1][1], ad);
                }
            }
            #pragma unroll
            for (int mi = 0; mi < 4; mi++)
                #pragma unroll
                for (int nj = 0; nj < 4; nj++)
                    mma16(acc[mi][nj], af[mi], bf[nj]);
        }
        __syncthreads();
    }

    #pragma unroll
    for (int mi = 0; mi < 4; mi++) {
        int r = row0 + wm * 64 + mi * 16 + g;
        #pragma unroll
        for (int nj = 0; nj < 4; nj++) {
            int c = col0 + wn * 32 + nj * 8 + tig * 2;
            float v0 = acc[mi][nj][0] * alpha;
            float v1 = acc[mi][nj][1] * alpha;
            float v2 = acc[mi][nj][2] * alpha;
            float v3 = acc[mi][nj][3] * alpha;
            if (mode == 1) {
                v0 = (c     > r    ) ? MIN_MASKED : v0;
                v1 = (c + 1 > r    ) ? MIN_MASKED : v1;
                v2 = (c     > r + 8) ? MIN_MASKED : v2;
                v3 = (c + 1 > r + 8) ? MIN_MASKED : v3;
            }
            if (c < N) {
                if (HALF_OUT) {
                    *(__half2*)(Ch + (long long)r * ldc + c) =
                        __halves2half2(__float2half(v0), __float2half(v1));
                    *(__half2*)(Ch + (long long)(r + 8) * ldc + c) =
                        __halves2half2(__float2half(v2), __float2half(v3));
                } else {
                    *(float2*)(Cf + (long long)r * ldc + c)       = make_float2(v0, v1);
                    *(float2*)(Cf + (long long)(r + 8) * ldc + c) = make_float2(v2, v3);
                }
            }
        }
    }
}

// ---------------- prepass: fp32 -> fp16 convert (8 elems/iter, STG.128) ----------------
__global__ void convert_f2h_kernel(const float4* __restrict__ src, uint4* __restrict__ dst, int n8)
{
    int i = blockIdx.x * blockDim.x + threadIdx.x;
    int stride = gridDim.x * blockDim.x;
    for (; i < n8; i += stride) {
        float4 a = src[2 * i], b = src[2 * i + 1];
        __half2 h0 = __floats2half2_rn(a.x, a.y);
        __half2 h1 = __floats2half2_rn(a.z, a.w);
        __half2 h2 = __floats2half2_rn(b.x, b.y);
        __half2 h3 = __floats2half2_rn(b.z, b.w);
        uint4 o;
        o.x = *(unsigned*)&h0; o.y = *(unsigned*)&h1;
        o.z = *(unsigned*)&h2; o.w = *(unsigned*)&h3;
        dst[i] = o;
    }
}

// ---------------- prepass: fp32 [rows][C] -> fp16 packed into dst[r][off..off+C) ----------------
__global__ void pack_f2h_kernel(const float* __restrict__ src, __half* __restrict__ dst,
                                int C, int ldd, int off)
{
    int c4 = blockIdx.x * blockDim.x + threadIdx.x;
    int r  = blockIdx.y;
    if (c4 < C / 4) {
        float4 v = *(const float4*)(src + (long long)r * C + 4 * c4);
        __half2 h0 = __floats2half2_rn(v.x, v.y);
        __half2 h1 = __floats2half2_rn(v.z, v.w);
        uint2 o; o.x = *(unsigned*)&h0; o.y = *(unsigned*)&h1;
        *(uint2*)(dst + (long long)r * ldd + off + 4 * c4) = o;
    }
}

// ---------------- rmsnorm(kva) + RoPE(k_pe) -> kfullh ----------------
__global__ void kva_rms_rope_kernel(const float* __restrict__ pre12,
                                    const float* __restrict__ kv_ln,
                                    const int*   __restrict__ pos_ids,
                                    __half* __restrict__ kfull)
{
    int s = blockIdx.x;
    const float* x = pre12 + (long long)s * N12 + Q_LORA;
    __half* out = kfull + (long long)s * CDIM;

    __shared__ float red[128];
    float ss = 0.0f;
    for (int i = threadIdx.x; i < KV_LORA; i += 128) { float v = x[i]; ss += v * v; }
    red[threadIdx.x] = ss; __syncthreads();
    for (int st = 64; st > 0; st >>= 1) {
        if (threadIdx.x < st) red[threadIdx.x] += red[threadIdx.x + st];
        __syncthreads();
    }
    float scale = rsqrtf(red[0] / (float)KV_LORA + 1e-6f);

    for (int i = threadIdx.x; i < KV_LORA; i += 128)
        out[i] = __float2half(x[i] * scale * kv_ln[i]);

    if (threadIdx.x < ROPE_D / 2) {
        int j = threadIdx.x;
        float pos  = (float)pos_ids[s];
        float invf = powf(10000.0f, -(float)(2 * j) / (float)ROPE_D);
        float ang  = pos * invf;
        float c = cosf(ang), sn = sinf(ang);
        float x0 = x[KV_LORA + 2 * j];
        float x1 = x[KV_LORA + 2 * j + 1];
        out[KV_LORA + j]              = __float2half(x0 * c - x1 * sn);
        out[KV_LORA + ROPE_D / 2 + j] = __float2half(x1 * c + x0 * sn);
    }
}

// ---------------- rmsnorm(q_a) -> fp16 ----------------
__global__ void qa_rms_kernel(const float* __restrict__ pre12,
                              const float* __restrict__ w,
                              __half* __restrict__ outp)
{
    int s = blockIdx.x;
    const float* x = pre12 + (long long)s * N12;
    __half* o = outp + (long long)s * Q_LORA;

    __shared__ float red[256];
    float ss = 0.0f;
    for (int i = threadIdx.x; i < Q_LORA; i += 256) { float v = x[i]; ss += v * v; }
    red[threadIdx.x] = ss; __syncthreads();
    for (int st = 128; st > 0; st >>= 1) {
        if (threadIdx.x < st) red[threadIdx.x] += red[threadIdx.x + st];
        __syncthreads();
    }
    float scale = rsqrtf(red[0] / (float)Q_LORA + 1e-6f);
    for (int i = threadIdx.x; i < Q_LORA; i += 256)
        o[i] = __float2half(x[i] * scale * w[i]);
}

// ---------------- RoPE on q_pe -> qfullh rope columns (warp per head, 8 heads/block) ----------------
__global__ void rope_q_kernel(const float* __restrict__ qpe,
                              const int*   __restrict__ pos_ids,
                              __half* __restrict__ qfull)
{
    int s = blockIdx.x;
    int h = blockIdx.y * 8 + (threadIdx.x >> 5);
    int j = threadIdx.x & 31;
    float pos  = (float)pos_ids[s];
    float invf = powf(10000.0f, -(float)(2 * j) / (float)ROPE_D);
    float ang  = pos * invf;
    float c = cosf(ang), sn = sinf(ang);
    const float* x = qpe + (long long)s * (NH * ROPE_D) + h * ROPE_D;
    float x0 = x[2 * j], x1 = x[2 * j + 1];
    __half* out = qfull + ((long long)h * S_LEN + s) * CDIM + KV_LORA;
    out[j]              = __float2half(x0 * c - x1 * sn);
    out[j + ROPE_D / 2] = __float2half(x1 * c + x0 * sn);
}

// ---------------- softmax over causal prefix; writes 512*p as fp16 ----------------
__global__ void softmax_kernel(const float* __restrict__ logits, __half* __restrict__ probs)
{
    long long row = blockIdx.x;
    int s = (int)(row & (S_LEN - 1));
    int limit = ((s >> 7) + 1) << 7;
    const float* p = logits + row * S_LEN;
    __half* q = probs + row * S_LEN;
    int tid = threadIdx.x;

    float v[8];
    int cnt = 0;
    float m = -1e30f;
    for (int i = tid; i < limit; i += 256) { v[cnt] = p[i]; m = fmaxf(m, v[cnt]); cnt++; }

    __shared__ float red[256];
    red[tid] = m; __syncthreads();
    for (int st = 128; st > 0; st >>= 1) {
        if (tid < st) red[tid] = fmaxf(red[tid], red[tid + st]);
        __syncthreads();
    }
    m = red[0]; __syncthreads();

    float sum = 0.0f;
    for (int j = 0; j < cnt; j++) { v[j] = __expf(v[j] - m); sum += v[j]; }
    red[tid] = sum; __syncthreads();
    for (int st = 128; st > 0; st >>= 1) {
        if (tid < st) red[tid] += red[tid + st];
        __syncthreads();
    }
    float inv = 512.0f / red[0];
    cnt = 0;
    for (int i = tid; i < limit; i += 256) { q[i] = __float2half(v[cnt] * inv); cnt++; }
}

// ---------------- host launchers ----------------
template<bool HALF_OUT, bool BKN>
static void launch_gemm16_t(const __half* A, const __half* B, void* C,
                            int M, int N, int K, int lda, int ldb, int ldc,
                            long long sA, long long sB, long long sC,
                            int batch, float alpha, int mode)
{
    dim3 grid(M / 128, (N + 127) / 128, batch);
    cudaFuncSetAttribute(gemm16_kernel<HALF_OUT, BKN>, cudaFuncAttributeMaxDynamicSharedMemorySize, 3 * STG_BYTES);
    gemm16_kernel<HALF_OUT, BKN><<<grid, 256, 3 * STG_BYTES>>>(A, B, C, M, N, K, lda, ldb, ldc, sA, sB, sC, alpha, mode);
}

static void launch_convert(const float* src, __half* dst, size_t n)
{
    int n8 = (int)(n / 8);
    int blocks = (n8 + 255) / 256;
    if (blocks > 2048) blocks = 2048;
    convert_f2h_kernel<<<blocks, 256>>>((const float4*)src, (uint4*)dst, n8);
}

extern "C" void kernel_launch(void* const* d_in, const int* in_sizes, int n_in,
                              void* d_out, int out_size)
{
    (void)in_sizes; (void)n_in; (void)out_size;
    const float* X        = (const float*)d_in[0];
    const int*   pos      = (const int*)d_in[2];
    const float* W_kv_a   = (const float*)d_in[3];
    const float* W_q_a    = (const float*)d_in[4];
    const float* q_ln     = (const float*)d_in[5];
    const float* kv_ln    = (const float*)d_in[6];
    const float* q_rope_w = (const float*)d_in[7];
    const float* fusedqk  = (const float*)d_in[8];
    const float* v_up     = (const float*)d_in[9];
    const float* W_o      = (const float*)d_in[10];
    float* out = (float*)d_out;

    float  *pre12, *qpe, *logits;
    __half *xh, *qah, *kfullh, *qfullh, *probsh, *vkva, *attnh;
    __half *w12h, *qrwh, *fqkh, *vuph, *woh;
    cudaGetSymbolAddress((void**)&pre12,  g_pre12);
    cudaGetSymbolAddress((void**)&qpe,    g_qpe);
    cudaGetSymbolAddress((void**)&logits, g_logits);
    cudaGetSymbolAddress((void**)&xh,     g_xh);
    cudaGetSymbolAddress((void**)&qah,    g_qah);
    cudaGetSymbolAddress((void**)&kfullh, g_kfullh);
    cudaGetSymbolAddress((void**)&qfullh, g_qfullh);
    cudaGetSymbolAddress((void**)&probsh, g_probsh);
    cudaGetSymbolAddress((void**)&vkva,   g_vkva);
    cudaGetSymbolAddress((void**)&attnh,  g_attnh);
    cudaGetSymbolAddress((void**)&w12h,   g_w12h);
    cudaGetSymbolAddress((void**)&qrwh,   g_qrwh);
    cudaGetSymbolAddress((void**)&fqkh,   g_fqkh);
    cudaGetSymbolAddress((void**)&vuph,   g_vuph);
    cudaGetSymbolAddress((void**)&woh,    g_woh);

    const float scale = 1.0f / sqrtf(192.0f);

    // 0) prepass converts (natural layouts)
    launch_convert(X,        xh,   (size_t)S_LEN * HID);
    pack_f2h_kernel<<<dim3((Q_LORA / 4 + 255) / 256, HID), 256>>>(W_q_a,  w12h, Q_LORA, N12, 0);
    pack_f2h_kernel<<<dim3((CDIM   / 4 + 255) / 256, HID), 256>>>(W_kv_a, w12h, CDIM,   N12, Q_LORA);
    launch_convert(q_rope_w, qrwh, (size_t)Q_LORA * (NH * ROPE_D));
    launch_convert(fusedqk,  fqkh, (size_t)NH * Q_LORA * KV_LORA);
    launch_convert(v_up,     vuph, (size_t)NH * KV_LORA * V_D);
    launch_convert(W_o,      woh,  (size_t)(NH * V_D) * HID);

    // 1+2) pre12 = X @ [W_q | W_kv]   [S,2112] f32
    launch_gemm16_t<false, true>(xh, w12h, pre12, S_LEN, N12, HID,
                                 HID, N12, N12, 0, 0, 0, 1, 1.0f, 0);
    // 3) kfullh
    kva_rms_rope_kernel<<<S_LEN, 128>>>(pre12, kv_ln, pos, kfullh);
    // 3b) vkva[h] = kva @ v_up[h]    [S,128] fp16 per head (A = kfullh[:, :512], lda=CDIM)
    launch_gemm16_t<true, true>(kfullh, vuph, vkva, S_LEN, V_D, KV_LORA,
                                CDIM, V_D, V_D,
                                0, (long long)KV_LORA * V_D, (long long)S_LEN * V_D,
                                NH, 1.0f, 0);
    // 4) qah
    qa_rms_kernel<<<S_LEN, 256>>>(pre12, q_ln, qah);
    // 5) qpe = qa @ q_rope_w
    launch_gemm16_t<false, true>(qah, qrwh, qpe, S_LEN, NH * ROPE_D, Q_LORA,
                                 Q_LORA, NH * ROPE_D, NH * ROPE_D, 0, 0, 0, 1, 1.0f, 0);
    // 6) rope(q_pe)
    rope_q_kernel<<<dim3(S_LEN, NH / 8), 256>>>(qpe, pos, qfullh);
    // 7) dq = qa @ fusedqk[h]
    launch_gemm16_t<true, true>(qah, fqkh, qfullh, S_LEN, KV_LORA, Q_LORA,
                                Q_LORA, KV_LORA, CDIM,
                                0, (long long)Q_LORA * KV_LORA, (long long)S_LEN * CDIM,
                                NH, 1.0f, 0);
    // 8) logits = scale * qfull @ kfull^T, causal
    launch_gemm16_t<false, false>(qfullh, kfullh, logits, S_LEN, S_LEN, CDIM,
                                  CDIM, CDIM, S_LEN,
                                  (long long)S_LEN * CDIM, 0, (long long)S_LEN * S_LEN,
                                  NH, scale, 1);
    // 9) softmax
    softmax_kernel<<<NH * S_LEN, 256>>>(logits, probsh);
    // 10) attnh[:, h*128:(h+1)*128] = (1/512) * probs_h @ vkva_h   (causal K cap)
    launch_gemm16_t<true, true>(probsh, vkva, attnh, S_LEN, V_D, S_LEN,
                                S_LEN, V_D, NH * V_D,
                                (long long)S_LEN * S_LEN, (long long)S_LEN * V_D, (long long)V_D,
                                NH, 1.0f / 512.0f, 2);
    // 12) out = attn @ W_o
    launch_gemm16_t<false, true>(attnh, woh, out, S_LEN, HID, NH * V_D,
                                 NH * V_D, HID, HID, 0, 0, 0, 1, 1.0f, 0);
}

// round 12
// speedup vs baseline: 3.3501x; 1.0609x over previous
#include <cuda_runtime.h>
#include <cuda_fp16.h>
#include <math.h>
#include <stdint.h>

// ---------------- problem constants ----------------
#define S_LEN   2048
#define HID     7168
#define NH      32
#define Q_LORA  1536
#define KV_LORA 512
#define ROPE_D  64
#define CDIM    576
#define V_D     128
#define N12     (Q_LORA + CDIM)     // 2112 merged projection width
#define MIN_MASKED (-10000.0f)

// ---------------- scratch ----------------
__device__ float  g_pre12[(size_t)S_LEN * N12];
__device__ float  g_qpe[(size_t)S_LEN * (NH * ROPE_D)];
__device__ float  g_logits[(size_t)NH * S_LEN * S_LEN];
__device__ __half g_xh   [(size_t)S_LEN * HID];
__device__ __half g_qah  [(size_t)S_LEN * Q_LORA];
__device__ __half g_kfullh[(size_t)S_LEN * CDIM];
__device__ __half g_qfullh[(size_t)NH * S_LEN * CDIM];
__device__ __half g_probsh[(size_t)NH * S_LEN * S_LEN];
__device__ __half g_vkva [(size_t)NH * S_LEN * V_D];     // kva @ v_up[h], fp16
__device__ __half g_attnh[(size_t)S_LEN * (NH * V_D)];
__device__ __half g_w12h[(size_t)HID * N12];
__device__ __half g_qrwh[(size_t)Q_LORA * (NH * ROPE_D)];
__device__ __half g_fqkh[(size_t)NH * Q_LORA * KV_LORA];
__device__ __half g_vuph[(size_t)NH * KV_LORA * V_D];
__device__ __half g_woh [(size_t)(NH * V_D) * HID];

// ---------------- helpers ----------------
__device__ __forceinline__ void mma16(float (&c)[4], const unsigned (&a)[4], const unsigned (&b)[2]) {
    asm volatile(
        "mma.sync.aligned.m16n8k16.row.col.f32.f16.f16.f32 "
        "{%0,%1,%2,%3}, {%4,%5,%6,%7}, {%8,%9}, {%0,%1,%2,%3};"
        : "+f"(c[0]), "+f"(c[1]), "+f"(c[2]), "+f"(c[3])
        : "r"(a[0]), "r"(a[1]), "r"(a[2]), "r"(a[3]), "r"(b[0]), "r"(b[1]));
}
__device__ __forceinline__ void ldsm4(unsigned &r0, unsigned &r1, unsigned &r2, unsigned &r3, uint32_t a) {
    asm volatile("ldmatrix.sync.aligned.m8n8.x4.shared.b16 {%0,%1,%2,%3}, [%4];"
                 : "=r"(r0), "=r"(r1), "=r"(r2), "=r"(r3) : "r"(a));
}
__device__ __forceinline__ void ldsm4t(unsigned &r0, unsigned &r1, unsigned &r2, unsigned &r3, uint32_t a) {
    asm volatile("ldmatrix.sync.aligned.m8n8.x4.trans.shared.b16 {%0,%1,%2,%3}, [%4];"
                 : "=r"(r0), "=r"(r1), "=r"(r2), "=r"(r3) : "r"(a));
}
__device__ __forceinline__ void cpasync16(uint32_t dst, const void* src, int srcsize) {
    asm volatile("cp.async.cg.shared.global [%0], [%1], 16, %2;"
                 :: "r"(dst), "l"(src), "r"(srcsize) : "memory");
}
__device__ __forceinline__ void cp_commit() { asm volatile("cp.async.commit_group;" ::: "memory"); }
template<int N> __device__ __forceinline__ void cp_wait() { asm volatile("cp.async.wait_group %0;" :: "n"(N) : "memory"); }

// ---------------- fp16 tensor-core GEMM, BK=64, 3-stage, ONE barrier/stage ----------------
// C[M,N] = alpha * A[M,K] @ B, A fp16 [M][K].
//   BKN=false: B fp16 [N][K]  -> ldmatrix
//   BKN=true : B fp16 [K][N]  -> ldmatrix.trans
// mode 0 plain; mode 1 causal epilogue + full-block skip; mode 2 kEnd=min(K,row0+128).
// Handshake per stage t: cp_wait<1> (local stage-t arrival) -> __syncthreads()
// (global arrival + all finished compute(t-1)) -> issue(t+2) (overwrites stage t-1,
// now safe) -> compute(t).
#define STG_BYTES 32768

template<bool HALF_OUT, bool BKN>
__global__ void __launch_bounds__(256, 2)
gemm16_kernel(const __half* __restrict__ A, const __half* __restrict__ B, void* Cv,
              int M, int N, int K, int lda, int ldb, int ldc,
              long long sA, long long sB, long long sC,
              float alpha, int mode)
{
    extern __shared__ char smem[];
    const long long bz = blockIdx.z;
    A += bz * sA;  B += bz * sB;

    const int row0 = blockIdx.x * 128;
    const int col0 = blockIdx.y * 128;
    if (mode == 1 && col0 >= row0 + 128) return;

    float*  Cf = (float*)Cv  + bz * sC;
    __half* Ch = (__half*)Cv + bz * sC;

    const int tid  = threadIdx.x;
    const int lane = tid & 31;
    const int wid  = tid >> 5;
    const int wm   = wid >> 2;
    const int wn   = wid & 3;
    const int g    = lane >> 2;
    const int tig  = lane & 3;

    uint32_t sbase;
    asm("{ .reg .u64 t; cvta.to.shared.u64 t, %1; cvt.u32.u64 %0, t; }" : "=r"(sbase) : "l"(smem));

    const int kEnd = (mode == 2) ? min(K, row0 + 128) : K;
    const int T = kEnd >> 6;        // BK = 64

    auto issue = [&](int t) {
        int k0 = t << 6;
        uint32_t st = sbase + (uint32_t)((t % 3) * STG_BYTES);
        #pragma unroll
        for (int e = 0; e < 4; e++) {           // A: 128 rows x 8 chunks
            int id = tid + e * 256;
            int r = id >> 3, c = id & 7;
            uint32_t dst = st + (uint32_t)(r * 128 + ((c ^ (r & 7)) * 16));
            cpasync16(dst, A + (long long)(row0 + r) * lda + k0 + c * 8, 16);
        }
        if (!BKN) {
            #pragma unroll
            for (int e = 0; e < 4; e++) {       // B [N][K]: 128 rows x 8 chunks
                int id = tid + e * 256;
                int n = id >> 3, c = id & 7;
                uint32_t dst = st + 16384u + (uint32_t)(n * 128 + ((c ^ (n & 7)) * 16));
                bool ok = (col0 + n) < N;
                const __half* src = ok ? (B + (long long)(col0 + n) * ldb + k0 + c * 8) : B;
                cpasync16(dst, src, ok ? 16 : 0);
            }
        } else {
            #pragma unroll
            for (int e = 0; e < 4; e++) {       // B [K][N]: 64 rows x 16 chunks
                int id = tid + e * 256;
                int k = id >> 4, c = id & 15;
                uint32_t dst = st + 16384u + (uint32_t)(k * 256 + ((c ^ (k & 7)) * 16));
                bool ok = (col0 + c * 8) < N;
                const __half* src = ok ? (B + (long long)(k0 + k) * ldb + col0 + c * 8) : B;
                cpasync16(dst, src, ok ? 16 : 0);
            }
        }
        cp_commit();
    };

    float acc[4][4][4] = {};

    issue(0);
    if (1 < T) issue(1);

    const int rbA  = wm * 64 + ((lane >> 3) & 1) * 8 + (lane & 7);
    const int ksel = lane >> 4;

    for (int t = 0; t < T; t++) {
        if (t + 1 < T) cp_wait<1>();
        else           cp_wait<0>();
        __syncthreads();
        if (t + 2 < T) issue(t + 2);

        uint32_t stA = sbase + (uint32_t)((t % 3) * STG_BYTES);
        uint32_t stB = stA + 16384u;

        #pragma unroll
        for (int kk16 = 0; kk16 < 4; kk16++) {
            unsigned af[4][4], bf[4][2];
            int cA = kk16 * 2 + ksel;
            #pragma unroll
            for (int mi = 0; mi < 4; mi++) {
                int r = rbA + mi * 16;
                uint32_t ad = stA + (uint32_t)(r * 128 + ((cA ^ (r & 7)) << 4));
                ldsm4(af[mi][0], af[mi][1], af[mi][2], af[mi][3], ad);
            }
            if (!BKN) {
                int cB = kk16 * 2 + ((lane >> 3) & 1);
                #pragma unroll
                for (int njp = 0; njp < 2; njp++) {
                    int n = wn * 32 + njp * 16 + (lane >> 4) * 8 + (lane & 7);
                    uint32_t ad = stB + (uint32_t)(n * 128 + ((cB ^ (n & 7)) << 4));
                    ldsm4(bf[2 * njp][0], bf[2 * njp][1], bf[2 * njp + 1][0], bf[2 * njp + 1][1], ad);
                }
            } else {
                int kr = kk16 * 16 + ((lane >> 3) & 1) * 8 + (lane & 7);
                #pragma unroll
                for (int njp = 0; njp < 2; njp++) {
                    int nch = wn * 4 + njp * 2 + (lane >> 4);
                    uint32_t ad = stB + (uint32_t)(kr * 256 + ((nch ^ (kr & 7)) << 4));
                    ldsm4t(bf[2 * njp][0], bf[2 * njp][1], bf[2 * njp + 1][0], bf[2 * njp + 1][1], ad);
                }
            }
            #pragma unroll
            for (int mi = 0; mi < 4; mi++)
                #pragma unroll
                for (int nj = 0; nj < 4; nj++)
                    mma16(acc[mi][nj], af[mi], bf[nj]);
        }
    }

    #pragma unroll
    for (int mi = 0; mi < 4; mi++) {
        int r = row0 + wm * 64 + mi * 16 + g;
        #pragma unroll
        for (int nj = 0; nj < 4; nj++) {
            int c = col0 + wn * 32 + nj * 8 + tig * 2;
            float v0 = acc[mi][nj][0] * alpha;
            float v1 = acc[mi][nj][1] * alpha;
            float v2 = acc[mi][nj][2] * alpha;
            float v3 = acc[mi][nj][3] * alpha;
            if (mode == 1) {
                v0 = (c     > r    ) ? MIN_MASKED : v0;
                v1 = (c + 1 > r    ) ? MIN_MASKED : v1;
                v2 = (c     > r + 8) ? MIN_MASKED : v2;
                v3 = (c + 1 > r + 8) ? MIN_MASKED : v3;
            }
            if (c < N) {
                if (HALF_OUT) {
                    *(__half2*)(Ch + (long long)r * ldc + c) =
                        __halves2half2(__float2half(v0), __float2half(v1));
                    *(__half2*)(Ch + (long long)(r + 8) * ldc + c) =
                        __halves2half2(__float2half(v2), __float2half(v3));
                } else {
                    *(float2*)(Cf + (long long)r * ldc + c)       = make_float2(v0, v1);
                    *(float2*)(Cf + (long long)(r + 8) * ldc + c) = make_float2(v2, v3);
                }
            }
        }
    }
}

// ---------------- prepass: fp32 -> fp16 convert (8 elems/iter, STG.128) ----------------
__global__ void convert_f2h_kernel(const float4* __restrict__ src, uint4* __restrict__ dst, int n8)
{
    int i = blockIdx.x * blockDim.x + threadIdx.x;
    int stride = gridDim.x * blockDim.x;
    for (; i < n8; i += stride) {
        float4 a = src[2 * i], b = src[2 * i + 1];
        __half2 h0 = __floats2half2_rn(a.x, a.y);
        __half2 h1 = __floats2half2_rn(a.z, a.w);
        __half2 h2 = __floats2half2_rn(b.x, b.y);
        __half2 h3 = __floats2half2_rn(b.z, b.w);
        uint4 o;
        o.x = *(unsigned*)&h0; o.y = *(unsigned*)&h1;
        o.z = *(unsigned*)&h2; o.w = *(unsigned*)&h3;
        dst[i] = o;
    }
}

// ---------------- prepass: fp32 [rows][C] -> fp16 packed into dst[r][off..off+C) ----------------
__global__ void pack_f2h_kernel(const float* __restrict__ src, __half* __restrict__ dst,
                                int C, int ldd, int off)
{
    int c4 = blockIdx.x * blockDim.x + threadIdx.x;
    int r  = blockIdx.y;
    if (c4 < C / 4) {
        float4 v = *(const float4*)(src + (long long)r * C + 4 * c4);
        __half2 h0 = __floats2half2_rn(v.x, v.y);
        __half2 h1 = __floats2half2_rn(v.z, v.w);
        uint2 o; o.x = *(unsigned*)&h0; o.y = *(unsigned*)&h1;
        *(uint2*)(dst + (long long)r * ldd + off + 4 * c4) = o;
    }
}

// ---------------- rmsnorm(kva) + RoPE(k_pe) -> kfullh ----------------
__global__ void kva_rms_rope_kernel(const float* __restrict__ pre12,
                                    const float* __restrict__ kv_ln,
                                    const int*   __restrict__ pos_ids,
                                    __half* __restrict__ kfull)
{
    int s = blockIdx.x;
    const float* x = pre12 + (long long)s * N12 + Q_LORA;
    __half* out = kfull + (long long)s * CDIM;

    __shared__ float red[128];
    float ss = 0.0f;
    for (int i = threadIdx.x; i < KV_LORA; i += 128) { float v = x[i]; ss += v * v; }
    red[threadIdx.x] = ss; __syncthreads();
    for (int st = 64; st > 0; st >>= 1) {
        if (threadIdx.x < st) red[threadIdx.x] += red[threadIdx.x + st];
        __syncthreads();
    }
    float scale = rsqrtf(red[0] / (float)KV_LORA + 1e-6f);

    for (int i = threadIdx.x; i < KV_LORA; i += 128)
        out[i] = __float2half(x[i] * scale * kv_ln[i]);

    if (threadIdx.x < ROPE_D / 2) {
        int j = threadIdx.x;
        float pos  = (float)pos_ids[s];
        float invf = powf(10000.0f, -(float)(2 * j) / (float)ROPE_D);
        float ang  = pos * invf;
        float c = cosf(ang), sn = sinf(ang);
        float x0 = x[KV_LORA + 2 * j];
        float x1 = x[KV_LORA + 2 * j + 1];
        out[KV_LORA + j]              = __float2half(x0 * c - x1 * sn);
        out[KV_LORA + ROPE_D / 2 + j] = __float2half(x1 * c + x0 * sn);
    }
}

// ---------------- rmsnorm(q_a) -> fp16 ----------------
__global__ void qa_rms_kernel(const float* __restrict__ pre12,
                              const float* __restrict__ w,
                              __half* __restrict__ outp)
{
    int s = blockIdx.x;
    const float* x = pre12 + (long long)s * N12;
    __half* o = outp + (long long)s * Q_LORA;

    __shared__ float red[256];
    float ss = 0.0f;
    for (int i = threadIdx.x; i < Q_LORA; i += 256) { float v = x[i]; ss += v * v; }
    red[threadIdx.x] = ss; __syncthreads();
    for (int st = 128; st > 0; st >>= 1) {
        if (threadIdx.x < st) red[threadIdx.x] += red[threadIdx.x + st];
        __syncthreads();
    }
    float scale = rsqrtf(red[0] / (float)Q_LORA + 1e-6f);
    for (int i = threadIdx.x; i < Q_LORA; i += 256)
        o[i] = __float2half(x[i] * scale * w[i]);
}

// ---------------- RoPE on q_pe -> qfullh rope columns (warp per head, 8 heads/block) ----------------
__global__ void rope_q_kernel(const float* __restrict__ qpe,
                              const int*   __restrict__ pos_ids,
                              __half* __restrict__ qfull)
{
    int s = blockIdx.x;
    int h = blockIdx.y * 8 + (threadIdx.x >> 5);
    int j = threadIdx.x & 31;
    float pos  = (float)pos_ids[s];
    float invf = powf(10000.0f, -(float)(2 * j) / (float)ROPE_D);
    float ang  = pos * invf;
    float c = cosf(ang), sn = sinf(ang);
    const float* x = qpe + (long long)s * (NH * ROPE_D) + h * ROPE_D;
    float x0 = x[2 * j], x1 = x[2 * j + 1];
    __half* out = qfull + ((long long)h * S_LEN + s) * CDIM + KV_LORA;
    out[j]              = __float2half(x0 * c - x1 * sn);
    out[j + ROPE_D / 2] = __float2half(x1 * c + x0 * sn);
}

// ---------------- softmax over causal prefix; writes 512*p as fp16 (vectorized) ----------------
__global__ void softmax_kernel(const float* __restrict__ logits, __half* __restrict__ probs)
{
    long long row = blockIdx.x;
    int s = (int)(row & (S_LEN - 1));
    int limit4 = (((s >> 7) + 1) << 7) >> 2;        // float4 count, multiple of 32
    const float4* p4 = (const float4*)(logits + row * S_LEN);
    __half* q = probs + row * S_LEN;
    int tid = threadIdx.x;

    float4 v[2];
    int cnt = 0;
    float m = -1e30f;
    for (int i = tid; i < limit4; i += 256) {
        float4 t = p4[i];
        v[cnt] = t;
        m = fmaxf(m, fmaxf(fmaxf(t.x, t.y), fmaxf(t.z, t.w)));
        cnt++;
    }

    __shared__ float red[256];
    red[tid] = m; __syncthreads();
    for (int st = 128; st > 0; st >>= 1) {
        if (tid < st) red[tid] = fmaxf(red[tid], red[tid + st]);
        __syncthreads();
    }
    m = red[0]; __syncthreads();

    float sum = 0.0f;
    #pragma unroll
    for (int j = 0; j < 2; j++) {
        if (j < cnt) {
            v[j].x = __expf(v[j].x - m); v[j].y = __expf(v[j].y - m);
            v[j].z = __expf(v[j].z - m); v[j].w = __expf(v[j].w - m);
            sum += v[j].x + v[j].y + v[j].z + v[j].w;
        }
    }
    red[tid] = sum; __syncthreads();
    for (int st = 128; st > 0; st >>= 1) {
        if (tid < st) red[tid] += red[tid + st];
        __syncthreads();
    }
    float inv = 512.0f / red[0];
    cnt = 0;
    for (int i = tid; i < limit4; i += 256) {
        __half2 h0 = __floats2half2_rn(v[cnt].x * inv, v[cnt].y * inv);
        __half2 h1 = __floats2half2_rn(v[cnt].z * inv, v[cnt].w * inv);
        uint2 o; o.x = *(unsigned*)&h0; o.y = *(unsigned*)&h1;
        *(uint2*)(q + 4 * i) = o;
        cnt++;
    }
}

// ---------------- host launchers ----------------
template<bool HALF_OUT, bool BKN>
static void launch_gemm16_t(const __half* A, const __half* B, void* C,
                            int M, int N, int K, int lda, int ldb, int ldc,
                            long long sA, long long sB, long long sC,
                            int batch, float alpha, int mode)
{
    dim3 grid(M / 128, (N + 127) / 128, batch);
    cudaFuncSetAttribute(gemm16_kernel<HALF_OUT, BKN>, cudaFuncAttributeMaxDynamicSharedMemorySize, 3 * STG_BYTES);
    gemm16_kernel<HALF_OUT, BKN><<<grid, 256, 3 * STG_BYTES>>>(A, B, C, M, N, K, lda, ldb, ldc, sA, sB, sC, alpha, mode);
}

static void launch_convert(const float* src, __half* dst, size_t n)
{
    int n8 = (int)(n / 8);
    int blocks = (n8 + 255) / 256;
    if (blocks > 2048) blocks = 2048;
    convert_f2h_kernel<<<blocks, 256>>>((const float4*)src, (uint4*)dst, n8);
}

extern "C" void kernel_launch(void* const* d_in, const int* in_sizes, int n_in,
                              void* d_out, int out_size)
{
    (void)in_sizes; (void)n_in; (void)out_size;
    const float* X        = (const float*)d_in[0];
    const int*   pos      = (const int*)d_in[2];
    const float* W_kv_a   = (const float*)d_in[3];
    const float* W_q_a    = (const float*)d_in[4];
    const float* q_ln     = (const float*)d_in[5];
    const float* kv_ln    = (const float*)d_in[6];
    const float* q_rope_w = (const float*)d_in[7];
    const float* fusedqk  = (const float*)d_in[8];
    const float* v_up     = (const float*)d_in[9];
    const float* W_o      = (const float*)d_in[10];
    float* out = (float*)d_out;

    float  *pre12, *qpe, *logits;
    __half *xh, *qah, *kfullh, *qfullh, *probsh, *vkva, *attnh;
    __half *w12h, *qrwh, *fqkh, *vuph, *woh;
    cudaGetSymbolAddress((void**)&pre12,  g_pre12);
    cudaGetSymbolAddress((void**)&qpe,    g_qpe);
    cudaGetSymbolAddress((void**)&logits, g_logits);
    cudaGetSymbolAddress((void**)&xh,     g_xh);
    cudaGetSymbolAddress((void**)&qah,    g_qah);
    cudaGetSymbolAddress((void**)&kfullh, g_kfullh);
    cudaGetSymbolAddress((void**)&qfullh, g_qfullh);
    cudaGetSymbolAddress((void**)&probsh, g_probsh);
    cudaGetSymbolAddress((void**)&vkva,   g_vkva);
    cudaGetSymbolAddress((void**)&attnh,  g_attnh);
    cudaGetSymbolAddress((void**)&w12h,   g_w12h);
    cudaGetSymbolAddress((void**)&qrwh,   g_qrwh);
    cudaGetSymbolAddress((void**)&fqkh,   g_fqkh);
    cudaGetSymbolAddress((void**)&vuph,   g_vuph);
    cudaGetSymbolAddress((void**)&woh,    g_woh);

    const float scale = 1.0f / sqrtf(192.0f);

    // 0) prepass converts (natural layouts)
    launch_convert(X,        xh,   (size_t)S_LEN * HID);
    pack_f2h_kernel<<<dim3((Q_LORA / 4 + 255) / 256, HID), 256>>>(W_q_a,  w12h, Q_LORA, N12, 0);
    pack_f2h_kernel<<<dim3((CDIM   / 4 + 255) / 256, HID), 256>>>(W_kv_a, w12h, CDIM,   N12, Q_LORA);
    launch_convert(q_rope_w, qrwh, (size_t)Q_LORA * (NH * ROPE_D));
    launch_convert(fusedqk,  fqkh, (size_t)NH * Q_LORA * KV_LORA);
    launch_convert(v_up,     vuph, (size_t)NH * KV_LORA * V_D);
    launch_convert(W_o,      woh,  (size_t)(NH * V_D) * HID);

    // 1+2) pre12 = X @ [W_q | W_kv]   [S,2112] f32
    launch_gemm16_t<false, true>(xh, w12h, pre12, S_LEN, N12, HID,
                                 HID, N12, N12, 0, 0, 0, 1, 1.0f, 0);
    // 3) kfullh
    kva_rms_rope_kernel<<<S_LEN, 128>>>(pre12, kv_ln, pos, kfullh);
    // 3b) vkva[h] = kva @ v_up[h]    [S,128] fp16 per head (A = kfullh[:, :512], lda=CDIM)
    launch_gemm16_t<true, true>(kfullh, vuph, vkva, S_LEN, V_D, KV_LORA,
                                CDIM, V_D, V_D,
                                0, (long long)KV_LORA * V_D, (long long)S_LEN * V_D,
                                NH, 1.0f, 0);
    // 4) qah
    qa_rms_kernel<<<S_LEN, 256>>>(pre12, q_ln, qah);
    // 5) qpe = qa @ q_rope_w
    launch_gemm16_t<false, true>(qah, qrwh, qpe, S_LEN, NH * ROPE_D, Q_LORA,
                                 Q_LORA, NH * ROPE_D, NH * ROPE_D, 0, 0, 0, 1, 1.0f, 0);
    // 6) rope(q_pe)
    rope_q_kernel<<<dim3(S_LEN, NH / 8), 256>>>(qpe, pos, qfullh);
    // 7) dq = qa @ fusedqk[h]
    launch_gemm16_t<true, true>(qah, fqkh, qfullh, S_LEN, KV_LORA, Q_LORA,
                                Q_LORA, KV_LORA, CDIM,
                                0, (long long)Q_LORA * KV_LORA, (long long)S_LEN * CDIM,
                                NH, 1.0f, 0);
    // 8) logits = scale * qfull @ kfull^T, causal
    launch_gemm16_t<false, false>(qfullh, kfullh, logits, S_LEN, S_LEN, CDIM,
                                  CDIM, CDIM, S_LEN,
                                  (long long)S_LEN * CDIM, 0, (long long)S_LEN * S_LEN,
                                  NH, scale, 1);
    // 9) softmax
    softmax_kernel<<<NH * S_LEN, 256>>>(logits, probsh);
    // 10) attnh[:, h*128:(h+1)*128] = (1/512) * probs_h @ vkva_h   (causal K cap)
    launch_gemm16_t<true, true>(probsh, vkva, attnh, S_LEN, V_D, S_LEN,
                                S_LEN, V_D, NH * V_D,
                                (long long)S_LEN * S_LEN, (long long)S_LEN * V_D, (long long)V_D,
                                NH, 1.0f / 512.0f, 2);
    // 12) out = attn @ W_o
    launch_gemm16_t<false, true>(attnh, woh, out, S_LEN, HID, NH * V_D,
                                 NH * V_D, HID, HID, 0, 0, 0, 1, 1.0f, 0);
}

// round 13
// speedup vs baseline: 3.3715x; 1.0064x over previous
#include <cuda_runtime.h>
#include <cuda_fp16.h>
#include <math.h>
#include <stdint.h>

// ---------------- problem constants ----------------
#define S_LEN   2048
#define HID     7168
#define NH      32
#define Q_LORA  1536
#define KV_LORA 512
#define ROPE_D  64
#define CDIM    576
#define V_D     128
#define N12     (Q_LORA + CDIM)
#define MIN_MASKED (-10000.0f)

// ---------------- scratch ----------------
__device__ float  g_pre12[(size_t)S_LEN * N12];
__device__ float  g_qpe[(size_t)S_LEN * (NH * ROPE_D)];
__device__ __half g_xh   [(size_t)S_LEN * HID];
__device__ __half g_qah  [(size_t)S_LEN * Q_LORA];
__device__ __half g_kfullh[(size_t)S_LEN * CDIM];
__device__ __half g_qfullh[(size_t)NH * S_LEN * CDIM];
__device__ __half g_vkva [(size_t)NH * S_LEN * V_D];
__device__ __half g_attnh[(size_t)S_LEN * (NH * V_D)];
__device__ __half g_w12h[(size_t)HID * N12];
__device__ __half g_qrwh[(size_t)Q_LORA * (NH * ROPE_D)];
__device__ __half g_fqkh[(size_t)NH * Q_LORA * KV_LORA];
__device__ __half g_vuph[(size_t)NH * KV_LORA * V_D];
__device__ __half g_woh [(size_t)(NH * V_D) * HID];

// ---------------- helpers ----------------
__device__ __forceinline__ void mma16(float (&c)[4], const unsigned (&a)[4], const unsigned (&b)[2]) {
    asm volatile(
        "mma.sync.aligned.m16n8k16.row.col.f32.f16.f16.f32 "
        "{%0,%1,%2,%3}, {%4,%5,%6,%7}, {%8,%9}, {%0,%1,%2,%3};"
        : "+f"(c[0]), "+f"(c[1]), "+f"(c[2]), "+f"(c[3])
        : "r"(a[0]), "r"(a[1]), "r"(a[2]), "r"(a[3]), "r"(b[0]), "r"(b[1]));
}
__device__ __forceinline__ void ldsm4(unsigned &r0, unsigned &r1, unsigned &r2, unsigned &r3, uint32_t a) {
    asm volatile("ldmatrix.sync.aligned.m8n8.x4.shared.b16 {%0,%1,%2,%3}, [%4];"
                 : "=r"(r0), "=r"(r1), "=r"(r2), "=r"(r3) : "r"(a));
}
__device__ __forceinline__ void ldsm4t(unsigned &r0, unsigned &r1, unsigned &r2, unsigned &r3, uint32_t a) {
    asm volatile("ldmatrix.sync.aligned.m8n8.x4.trans.shared.b16 {%0,%1,%2,%3}, [%4];"
                 : "=r"(r0), "=r"(r1), "=r"(r2), "=r"(r3) : "r"(a));
}
__device__ __forceinline__ void cpasync16(uint32_t dst, const void* src, int srcsize) {
    asm volatile("cp.async.cg.shared.global [%0], [%1], 16, %2;"
                 :: "r"(dst), "l"(src), "r"(srcsize) : "memory");
}
__device__ __forceinline__ void cp_commit() { asm volatile("cp.async.commit_group;" ::: "memory"); }
template<int N> __device__ __forceinline__ void cp_wait() { asm volatile("cp.async.wait_group %0;" :: "n"(N) : "memory"); }
__device__ __forceinline__ uint32_t smem_addr32(const void* p) {
    uint32_t a;
    asm("{ .reg .u64 t; cvta.to.shared.u64 t, %1; cvt.u32.u64 %0, t; }" : "=r"(a) : "l"(p));
    return a;
}

// ---------------- fp16 tensor-core GEMM (unchanged from R11) ----------------
#define STG_BYTES 32768

template<bool HALF_OUT, bool BKN>
__global__ void __launch_bounds__(256, 2)
gemm16_kernel(const __half* __restrict__ A, const __half* __restrict__ B, void* Cv,
              int M, int N, int K, int lda, int ldb, int ldc,
              long long sA, long long sB, long long sC,
              float alpha, int mode)
{
    extern __shared__ char smem[];
    const long long bz = blockIdx.z;
    A += bz * sA;  B += bz * sB;

    const int row0 = blockIdx.x * 128;
    const int col0 = blockIdx.y * 128;
    if (mode == 1 && col0 >= row0 + 128) return;

    float*  Cf = (float*)Cv  + bz * sC;
    __half* Ch = (__half*)Cv + bz * sC;

    const int tid  = threadIdx.x;
    const int lane = tid & 31;
    const int wid  = tid >> 5;
    const int wm   = wid >> 2;
    const int wn   = wid & 3;
    const int g    = lane >> 2;
    const int tig  = lane & 3;

    uint32_t sbase = smem_addr32(smem);

    const int kEnd = (mode == 2) ? min(K, row0 + 128) : K;
    const int T = kEnd >> 6;

    auto issue = [&](int t) {
        int k0 = t << 6;
        uint32_t st = sbase + (uint32_t)((t % 3) * STG_BYTES);
        #pragma unroll
        for (int e = 0; e < 4; e++) {
            int id = tid + e * 256;
            int r = id >> 3, c = id & 7;
            uint32_t dst = st + (uint32_t)(r * 128 + ((c ^ (r & 7)) * 16));
            cpasync16(dst, A + (long long)(row0 + r) * lda + k0 + c * 8, 16);
        }
        if (!BKN) {
            #pragma unroll
            for (int e = 0; e < 4; e++) {
                int id = tid + e * 256;
                int n = id >> 3, c = id & 7;
                uint32_t dst = st + 16384u + (uint32_t)(n * 128 + ((c ^ (n & 7)) * 16));
                bool ok = (col0 + n) < N;
                const __half* src = ok ? (B + (long long)(col0 + n) * ldb + k0 + c * 8) : B;
                cpasync16(dst, src, ok ? 16 : 0);
            }
        } else {
            #pragma unroll
            for (int e = 0; e < 4; e++) {
                int id = tid + e * 256;
                int k = id >> 4, c = id & 15;
                uint32_t dst = st + 16384u + (uint32_t)(k * 256 + ((c ^ (k & 7)) * 16));
                bool ok = (col0 + c * 8) < N;
                const __half* src = ok ? (B + (long long)(k0 + k) * ldb + col0 + c * 8) : B;
                cpasync16(dst, src, ok ? 16 : 0);
            }
        }
        cp_commit();
    };

    float acc[4][4][4] = {};

    issue(0);
    if (1 < T) issue(1);

    const int rbA  = wm * 64 + ((lane >> 3) & 1) * 8 + (lane & 7);
    const int ksel = lane >> 4;

    for (int t = 0; t < T; t++) {
        if (t + 1 < T) cp_wait<1>();
        else           cp_wait<0>();
        __syncthreads();
        if (t + 2 < T) issue(t + 2);

        uint32_t stA = sbase + (uint32_t)((t % 3) * STG_BYTES);
        uint32_t stB = stA + 16384u;

        #pragma unroll
        for (int kk16 = 0; kk16 < 4; kk16++) {
            unsigned af[4][4], bf[4][2];
            int cA = kk16 * 2 + ksel;
            #pragma unroll
            for (int mi = 0; mi < 4; mi++) {
                int r = rbA + mi * 16;
                uint32_t ad = stA + (uint32_t)(r * 128 + ((cA ^ (r & 7)) << 4));
                ldsm4(af[mi][0], af[mi][1], af[mi][2], af[mi][3], ad);
            }
            if (!BKN) {
                int cB = kk16 * 2 + ((lane >> 3) & 1);
                #pragma unroll
                for (int njp = 0; njp < 2; njp++) {
                    int n = wn * 32 + njp * 16 + (lane >> 4) * 8 + (lane & 7);
                    uint32_t ad = stB + (uint32_t)(n * 128 + ((cB ^ (n & 7)) << 4));
                    ldsm4(bf[2 * njp][0], bf[2 * njp][1], bf[2 * njp + 1][0], bf[2 * njp + 1][1], ad);
                }
            } else {
                int kr = kk16 * 16 + ((lane >> 3) & 1) * 8 + (lane & 7);
                #pragma unroll
                for (int njp = 0; njp < 2; njp++) {
                    int nch = wn * 4 + njp * 2 + (lane >> 4);
                    uint32_t ad = stB + (uint32_t)(kr * 256 + ((nch ^ (kr & 7)) << 4));
                    ldsm4t(bf[2 * njp][0], bf[2 * njp][1], bf[2 * njp + 1][0], bf[2 * njp + 1][1], ad);
                }
            }
            #pragma unroll
            for (int mi = 0; mi < 4; mi++)
                #pragma unroll
                for (int nj = 0; nj < 4; nj++)
                    mma16(acc[mi][nj], af[mi], bf[nj]);
        }
    }

    #pragma unroll
    for (int mi = 0; mi < 4; mi++) {
        int r = row0 + wm * 64 + mi * 16 + g;
        #pragma unroll
        for (int nj = 0; nj < 4; nj++) {
            int c = col0 + wn * 32 + nj * 8 + tig * 2;
            float v0 = acc[mi][nj][0] * alpha;
            float v1 = acc[mi][nj][1] * alpha;
            float v2 = acc[mi][nj][2] * alpha;
            float v3 = acc[mi][nj][3] * alpha;
            if (mode == 1) {
                v0 = (c     > r    ) ? MIN_MASKED : v0;
                v1 = (c + 1 > r    ) ? MIN_MASKED : v1;
                v2 = (c     > r + 8) ? MIN_MASKED : v2;
                v3 = (c + 1 > r + 8) ? MIN_MASKED : v3;
            }
            if (c < N) {
                if (HALF_OUT) {
                    *(__half2*)(Ch + (long long)r * ldc + c) =
                        __halves2half2(__float2half(v0), __float2half(v1));
                    *(__half2*)(Ch + (long long)(r + 8) * ldc + c) =
                        __halves2half2(__float2half(v2), __float2half(v3));
                } else {
                    *(float2*)(Cf + (long long)r * ldc + c)       = make_float2(v0, v1);
                    *(float2*)(Cf + (long long)(r + 8) * ldc + c) = make_float2(v2, v3);
                }
            }
        }
    }
}

// ---------------- fused flash attention: QK^T + online softmax + PV ----------------
// One CTA = (row block i, head h). S = Q_i K_j^T streamed over j<=i with the
// 3-stage cp.async mainloop; P staged through smem in GEMM-A format; V prefetched
// during S-phase; O normalized by 1/(512*l) at the end.
// smem: [0,98304) 3 QK stages; [98304,131072) P; [131072,163840) V;
//       [163840,165888) smax; [165888,167936) ssum.
#define FL_SMEM 167936

__global__ void __launch_bounds__(256, 1)
flash_kernel(const __half* __restrict__ Qf, const __half* __restrict__ Kf,
             const __half* __restrict__ Vk, __half* __restrict__ attn,
             float scale)
{
    extern __shared__ char smem[];
    const int i = 15 - blockIdx.x;          // largest-work CTAs first
    const int h = blockIdx.z;
    const int row0 = i * 128;
    const __half* Q = Qf + (size_t)h * S_LEN * CDIM;
    const __half* V = Vk + (size_t)h * S_LEN * V_D;

    const int tid  = threadIdx.x;
    const int lane = tid & 31;
    const int wid  = tid >> 5;
    const int wm   = wid >> 2;
    const int wn   = wid & 3;
    const int g    = lane >> 2;
    const int tig  = lane & 3;

    uint32_t sb = smem_addr32(smem);
    uint32_t Pb = sb + 98304u;
    uint32_t Vb = sb + 131072u;
    float* smax = (float*)(smem + 163840);
    float* ssum = (float*)(smem + 165888);

    float O[4][4][4] = {};
    float mst[4][2], lst[4][2];
    #pragma unroll
    for (int mi = 0; mi < 4; mi++) { mst[mi][0] = mst[mi][1] = -1e30f; lst[mi][0] = lst[mi][1] = 0.f; }

    const int rbA  = wm * 64 + ((lane >> 3) & 1) * 8 + (lane & 7);
    const int ksel = lane >> 4;

    for (int j = 0; j <= i; j++) {
        // --- V prefetch (own cp.async group, completes by wait<0> at t=8) ---
        #pragma unroll
        for (int e = 0; e < 8; e++) {
            int id = tid + e * 256;
            int k = id >> 4, c = id & 15;
            uint32_t dst = Vb + (uint32_t)((k >> 6) * 16384 + (k & 63) * 256 + ((c ^ (k & 7)) << 4));
            cpasync16(dst, V + (size_t)(j * 128 + k) * V_D + c * 8, 16);
        }
        cp_commit();

        // --- S = Q_i K_j^T, K=576 (T=9), 3-stage pipeline ---
        auto issueS = [&](int t) {
            int k0 = t << 6;
            uint32_t st = sb + (uint32_t)((t % 3) * STG_BYTES);
            #pragma unroll
            for (int e = 0; e < 4; e++) {
                int id = tid + e * 256;
                int r = id >> 3, c = id & 7;
                cpasync16(st + (uint32_t)(r * 128 + ((c ^ (r & 7)) * 16)),
                          Q + (size_t)(row0 + r) * CDIM + k0 + c * 8, 16);
            }
            #pragma unroll
            for (int e = 0; e < 4; e++) {
                int id = tid + e * 256;
                int n = id >> 3, c = id & 7;
                cpasync16(st + 16384u + (uint32_t)(n * 128 + ((c ^ (n & 7)) * 16)),
                          Kf + (size_t)(j * 128 + n) * CDIM + k0 + c * 8, 16);
            }
            cp_commit();
        };

        float S[4][4][4] = {};
        issueS(0); issueS(1);
        for (int t = 0; t < 9; t++) {
            if (t + 1 < 9) cp_wait<1>();
            else           cp_wait<0>();
            __syncthreads();
            if (t + 2 < 9) issueS(t + 2);

            uint32_t stA = sb + (uint32_t)((t % 3) * STG_BYTES);
            uint32_t stB = stA + 16384u;
            #pragma unroll
            for (int kk16 = 0; kk16 < 4; kk16++) {
                unsigned af[4][4], bf[4][2];
                int cA = kk16 * 2 + ksel;
                #pragma unroll
                for (int mi = 0; mi < 4; mi++) {
                    int r = rbA + mi * 16;
                    ldsm4(af[mi][0], af[mi][1], af[mi][2], af[mi][3],
                          stA + (uint32_t)(r * 128 + ((cA ^ (r & 7)) << 4)));
                }
                int cB = kk16 * 2 + ((lane >> 3) & 1);
                #pragma unroll
                for (int njp = 0; njp < 2; njp++) {
                    int n = wn * 32 + njp * 16 + (lane >> 4) * 8 + (lane & 7);
                    ldsm4(bf[2 * njp][0], bf[2 * njp][1], bf[2 * njp + 1][0], bf[2 * njp + 1][1],
                          stB + (uint32_t)(n * 128 + ((cB ^ (n & 7)) << 4)));
                }
                #pragma unroll
                for (int mi = 0; mi < 4; mi++)
                    #pragma unroll
                    for (int nj = 0; nj < 4; nj++)
                        mma16(S[mi][nj], af[mi], bf[nj]);
            }
        }

        // --- online softmax: row max ---
        const bool diag = (j == i);
        float lm[4][2];
        #pragma unroll
        for (int mi = 0; mi < 4; mi++) { lm[mi][0] = lm[mi][1] = -1e30f; }
        #pragma unroll
        for (int mi = 0; mi < 4; mi++)
            #pragma unroll
            for (int nj = 0; nj < 4; nj++)
                #pragma unroll
                for (int c = 0; c < 4; c++) {
                    int hf = c >> 1;
                    int rl = wm * 64 + mi * 16 + g + hf * 8;
                    int cl = wn * 32 + nj * 8 + tig * 2 + (c & 1);
                    float s = S[mi][nj][c] * scale;
                    if (diag && cl > rl) s = -1e30f;
                    lm[mi][hf] = fmaxf(lm[mi][hf], s);
                }
        #pragma unroll
        for (int mi = 0; mi < 4; mi++)
            #pragma unroll
            for (int hf = 0; hf < 2; hf++) {
                lm[mi][hf] = fmaxf(lm[mi][hf], __shfl_xor_sync(0xffffffffu, lm[mi][hf], 1));
                lm[mi][hf] = fmaxf(lm[mi][hf], __shfl_xor_sync(0xffffffffu, lm[mi][hf], 2));
            }
        if (tig == 0) {
            #pragma unroll
            for (int mi = 0; mi < 4; mi++)
                #pragma unroll
                for (int hf = 0; hf < 2; hf++)
                    smax[wn * 128 + wm * 64 + mi * 16 + g + hf * 8] = lm[mi][hf];
        }
        __syncthreads();

        float alpha_[4][2];
        #pragma unroll
        for (int mi = 0; mi < 4; mi++)
            #pragma unroll
            for (int hf = 0; hf < 2; hf++) {
                int rl = wm * 64 + mi * 16 + g + hf * 8;
                float mj = fmaxf(fmaxf(smax[rl], smax[128 + rl]),
                                 fmaxf(smax[256 + rl], smax[384 + rl]));
                float mn = fmaxf(mst[mi][hf], mj);
                float al = __expf(mst[mi][hf] - mn);
                mst[mi][hf] = mn;
                lst[mi][hf] *= al;
                alpha_[mi][hf] = al;
            }
        #pragma unroll
        for (int mi = 0; mi < 4; mi++)
            #pragma unroll
            for (int nj = 0; nj < 4; nj++) {
                O[mi][nj][0] *= alpha_[mi][0]; O[mi][nj][1] *= alpha_[mi][0];
                O[mi][nj][2] *= alpha_[mi][1]; O[mi][nj][3] *= alpha_[mi][1];
            }

        // --- exp + P store (x512, fp16) + row sums ---
        float ls[4][2];
        #pragma unroll
        for (int mi = 0; mi < 4; mi++) { ls[mi][0] = ls[mi][1] = 0.f; }
        #pragma unroll
        for (int mi = 0; mi < 4; mi++)
            #pragma unroll
            for (int nj = 0; nj < 4; nj++) {
                #pragma unroll
                for (int c = 0; c < 4; c++) {
                    int hf = c >> 1;
                    int rl = wm * 64 + mi * 16 + g + hf * 8;
                    int cl = wn * 32 + nj * 8 + tig * 2 + (c & 1);
                    float s = S[mi][nj][c] * scale;
                    if (diag && cl > rl) s = -1e30f;
                    float p = __expf(s - mst[mi][hf]);
                    S[mi][nj][c] = p;
                    ls[mi][hf] += p;
                }
                // store 512*p as half2 into P (GEMM-A swizzled format)
                int cc = wn * 32 + nj * 8 + tig * 2;
                uint32_t hb  = (uint32_t)(cc >> 6) * 16384u;
                int ccc = cc & 63;
                int r1 = wm * 64 + mi * 16 + g;
                uint32_t a1 = Pb + hb + (uint32_t)(r1 * 128 + ((((ccc >> 3) ^ (r1 & 7))) << 4) + (ccc & 7) * 2);
                int r2 = r1 + 8;
                uint32_t a2 = Pb + hb + (uint32_t)(r2 * 128 + ((((ccc >> 3) ^ (r2 & 7))) << 4) + (ccc & 7) * 2);
                __half2 v1 = __floats2half2_rn(S[mi][nj][0] * 512.f, S[mi][nj][1] * 512.f);
                __half2 v2 = __floats2half2_rn(S[mi][nj][2] * 512.f, S[mi][nj][3] * 512.f);
                *(__half2*)(smem + (a1 - sb)) = v1;
                *(__half2*)(smem + (a2 - sb)) = v2;
            }
        #pragma unroll
        for (int mi = 0; mi < 4; mi++)
            #pragma unroll
            for (int hf = 0; hf < 2; hf++) {
                ls[mi][hf] += __shfl_xor_sync(0xffffffffu, ls[mi][hf], 1);
                ls[mi][hf] += __shfl_xor_sync(0xffffffffu, ls[mi][hf], 2);
            }
        if (tig == 0) {
            #pragma unroll
            for (int mi = 0; mi < 4; mi++)
                #pragma unroll
                for (int hf = 0; hf < 2; hf++)
                    ssum[wn * 128 + wm * 64 + mi * 16 + g + hf * 8] = ls[mi][hf];
        }
        __syncthreads();

        #pragma unroll
        for (int mi = 0; mi < 4; mi++)
            #pragma unroll
            for (int hf = 0; hf < 2; hf++) {
                int rl = wm * 64 + mi * 16 + g + hf * 8;
                lst[mi][hf] += ssum[rl] + ssum[128 + rl] + ssum[256 + rl] + ssum[384 + rl];
            }

        // --- PV: O += P(128x128) @ V(128x128) ---
        #pragma unroll
        for (int kk64 = 0; kk64 < 2; kk64++) {
            uint32_t stA = Pb + (uint32_t)(kk64 * 16384);
            uint32_t stV = Vb + (uint32_t)(kk64 * 16384);
            #pragma unroll
            for (int kk16 = 0; kk16 < 4; kk16++) {
                unsigned af[4][4], bf[4][2];
                int cA = kk16 * 2 + ksel;
                #pragma unroll
                for (int mi = 0; mi < 4; mi++) {
                    int r = rbA + mi * 16;
                    ldsm4(af[mi][0], af[mi][1], af[mi][2], af[mi][3],
                          stA + (uint32_t)(r * 128 + ((cA ^ (r & 7)) << 4)));
                }
                int kr = kk16 * 16 + ((lane >> 3) & 1) * 8 + (lane & 7);
                #pragma unroll
                for (int njp = 0; njp < 2; njp++) {
                    int nch = wn * 4 + njp * 2 + (lane >> 4);
                    ldsm4t(bf[2 * njp][0], bf[2 * njp][1], bf[2 * njp + 1][0], bf[2 * njp + 1][1],
                           stV + (uint32_t)(kr * 256 + ((nch ^ (kr & 7)) << 4)));
                }
                #pragma unroll
                for (int mi = 0; mi < 4; mi++)
                    #pragma unroll
                    for (int nj = 0; nj < 4; nj++)
                        mma16(O[mi][nj], af[mi], bf[nj]);
            }
        }
        __syncthreads();   // protect P/V/stats before next j
    }

    // --- normalize + store ---
    #pragma unroll
    for (int mi = 0; mi < 4; mi++) {
        float inv0 = 1.0f / (512.0f * lst[mi][0]);
        float inv1 = 1.0f / (512.0f * lst[mi][1]);
        int r = row0 + wm * 64 + mi * 16 + g;
        #pragma unroll
        for (int nj = 0; nj < 4; nj++) {
            int c = h * V_D + wn * 32 + nj * 8 + tig * 2;
            *(__half2*)(attn + (size_t)r * (NH * V_D) + c) =
                __floats2half2_rn(O[mi][nj][0] * inv0, O[mi][nj][1] * inv0);
            *(__half2*)(attn + (size_t)(r + 8) * (NH * V_D) + c) =
                __floats2half2_rn(O[mi][nj][2] * inv1, O[mi][nj][3] * inv1);
        }
    }
}

// ---------------- prepass converts ----------------
__global__ void convert_f2h_kernel(const float4* __restrict__ src, uint4* __restrict__ dst, int n8)
{
    int i = blockIdx.x * blockDim.x + threadIdx.x;
    int stride = gridDim.x * blockDim.x;
    for (; i < n8; i += stride) {
        float4 a = src[2 * i], b = src[2 * i + 1];
        __half2 h0 = __floats2half2_rn(a.x, a.y);
        __half2 h1 = __floats2half2_rn(a.z, a.w);
        __half2 h2 = __floats2half2_rn(b.x, b.y);
        __half2 h3 = __floats2half2_rn(b.z, b.w);
        uint4 o;
        o.x = *(unsigned*)&h0; o.y = *(unsigned*)&h1;
        o.z = *(unsigned*)&h2; o.w = *(unsigned*)&h3;
        dst[i] = o;
    }
}
__global__ void pack_f2h_kernel(const float* __restrict__ src, __half* __restrict__ dst,
                                int C, int ldd, int off)
{
    int c4 = blockIdx.x * blockDim.x + threadIdx.x;
    int r  = blockIdx.y;
    if (c4 < C / 4) {
        float4 v = *(const float4*)(src + (long long)r * C + 4 * c4);
        __half2 h0 = __floats2half2_rn(v.x, v.y);
        __half2 h1 = __floats2half2_rn(v.z, v.w);
        uint2 o; o.x = *(unsigned*)&h0; o.y = *(unsigned*)&h1;
        *(uint2*)(dst + (long long)r * ldd + off + 4 * c4) = o;
    }
}

// ---------------- rmsnorm / rope kernels (unchanged) ----------------
__global__ void kva_rms_rope_kernel(const float* __restrict__ pre12,
                                    const float* __restrict__ kv_ln,
                                    const int*   __restrict__ pos_ids,
                                    __half* __restrict__ kfull)
{
    int s = blockIdx.x;
    const float* x = pre12 + (long long)s * N12 + Q_LORA;
    __half* out = kfull + (long long)s * CDIM;

    __shared__ float red[128];
    float ss = 0.0f;
    for (int i = threadIdx.x; i < KV_LORA; i += 128) { float v = x[i]; ss += v * v; }
    red[threadIdx.x] = ss; __syncthreads();
    for (int st = 64; st > 0; st >>= 1) {
        if (threadIdx.x < st) red[threadIdx.x] += red[threadIdx.x + st];
        __syncthreads();
    }
    float scale = rsqrtf(red[0] / (float)KV_LORA + 1e-6f);

    for (int i = threadIdx.x; i < KV_LORA; i += 128)
        out[i] = __float2half(x[i] * scale * kv_ln[i]);

    if (threadIdx.x < ROPE_D / 2) {
        int j = threadIdx.x;
        float pos  = (float)pos_ids[s];
        float invf = powf(10000.0f, -(float)(2 * j) / (float)ROPE_D);
        float ang  = pos * invf;
        float c = cosf(ang), sn = sinf(ang);
        float x0 = x[KV_LORA + 2 * j];
        float x1 = x[KV_LORA + 2 * j + 1];
        out[KV_LORA + j]              = __float2half(x0 * c - x1 * sn);
        out[KV_LORA + ROPE_D / 2 + j] = __float2half(x1 * c + x0 * sn);
    }
}
__global__ void qa_rms_kernel(const float* __restrict__ pre12,
                              const float* __restrict__ w,
                              __half* __restrict__ outp)
{
    int s = blockIdx.x;
    const float* x = pre12 + (long long)s * N12;
    __half* o = outp + (long long)s * Q_LORA;

    __shared__ float red[256];
    float ss = 0.0f;
    for (int i = threadIdx.x; i < Q_LORA; i += 256) { float v = x[i]; ss += v * v; }
    red[threadIdx.x] = ss; __syncthreads();
    for (int st = 128; st > 0; st >>= 1) {
        if (threadIdx.x < st) red[threadIdx.x] += red[threadIdx.x + st];
        __syncthreads();
    }
    float scale = rsqrtf(red[0] / (float)Q_LORA + 1e-6f);
    for (int i = threadIdx.x; i < Q_LORA; i += 256)
        o[i] = __float2half(x[i] * scale * w[i]);
}
__global__ void rope_q_kernel(const float* __restrict__ qpe,
                              const int*   __restrict__ pos_ids,
                              __half* __restrict__ qfull)
{
    int s = blockIdx.x;
    int h = blockIdx.y * 8 + (threadIdx.x >> 5);
    int j = threadIdx.x & 31;
    float pos  = (float)pos_ids[s];
    float invf = powf(10000.0f, -(float)(2 * j) / (float)ROPE_D);
    float ang  = pos * invf;
    float c = cosf(ang), sn = sinf(ang);
    const float* x = qpe + (long long)s * (NH * ROPE_D) + h * ROPE_D;
    float x0 = x[2 * j], x1 = x[2 * j + 1];
    __half* out = qfull + ((long long)h * S_LEN + s) * CDIM + KV_LORA;
    out[j]              = __float2half(x0 * c - x1 * sn);
    out[j + ROPE_D / 2] = __float2half(x1 * c + x0 * sn);
}

// ---------------- host launchers ----------------
template<bool HALF_OUT, bool BKN>
static void launch_gemm16_t(const __half* A, const __half* B, void* C,
                            int M, int N, int K, int lda, int ldb, int ldc,
                            long long sA, long long sB, long long sC,
                            int batch, float alpha, int mode)
{
    dim3 grid(M / 128, (N + 127) / 128, batch);
    cudaFuncSetAttribute(gemm16_kernel<HALF_OUT, BKN>, cudaFuncAttributeMaxDynamicSharedMemorySize, 3 * STG_BYTES);
    gemm16_kernel<HALF_OUT, BKN><<<grid, 256, 3 * STG_BYTES>>>(A, B, C, M, N, K, lda, ldb, ldc, sA, sB, sC, alpha, mode);
}
static void launch_convert(const float* src, __half* dst, size_t n)
{
    int n8 = (int)(n / 8);
    int blocks = (n8 + 255) / 256;
    if (blocks > 2048) blocks = 2048;
    convert_f2h_kernel<<<blocks, 256>>>((const float4*)src, (uint4*)dst, n8);
}

extern "C" void kernel_launch(void* const* d_in, const int* in_sizes, int n_in,
                              void* d_out, int out_size)
{
    (void)in_sizes; (void)n_in; (void)out_size;
    const float* X        = (const float*)d_in[0];
    const int*   pos      = (const int*)d_in[2];
    const float* W_kv_a   = (const float*)d_in[3];
    const float* W_q_a    = (const float*)d_in[4];
    const float* q_ln     = (const float*)d_in[5];
    const float* kv_ln    = (const float*)d_in[6];
    const float* q_rope_w = (const float*)d_in[7];
    const float* fusedqk  = (const float*)d_in[8];
    const float* v_up     = (const float*)d_in[9];
    const float* W_o      = (const float*)d_in[10];
    float* out = (float*)d_out;

    float  *pre12, *qpe;
    __half *xh, *qah, *kfullh, *qfullh, *vkva, *attnh;
    __half *w12h, *qrwh, *fqkh, *vuph, *woh;
    cudaGetSymbolAddress((void**)&pre12,  g_pre12);
    cudaGetSymbolAddress((void**)&qpe,    g_qpe);
    cudaGetSymbolAddress((void**)&xh,     g_xh);
    cudaGetSymbolAddress((void**)&qah,    g_qah);
    cudaGetSymbolAddress((void**)&kfullh, g_kfullh);
    cudaGetSymbolAddress((void**)&qfullh, g_qfullh);
    cudaGetSymbolAddress((void**)&vkva,   g_vkva);
    cudaGetSymbolAddress((void**)&attnh,  g_attnh);
    cudaGetSymbolAddress((void**)&w12h,   g_w12h);
    cudaGetSymbolAddress((void**)&qrwh,   g_qrwh);
    cudaGetSymbolAddress((void**)&fqkh,   g_fqkh);
    cudaGetSymbolAddress((void**)&vuph,   g_vuph);
    cudaGetSymbolAddress((void**)&woh,    g_woh);

    const float scale = 1.0f / sqrtf(192.0f);

    // 0) prepass converts
    launch_convert(X,        xh,   (size_t)S_LEN * HID);
    pack_f2h_kernel<<<dim3((Q_LORA / 4 + 255) / 256, HID), 256>>>(W_q_a,  w12h, Q_LORA, N12, 0);
    pack_f2h_kernel<<<dim3((CDIM   / 4 + 255) / 256, HID), 256>>>(W_kv_a, w12h, CDIM,   N12, Q_LORA);
    launch_convert(q_rope_w, qrwh, (size_t)Q_LORA * (NH * ROPE_D));
    launch_convert(fusedqk,  fqkh, (size_t)NH * Q_LORA * KV_LORA);
    launch_convert(v_up,     vuph, (size_t)NH * KV_LORA * V_D);
    launch_convert(W_o,      woh,  (size_t)(NH * V_D) * HID);

    // 1+2) pre12 = X @ [W_q | W_kv]
    launch_gemm16_t<false, true>(xh, w12h, pre12, S_LEN, N12, HID,
                                 HID, N12, N12, 0, 0, 0, 1, 1.0f, 0);
    // 3) kfullh
    kva_rms_rope_kernel<<<S_LEN, 128>>>(pre12, kv_ln, pos, kfullh);
    // 3b) vkva[h] = kva @ v_up[h]
    launch_gemm16_t<true, true>(kfullh, vuph, vkva, S_LEN, V_D, KV_LORA,
                                CDIM, V_D, V_D,
                                0, (long long)KV_LORA * V_D, (long long)S_LEN * V_D,
                                NH, 1.0f, 0);
    // 4) qah
    qa_rms_kernel<<<S_LEN, 256>>>(pre12, q_ln, qah);
    // 5) qpe = qa @ q_rope_w
    launch_gemm16_t<false, true>(qah, qrwh, qpe, S_LEN, NH * ROPE_D, Q_LORA,
                                 Q_LORA, NH * ROPE_D, NH * ROPE_D, 0, 0, 0, 1, 1.0f, 0);
    // 6) rope(q_pe)
    rope_q_kernel<<<dim3(S_LEN, NH / 8), 256>>>(qpe, pos, qfullh);
    // 7) dq = qa @ fusedqk[h]
    launch_gemm16_t<true, true>(qah, fqkh, qfullh, S_LEN, KV_LORA, Q_LORA,
                                Q_LORA, KV_LORA, CDIM,
                                0, (long long)Q_LORA * KV_LORA, (long long)S_LEN * CDIM,
                                NH, 1.0f, 0);
    // 8-10) fused flash attention -> attnh
    {
        cudaFuncSetAttribute(flash_kernel, cudaFuncAttributeMaxDynamicSharedMemorySize, FL_SMEM);
        dim3 grid(S_LEN / 128, 1, NH);
        flash_kernel<<<grid, 256, FL_SMEM>>>(qfullh, kfullh, vkva, attnh, scale);
    }
    // 12) out = attn @ W_o
    launch_gemm16_t<false, true>(attnh, woh, out, S_LEN, HID, NH * V_D,
                                 NH * V_D, HID, HID, 0, 0, 0, 1, 1.0f, 0);
}

// round 14
// speedup vs baseline: 3.3813x; 1.0029x over previous
#include <cuda_runtime.h>
#include <cuda_fp16.h>
#include <math.h>
#include <stdint.h>

// ---------------- problem constants ----------------
#define S_LEN   2048
#define HID     7168
#define NH      32
#define Q_LORA  1536
#define KV_LORA 512
#define ROPE_D  64
#define CDIM    576
#define V_D     128
#define N12     (Q_LORA + CDIM)
#define MIN_MASKED (-10000.0f)

// ---------------- scratch ----------------
__device__ float  g_pre12[(size_t)S_LEN * N12];
__device__ float  g_qpe[(size_t)S_LEN * (NH * ROPE_D)];
__device__ __half g_xh   [(size_t)S_LEN * HID];
__device__ __half g_qah  [(size_t)S_LEN * Q_LORA];
__device__ __half g_kfullh[(size_t)S_LEN * CDIM];
__device__ __half g_qfullh[(size_t)NH * S_LEN * CDIM];
__device__ __half g_vkva [(size_t)NH * S_LEN * V_D];
__device__ __half g_attnh[(size_t)S_LEN * (NH * V_D)];
__device__ __half g_w12h[(size_t)HID * N12];
__device__ __half g_qrwh[(size_t)Q_LORA * (NH * ROPE_D)];
__device__ __half g_fqkh[(size_t)NH * Q_LORA * KV_LORA];
__device__ __half g_vuph[(size_t)NH * KV_LORA * V_D];
__device__ __half g_woh [(size_t)(NH * V_D) * HID];

// ---------------- helpers ----------------
__device__ __forceinline__ void mma16(float (&c)[4], const unsigned (&a)[4], const unsigned (&b)[2]) {
    asm volatile(
        "mma.sync.aligned.m16n8k16.row.col.f32.f16.f16.f32 "
        "{%0,%1,%2,%3}, {%4,%5,%6,%7}, {%8,%9}, {%0,%1,%2,%3};"
        : "+f"(c[0]), "+f"(c[1]), "+f"(c[2]), "+f"(c[3])
        : "r"(a[0]), "r"(a[1]), "r"(a[2]), "r"(a[3]), "r"(b[0]), "r"(b[1]));
}
__device__ __forceinline__ void ldsm4(unsigned &r0, unsigned &r1, unsigned &r2, unsigned &r3, uint32_t a) {
    asm volatile("ldmatrix.sync.aligned.m8n8.x4.shared.b16 {%0,%1,%2,%3}, [%4];"
                 : "=r"(r0), "=r"(r1), "=r"(r2), "=r"(r3) : "r"(a));
}
__device__ __forceinline__ void ldsm4t(unsigned &r0, unsigned &r1, unsigned &r2, unsigned &r3, uint32_t a) {
    asm volatile("ldmatrix.sync.aligned.m8n8.x4.trans.shared.b16 {%0,%1,%2,%3}, [%4];"
                 : "=r"(r0), "=r"(r1), "=r"(r2), "=r"(r3) : "r"(a));
}
__device__ __forceinline__ void cpasync16(uint32_t dst, const void* src, int srcsize) {
    asm volatile("cp.async.cg.shared.global [%0], [%1], 16, %2;"
                 :: "r"(dst), "l"(src), "r"(srcsize) : "memory");
}
__device__ __forceinline__ void cp_commit() { asm volatile("cp.async.commit_group;" ::: "memory"); }
template<int N> __device__ __forceinline__ void cp_wait() { asm volatile("cp.async.wait_group %0;" :: "n"(N) : "memory"); }
__device__ __forceinline__ uint32_t smem_addr32(const void* p) {
    uint32_t a;
    asm("{ .reg .u64 t; cvta.to.shared.u64 t, %1; cvt.u32.u64 %0, t; }" : "=r"(a) : "l"(p));
    return a;
}
__device__ __forceinline__ float ex2f(float x) {
    float y;
    asm("ex2.approx.f32 %0, %1;" : "=f"(y) : "f"(x));
    return y;
}

// ---------------- fp16 tensor-core GEMM (unchanged) ----------------
#define STG_BYTES 32768

template<bool HALF_OUT, bool BKN>
__global__ void __launch_bounds__(256, 2)
gemm16_kernel(const __half* __restrict__ A, const __half* __restrict__ B, void* Cv,
              int M, int N, int K, int lda, int ldb, int ldc,
              long long sA, long long sB, long long sC,
              float alpha, int mode)
{
    extern __shared__ char smem[];
    const long long bz = blockIdx.z;
    A += bz * sA;  B += bz * sB;

    const int row0 = blockIdx.x * 128;
    const int col0 = blockIdx.y * 128;
    if (mode == 1 && col0 >= row0 + 128) return;

    float*  Cf = (float*)Cv  + bz * sC;
    __half* Ch = (__half*)Cv + bz * sC;

    const int tid  = threadIdx.x;
    const int lane = tid & 31;
    const int wid  = tid >> 5;
    const int wm   = wid >> 2;
    const int wn   = wid & 3;
    const int g    = lane >> 2;
    const int tig  = lane & 3;

    uint32_t sbase = smem_addr32(smem);

    const int kEnd = (mode == 2) ? min(K, row0 + 128) : K;
    const int T = kEnd >> 6;

    auto issue = [&](int t) {
        int k0 = t << 6;
        uint32_t st = sbase + (uint32_t)((t % 3) * STG_BYTES);
        #pragma unroll
        for (int e = 0; e < 4; e++) {
            int id = tid + e * 256;
            int r = id >> 3, c = id & 7;
            uint32_t dst = st + (uint32_t)(r * 128 + ((c ^ (r & 7)) * 16));
            cpasync16(dst, A + (long long)(row0 + r) * lda + k0 + c * 8, 16);
        }
        if (!BKN) {
            #pragma unroll
            for (int e = 0; e < 4; e++) {
                int id = tid + e * 256;
                int n = id >> 3, c = id & 7;
                uint32_t dst = st + 16384u + (uint32_t)(n * 128 + ((c ^ (n & 7)) * 16));
                bool ok = (col0 + n) < N;
                const __half* src = ok ? (B + (long long)(col0 + n) * ldb + k0 + c * 8) : B;
                cpasync16(dst, src, ok ? 16 : 0);
            }
        } else {
            #pragma unroll
            for (int e = 0; e < 4; e++) {
                int id = tid + e * 256;
                int k = id >> 4, c = id & 15;
                uint32_t dst = st + 16384u + (uint32_t)(k * 256 + ((c ^ (k & 7)) * 16));
                bool ok = (col0 + c * 8) < N;
                const __half* src = ok ? (B + (long long)(k0 + k) * ldb + col0 + c * 8) : B;
                cpasync16(dst, src, ok ? 16 : 0);
            }
        }
        cp_commit();
    };

    float acc[4][4][4] = {};

    issue(0);
    if (1 < T) issue(1);

    const int rbA  = wm * 64 + ((lane >> 3) & 1) * 8 + (lane & 7);
    const int ksel = lane >> 4;

    for (int t = 0; t < T; t++) {
        if (t + 1 < T) cp_wait<1>();
        else           cp_wait<0>();
        __syncthreads();
        if (t + 2 < T) issue(t + 2);

        uint32_t stA = sbase + (uint32_t)((t % 3) * STG_BYTES);
        uint32_t stB = stA + 16384u;

        #pragma unroll
        for (int kk16 = 0; kk16 < 4; kk16++) {
            unsigned af[4][4], bf[4][2];
            int cA = kk16 * 2 + ksel;
            #pragma unroll
            for (int mi = 0; mi < 4; mi++) {
                int r = rbA + mi * 16;
                uint32_t ad = stA + (uint32_t)(r * 128 + ((cA ^ (r & 7)) << 4));
                ldsm4(af[mi][0], af[mi][1], af[mi][2], af[mi][3], ad);
            }
            if (!BKN) {
                int cB = kk16 * 2 + ((lane >> 3) & 1);
                #pragma unroll
                for (int njp = 0; njp < 2; njp++) {
                    int n = wn * 32 + njp * 16 + (lane >> 4) * 8 + (lane & 7);
                    uint32_t ad = stB + (uint32_t)(n * 128 + ((cB ^ (n & 7)) << 4));
                    ldsm4(bf[2 * njp][0], bf[2 * njp][1], bf[2 * njp + 1][0], bf[2 * njp + 1][1], ad);
                }
            } else {
                int kr = kk16 * 16 + ((lane >> 3) & 1) * 8 + (lane & 7);
                #pragma unroll
                for (int njp = 0; njp < 2; njp++) {
                    int nch = wn * 4 + njp * 2 + (lane >> 4);
                    uint32_t ad = stB + (uint32_t)(kr * 256 + ((nch ^ (kr & 7)) << 4));
                    ldsm4t(bf[2 * njp][0], bf[2 * njp][1], bf[2 * njp + 1][0], bf[2 * njp + 1][1], ad);
                }
            }
            #pragma unroll
            for (int mi = 0; mi < 4; mi++)
                #pragma unroll
                for (int nj = 0; nj < 4; nj++)
                    mma16(acc[mi][nj], af[mi], bf[nj]);
        }
    }

    #pragma unroll
    for (int mi = 0; mi < 4; mi++) {
        int r = row0 + wm * 64 + mi * 16 + g;
        #pragma unroll
        for (int nj = 0; nj < 4; nj++) {
            int c = col0 + wn * 32 + nj * 8 + tig * 2;
            float v0 = acc[mi][nj][0] * alpha;
            float v1 = acc[mi][nj][1] * alpha;
            float v2 = acc[mi][nj][2] * alpha;
            float v3 = acc[mi][nj][3] * alpha;
            if (mode == 1) {
                v0 = (c     > r    ) ? MIN_MASKED : v0;
                v1 = (c + 1 > r    ) ? MIN_MASKED : v1;
                v2 = (c     > r + 8) ? MIN_MASKED : v2;
                v3 = (c + 1 > r + 8) ? MIN_MASKED : v3;
            }
            if (c < N) {
                if (HALF_OUT) {
                    *(__half2*)(Ch + (long long)r * ldc + c) =
                        __halves2half2(__float2half(v0), __float2half(v1));
                    *(__half2*)(Ch + (long long)(r + 8) * ldc + c) =
                        __halves2half2(__float2half(v2), __float2half(v3));
                } else {
                    *(float2*)(Cf + (long long)r * ldc + c)       = make_float2(v0, v1);
                    *(float2*)(Cf + (long long)(r + 8) * ldc + c) = make_float2(v2, v3);
                }
            }
        }
    }
}

// ---------------- fused flash attention (pipelined across j) ----------------
// smem: [0,98304) 3 QK stages; [98304,131072) P; [131072,196608) V double-buffer;
//       [196608,198656) smax; [198656,200704) ssum.
// Per j: V(j+1) + QK stages 0-1 of j+1 are issued during the softmax/PV phase of j,
// so the S loop's first wait never exposes gmem latency.
// log2-domain softmax: s2 = S * scale*log2e; p = ex2(s2 - m2).
#define FL_SMEM 200704

__global__ void __launch_bounds__(256, 1)
flash_kernel(const __half* __restrict__ Qf, const __half* __restrict__ Kf,
             const __half* __restrict__ Vk, __half* __restrict__ attn,
             float scale)
{
    extern __shared__ char smem[];
    const int i = 15 - blockIdx.x;
    const int h = blockIdx.z;
    const int row0 = i * 128;
    const __half* Q = Qf + (size_t)h * S_LEN * CDIM;
    const __half* V = Vk + (size_t)h * S_LEN * V_D;
    const float scale2 = scale * 1.44269504088896f;   // log2 domain

    const int tid  = threadIdx.x;
    const int lane = tid & 31;
    const int wid  = tid >> 5;
    const int wm   = wid >> 2;
    const int wn   = wid & 3;
    const int g    = lane >> 2;
    const int tig  = lane & 3;

    uint32_t sb = smem_addr32(smem);
    uint32_t Pb = sb + 98304u;
    uint32_t Vb = sb + 131072u;
    float* smax = (float*)(smem + 196608);
    float* ssum = (float*)(smem + 198656);

    float O[4][4][4] = {};
    float mst[4][2], lst[4][2];
    #pragma unroll
    for (int mi = 0; mi < 4; mi++) { mst[mi][0] = mst[mi][1] = -1e30f; lst[mi][0] = lst[mi][1] = 0.f; }

    const int rbA  = wm * 64 + ((lane >> 3) & 1) * 8 + (lane & 7);
    const int ksel = lane >> 4;

    auto issueV = [&](int jj) {
        uint32_t vb = Vb + (uint32_t)((jj & 1) * 32768);
        #pragma unroll
        for (int e = 0; e < 8; e++) {
            int id = tid + e * 256;
            int k = id >> 4, c = id & 15;
            uint32_t dst = vb + (uint32_t)((k >> 6) * 16384 + (k & 63) * 256 + ((c ^ (k & 7)) << 4));
            cpasync16(dst, V + (size_t)(jj * 128 + k) * V_D + c * 8, 16);
        }
        cp_commit();
    };
    auto issueS = [&](int jj, int t) {
        int k0 = t << 6;
        uint32_t st = sb + (uint32_t)((t % 3) * STG_BYTES);
        #pragma unroll
        for (int e = 0; e < 4; e++) {
            int id = tid + e * 256;
            int r = id >> 3, c = id & 7;
            cpasync16(st + (uint32_t)(r * 128 + ((c ^ (r & 7)) * 16)),
                      Q + (size_t)(row0 + r) * CDIM + k0 + c * 8, 16);
        }
        #pragma unroll
        for (int e = 0; e < 4; e++) {
            int id = tid + e * 256;
            int n = id >> 3, c = id & 7;
            cpasync16(st + 16384u + (uint32_t)(n * 128 + ((c ^ (n & 7)) * 16)),
                      Kf + (size_t)(jj * 128 + n) * CDIM + k0 + c * 8, 16);
        }
        cp_commit();
    };

    // prologue: V(0) + first two QK stages of j=0
    issueV(0);
    issueS(0, 0);
    issueS(0, 1);

    for (int j = 0; j <= i; j++) {
        // --- S = Q_i K_j^T, K=576 (T=9), 3-stage pipeline ---
        float S[4][4][4] = {};
        for (int t = 0; t < 9; t++) {
            if (t + 1 < 9) cp_wait<1>();
            else           cp_wait<0>();
            __syncthreads();
            if (t + 2 < 9) issueS(j, t + 2);

            uint32_t stA = sb + (uint32_t)((t % 3) * STG_BYTES);
            uint32_t stB = stA + 16384u;
            #pragma unroll
            for (int kk16 = 0; kk16 < 4; kk16++) {
                unsigned af[4][4], bf[4][2];
                int cA = kk16 * 2 + ksel;
                #pragma unroll
                for (int mi = 0; mi < 4; mi++) {
                    int r = rbA + mi * 16;
                    ldsm4(af[mi][0], af[mi][1], af[mi][2], af[mi][3],
                          stA + (uint32_t)(r * 128 + ((cA ^ (r & 7)) << 4)));
                }
                int cB = kk16 * 2 + ((lane >> 3) & 1);
                #pragma unroll
                for (int njp = 0; njp < 2; njp++) {
                    int n = wn * 32 + njp * 16 + (lane >> 4) * 8 + (lane & 7);
                    ldsm4(bf[2 * njp][0], bf[2 * njp][1], bf[2 * njp + 1][0], bf[2 * njp + 1][1],
                          stB + (uint32_t)(n * 128 + ((cB ^ (n & 7)) << 4)));
                }
                #pragma unroll
                for (int mi = 0; mi < 4; mi++)
                    #pragma unroll
                    for (int nj = 0; nj < 4; nj++)
                        mma16(S[mi][nj], af[mi], bf[nj]);
            }
        }

        // --- scale to log2 domain + mask (in place) + row max ---
        const bool diag = (j == i);
        float lm[4][2];
        #pragma unroll
        for (int mi = 0; mi < 4; mi++) { lm[mi][0] = lm[mi][1] = -1e30f; }
        #pragma unroll
        for (int mi = 0; mi < 4; mi++)
            #pragma unroll
            for (int nj = 0; nj < 4; nj++)
                #pragma unroll
                for (int c = 0; c < 4; c++) {
                    int hf = c >> 1;
                    int rl = wm * 64 + mi * 16 + g + hf * 8;
                    int cl = wn * 32 + nj * 8 + tig * 2 + (c & 1);
                    float s = S[mi][nj][c] * scale2;
                    if (diag && cl > rl) s = -1e30f;
                    S[mi][nj][c] = s;
                    lm[mi][hf] = fmaxf(lm[mi][hf], s);
                }
        #pragma unroll
        for (int mi = 0; mi < 4; mi++)
            #pragma unroll
            for (int hf = 0; hf < 2; hf++) {
                lm[mi][hf] = fmaxf(lm[mi][hf], __shfl_xor_sync(0xffffffffu, lm[mi][hf], 1));
                lm[mi][hf] = fmaxf(lm[mi][hf], __shfl_xor_sync(0xffffffffu, lm[mi][hf], 2));
            }
        if (tig == 0) {
            #pragma unroll
            for (int mi = 0; mi < 4; mi++)
                #pragma unroll
                for (int hf = 0; hf < 2; hf++)
                    smax[wn * 128 + wm * 64 + mi * 16 + g + hf * 8] = lm[mi][hf];
        }
        __syncthreads();

        float alpha_[4][2];
        #pragma unroll
        for (int mi = 0; mi < 4; mi++)
            #pragma unroll
            for (int hf = 0; hf < 2; hf++) {
                int rl = wm * 64 + mi * 16 + g + hf * 8;
                float mj = fmaxf(fmaxf(smax[rl], smax[128 + rl]),
                                 fmaxf(smax[256 + rl], smax[384 + rl]));
                float mn = fmaxf(mst[mi][hf], mj);
                float al = ex2f(mst[mi][hf] - mn);
                mst[mi][hf] = mn;
                lst[mi][hf] *= al;
                alpha_[mi][hf] = al;
            }
        #pragma unroll
        for (int mi = 0; mi < 4; mi++)
            #pragma unroll
            for (int nj = 0; nj < 4; nj++) {
                O[mi][nj][0] *= alpha_[mi][0]; O[mi][nj][1] *= alpha_[mi][0];
                O[mi][nj][2] *= alpha_[mi][1]; O[mi][nj][3] *= alpha_[mi][1];
            }

        // --- exp (ex2) + P store (x512, fp16) + row sums ---
        float ls[4][2];
        #pragma unroll
        for (int mi = 0; mi < 4; mi++) { ls[mi][0] = ls[mi][1] = 0.f; }
        #pragma unroll
        for (int mi = 0; mi < 4; mi++)
            #pragma unroll
            for (int nj = 0; nj < 4; nj++) {
                #pragma unroll
                for (int c = 0; c < 4; c++) {
                    int hf = c >> 1;
                    float p = ex2f(S[mi][nj][c] - mst[mi][hf]);
                    S[mi][nj][c] = p;
                    ls[mi][hf] += p;
                }
                int cc = wn * 32 + nj * 8 + tig * 2;
                uint32_t hb  = (uint32_t)(cc >> 6) * 16384u;
                int ccc = cc & 63;
                int r1 = wm * 64 + mi * 16 + g;
                uint32_t a1 = Pb + hb + (uint32_t)(r1 * 128 + ((((ccc >> 3) ^ (r1 & 7))) << 4) + (ccc & 7) * 2);
                int r2 = r1 + 8;
                uint32_t a2 = Pb + hb + (uint32_t)(r2 * 128 + ((((ccc >> 3) ^ (r2 & 7))) << 4) + (ccc & 7) * 2);
                __half2 v1 = __floats2half2_rn(S[mi][nj][0] * 512.f, S[mi][nj][1] * 512.f);
                __half2 v2 = __floats2half2_rn(S[mi][nj][2] * 512.f, S[mi][nj][3] * 512.f);
                *(__half2*)(smem + (a1 - sb)) = v1;
                *(__half2*)(smem + (a2 - sb)) = v2;
            }
        #pragma unroll
        for (int mi = 0; mi < 4; mi++)
            #pragma unroll
            for (int hf = 0; hf < 2; hf++) {
                ls[mi][hf] += __shfl_xor_sync(0xffffffffu, ls[mi][hf], 1);
                ls[mi][hf] += __shfl_xor_sync(0xffffffffu, ls[mi][hf], 2);
            }
        if (tig == 0) {
            #pragma unroll
            for (int mi = 0; mi < 4; mi++)
                #pragma unroll
                for (int hf = 0; hf < 2; hf++)
                    ssum[wn * 128 + wm * 64 + mi * 16 + g + hf * 8] = ls[mi][hf];
        }
        __syncthreads();

        #pragma unroll
        for (int mi = 0; mi < 4; mi++)
            #pragma unroll
            for (int hf = 0; hf < 2; hf++) {
                int rl = wm * 64 + mi * 16 + g + hf * 8;
                lst[mi][hf] += ssum[rl] + ssum[128 + rl] + ssum[256 + rl] + ssum[384 + rl];
            }

        // --- prefetch next j's V and first two QK stages (overlaps PV) ---
        if (j < i) {
            issueV(j + 1);
            issueS(j + 1, 0);
            issueS(j + 1, 1);
        }

        // --- PV: O += P(128x128) @ V_j(128x128) ---
        uint32_t Vcur = Vb + (uint32_t)((j & 1) * 32768);
        #pragma unroll
        for (int kk64 = 0; kk64 < 2; kk64++) {
            uint32_t stA = Pb + (uint32_t)(kk64 * 16384);
            uint32_t stV = Vcur + (uint32_t)(kk64 * 16384);
            #pragma unroll
            for (int kk16 = 0; kk16 < 4; kk16++) {
                unsigned af[4][4], bf[4][2];
                int cA = kk16 * 2 + ksel;
                #pragma unroll
                for (int mi = 0; mi < 4; mi++) {
                    int r = rbA + mi * 16;
                    ldsm4(af[mi][0], af[mi][1], af[mi][2], af[mi][3],
                          stA + (uint32_t)(r * 128 + ((cA ^ (r & 7)) << 4)));
                }
                int kr = kk16 * 16 + ((lane >> 3) & 1) * 8 + (lane & 7);
                #pragma unroll
                for (int njp = 0; njp < 2; njp++) {
                    int nch = wn * 4 + njp * 2 + (lane >> 4);
                    ldsm4t(bf[2 * njp][0], bf[2 * njp][1], bf[2 * njp + 1][0], bf[2 * njp + 1][1],
                           stV + (uint32_t)(kr * 256 + ((nch ^ (kr & 7)) << 4)));
                }
                #pragma unroll
                for (int mi = 0; mi < 4; mi++)
                    #pragma unroll
                    for (int nj = 0; nj < 4; nj++)
                        mma16(O[mi][nj], af[mi], bf[nj]);
            }
        }
        // no trailing barrier: next j's S loop syncs before any shared write
    }

    // --- normalize + store ---
    #pragma unroll
    for (int mi = 0; mi < 4; mi++) {
        float inv0 = 1.0f / (512.0f * lst[mi][0]);
        float inv1 = 1.0f / (512.0f * lst[mi][1]);
        int r = row0 + wm * 64 + mi * 16 + g;
        #pragma unroll
        for (int nj = 0; nj < 4; nj++) {
            int c = h * V_D + wn * 32 + nj * 8 + tig * 2;
            *(__half2*)(attn + (size_t)r * (NH * V_D) + c) =
                __floats2half2_rn(O[mi][nj][0] * inv0, O[mi][nj][1] * inv0);
            *(__half2*)(attn + (size_t)(r + 8) * (NH * V_D) + c) =
                __floats2half2_rn(O[mi][nj][2] * inv1, O[mi][nj][3] * inv1);
        }
    }
}

// ---------------- prepass converts (2-way ILP) ----------------
__global__ void convert_f2h_kernel(const float4* __restrict__ src, uint4* __restrict__ dst, int n8)
{
    int i = blockIdx.x * blockDim.x + threadIdx.x;
    int stride = gridDim.x * blockDim.x;
    for (; i < n8; i += 2 * stride) {
        int i1 = i + stride;
        float4 a0 = src[2 * i],  b0 = src[2 * i + 1];
        float4 a1, b1;
        bool ok1 = i1 < n8;
        if (ok1) { a1 = src[2 * i1]; b1 = src[2 * i1 + 1]; }
        {
            __half2 h0 = __floats2half2_rn(a0.x, a0.y);
            __half2 h1 = __floats2half2_rn(a0.z, a0.w);
            __half2 h2 = __floats2half2_rn(b0.x, b0.y);
            __half2 h3 = __floats2half2_rn(b0.z, b0.w);
            uint4 o;
            o.x = *(unsigned*)&h0; o.y = *(unsigned*)&h1;
            o.z = *(unsigned*)&h2; o.w = *(unsigned*)&h3;
            dst[i] = o;
        }
        if (ok1) {
            __half2 h0 = __floats2half2_rn(a1.x, a1.y);
            __half2 h1 = __floats2half2_rn(a1.z, a1.w);
            __half2 h2 = __floats2half2_rn(b1.x, b1.y);
            __half2 h3 = __floats2half2_rn(b1.z, b1.w);
            uint4 o;
            o.x = *(unsigned*)&h0; o.y = *(unsigned*)&h1;
            o.z = *(unsigned*)&h2; o.w = *(unsigned*)&h3;
            dst[i1] = o;
        }
    }
}
__global__ void pack_f2h_kernel(const float* __restrict__ src, __half* __restrict__ dst,
                                int C, int ldd, int off)
{
    int c4 = blockIdx.x * blockDim.x + threadIdx.x;
    int r  = blockIdx.y;
    if (c4 < C / 4) {
        float4 v = *(const float4*)(src + (long long)r * C + 4 * c4);
        __half2 h0 = __floats2half2_rn(v.x, v.y);
        __half2 h1 = __floats2half2_rn(v.z, v.w);
        uint2 o; o.x = *(unsigned*)&h0; o.y = *(unsigned*)&h1;
        *(uint2*)(dst + (long long)r * ldd + off + 4 * c4) = o;
    }
}

// ---------------- rmsnorm / rope kernels (unchanged) ----------------
__global__ void kva_rms_rope_kernel(const float* __restrict__ pre12,
                                    const float* __restrict__ kv_ln,
                                    const int*   __restrict__ pos_ids,
                                    __half* __restrict__ kfull)
{
    int s = blockIdx.x;
    const float* x = pre12 + (long long)s * N12 + Q_LORA;
    __half* out = kfull + (long long)s * CDIM;

    __shared__ float red[128];
    float ss = 0.0f;
    for (int i = threadIdx.x; i < KV_LORA; i += 128) { float v = x[i]; ss += v * v; }
    red[threadIdx.x] = ss; __syncthreads();
    for (int st = 64; st > 0; st >>= 1) {
        if (threadIdx.x < st) red[threadIdx.x] += red[threadIdx.x + st];
        __syncthreads();
    }
    float scale = rsqrtf(red[0] / (float)KV_LORA + 1e-6f);

    for (int i = threadIdx.x; i < KV_LORA; i += 128)
        out[i] = __float2half(x[i] * scale * kv_ln[i]);

    if (threadIdx.x < ROPE_D / 2) {
        int j = threadIdx.x;
        float pos  = (float)pos_ids[s];
        float invf = powf(10000.0f, -(float)(2 * j) / (float)ROPE_D);
        float ang  = pos * invf;
        float c = cosf(ang), sn = sinf(ang);
        float x0 = x[KV_LORA + 2 * j];
        float x1 = x[KV_LORA + 2 * j + 1];
        out[KV_LORA + j]              = __float2half(x0 * c - x1 * sn);
        out[KV_LORA + ROPE_D / 2 + j] = __float2half(x1 * c + x0 * sn);
    }
}
__global__ void qa_rms_kernel(const float* __restrict__ pre12,
                              const float* __restrict__ w,
                              __half* __restrict__ outp)
{
    int s = blockIdx.x;
    const float* x = pre12 + (long long)s * N12;
    __half* o = outp + (long long)s * Q_LORA;

    __shared__ float red[256];
    float ss = 0.0f;
    for (int i = threadIdx.x; i < Q_LORA; i += 256) { float v = x[i]; ss += v * v; }
    red[threadIdx.x] = ss; __syncthreads();
    for (int st = 128; st > 0; st >>= 1) {
        if (threadIdx.x < st) red[threadIdx.x] += red[threadIdx.x + st];
        __syncthreads();
    }
    float scale = rsqrtf(red[0] / (float)Q_LORA + 1e-6f);
    for (int i = threadIdx.x; i < Q_LORA; i += 256)
        o[i] = __float2half(x[i] * scale * w[i]);
}
__global__ void rope_q_kernel(const float* __restrict__ qpe,
                              const int*   __restrict__ pos_ids,
                              __half* __restrict__ qfull)
{
    int s = blockIdx.x;
    int h = blockIdx.y * 8 + (threadIdx.x >> 5);
    int j = threadIdx.x & 31;
    float pos  = (float)pos_ids[s];
    float invf = powf(10000.0f, -(float)(2 * j) / (float)ROPE_D);
    float ang  = pos * invf;
    float c = cosf(ang), sn = sinf(ang);
    const float* x = qpe + (long long)s * (NH * ROPE_D) + h * ROPE_D;
    float x0 = x[2 * j], x1 = x[2 * j + 1];
    __half* out = qfull + ((long long)h * S_LEN + s) * CDIM + KV_LORA;
    out[j]              = __float2half(x0 * c - x1 * sn);
    out[j + ROPE_D / 2] = __float2half(x1 * c + x0 * sn);
}

// ---------------- host launchers ----------------
template<bool HALF_OUT, bool BKN>
static void launch_gemm16_t(const __half* A, const __half* B, void* C,
                            int M, int N, int K, int lda, int ldb, int ldc,
                            long long sA, long long sB, long long sC,
                            int batch, float alpha, int mode)
{
    dim3 grid(M / 128, (N + 127) / 128, batch);
    cudaFuncSetAttribute(gemm16_kernel<HALF_OUT, BKN>, cudaFuncAttributeMaxDynamicSharedMemorySize, 3 * STG_BYTES);
    gemm16_kernel<HALF_OUT, BKN><<<grid, 256, 3 * STG_BYTES>>>(A, B, C, M, N, K, lda, ldb, ldc, sA, sB, sC, alpha, mode);
}
static void launch_convert(const float* src, __half* dst, size_t n)
{
    int n8 = (int)(n / 8);
    int blocks = (n8 + 255) / 256;
    if (blocks > 2048) blocks = 2048;
    convert_f2h_kernel<<<blocks, 256>>>((const float4*)src, (uint4*)dst, n8);
}

extern "C" void kernel_launch(void* const* d_in, const int* in_sizes, int n_in,
                              void* d_out, int out_size)
{
    (void)in_sizes; (void)n_in; (void)out_size;
    const float* X        = (const float*)d_in[0];
    const int*   pos      = (const int*)d_in[2];
    const float* W_kv_a   = (const float*)d_in[3];
    const float* W_q_a    = (const float*)d_in[4];
    const float* q_ln     = (const float*)d_in[5];
    const float* kv_ln    = (const float*)d_in[6];
    const float* q_rope_w = (const float*)d_in[7];
    const float* fusedqk  = (const float*)d_in[8];
    const float* v_up     = (const float*)d_in[9];
    const float* W_o      = (const float*)d_in[10];
    float* out = (float*)d_out;

    float  *pre12, *qpe;
    __half *xh, *qah, *kfullh, *qfullh, *vkva, *attnh;
    __half *w12h, *qrwh, *fqkh, *vuph, *woh;
    cudaGetSymbolAddress((void**)&pre12,  g_pre12);
    cudaGetSymbolAddress((void**)&qpe,    g_qpe);
    cudaGetSymbolAddress((void**)&xh,     g_xh);
    cudaGetSymbolAddress((void**)&qah,    g_qah);
    cudaGetSymbolAddress((void**)&kfullh, g_kfullh);
    cudaGetSymbolAddress((void**)&qfullh, g_qfullh);
    cudaGetSymbolAddress((void**)&vkva,   g_vkva);
    cudaGetSymbolAddress((void**)&attnh,  g_attnh);
    cudaGetSymbolAddress((void**)&w12h,   g_w12h);
    cudaGetSymbolAddress((void**)&qrwh,   g_qrwh);
    cudaGetSymbolAddress((void**)&fqkh,   g_fqkh);
    cudaGetSymbolAddress((void**)&vuph,   g_vuph);
    cudaGetSymbolAddress((void**)&woh,    g_woh);

    const float scale = 1.0f / sqrtf(192.0f);

    // 0) prepass converts
    launch_convert(X,        xh,   (size_t)S_LEN * HID);
    pack_f2h_kernel<<<dim3((Q_LORA / 4 + 255) / 256, HID), 256>>>(W_q_a,  w12h, Q_LORA, N12, 0);
    pack_f2h_kernel<<<dim3((CDIM   / 4 + 255) / 256, HID), 256>>>(W_kv_a, w12h, CDIM,   N12, Q_LORA);
    launch_convert(q_rope_w, qrwh, (size_t)Q_LORA * (NH * ROPE_D));
    launch_convert(fusedqk,  fqkh, (size_t)NH * Q_LORA * KV_LORA);
    launch_convert(v_up,     vuph, (size_t)NH * KV_LORA * V_D);
    launch_convert(W_o,      woh,  (size_t)(NH * V_D) * HID);

    // 1+2) pre12 = X @ [W_q | W_kv]
    launch_gemm16_t<false, true>(xh, w12h, pre12, S_LEN, N12, HID,
                                 HID, N12, N12, 0, 0, 0, 1, 1.0f, 0);
    // 3) kfullh
    kva_rms_rope_kernel<<<S_LEN, 128>>>(pre12, kv_ln, pos, kfullh);
    // 3b) vkva[h] = kva @ v_up[h]
    launch_gemm16_t<true, true>(kfullh, vuph, vkva, S_LEN, V_D, KV_LORA,
                                CDIM, V_D, V_D,
                                0, (long long)KV_LORA * V_D, (long long)S_LEN * V_D,
                                NH, 1.0f, 0);
    // 4) qah
    qa_rms_kernel<<<S_LEN, 256>>>(pre12, q_ln, qah);
    // 5) qpe = qa @ q_rope_w
    launch_gemm16_t<false, true>(qah, qrwh, qpe, S_LEN, NH * ROPE_D, Q_LORA,
                                 Q_LORA, NH * ROPE_D, NH * ROPE_D, 0, 0, 0, 1, 1.0f, 0);
    // 6) rope(q_pe)
    rope_q_kernel<<<dim3(S_LEN, NH / 8), 256>>>(qpe, pos, qfullh);
    // 7) dq = qa @ fusedqk[h]
    launch_gemm16_t<true, true>(qah, fqkh, qfullh, S_LEN, KV_LORA, Q_LORA,
                                Q_LORA, KV_LORA, CDIM,
                                0, (long long)Q_LORA * KV_LORA, (long long)S_LEN * CDIM,
                                NH, 1.0f, 0);
    // 8-10) fused flash attention -> attnh
    {
        cudaFuncSetAttribute(flash_kernel, cudaFuncAttributeMaxDynamicSharedMemorySize, FL_SMEM);
        dim3 grid(S_LEN / 128, 1, NH);
        flash_kernel<<<grid, 256, FL_SMEM>>>(qfullh, kfullh, vkva, attnh, scale);
    }
    // 12) out = attn @ W_o
    launch_gemm16_t<false, true>(attnh, woh, out, S_LEN, HID, NH * V_D,
                                 NH * V_D, HID, HID, 0, 0, 0, 1, 1.0f, 0);
}